// round 10
// baseline (speedup 1.0000x reference)
#include <cuda_runtime.h>
#include <cuda_bf16.h>
#include <cstdint>
#include <math.h>

// Problem constants
#define NB     4
#define NSEQ   1024
#define DMODEL 512
#define NH     8
#define HD     64
#define EOUT   2048          // 2*H*Dv + 2*H*Dq
#define ROWS   (NB*NSEQ)     // 4096

// Single dynamic-smem symbol (typed via casts in each kernel)
extern __shared__ __align__(128) unsigned char dynsmem[];

// ---------------------------------------------------------------------------
// Scratch (allocation-free -> __device__ globals)
// ---------------------------------------------------------------------------
__device__ float g_ao0[ROWS*DMODEL];  // attention output (split 0)
__device__ float g_ao1[ROWS*DMODEL];  // attention output (split 1, rows i>=512)
__device__ float g_bias[(size_t)NB*NSEQ*NSEQ];                    // rel-bias, head-invariant
__device__ __nv_bfloat16 g_uoh[ROWS*EOUT], g_uol[ROWS*EOUT];      // silu(nx@uvqk) hi/lo
__device__ __nv_bfloat16 g_nxh[ROWS*DMODEL], g_nxl[ROWS*DMODEL];  // LN(x) hi/lo
__device__ __nv_bfloat16 g_th [ROWS*DMODEL], g_tl [ROWS*DMODEL];  // u*LN(ao) hi/lo
__device__ __nv_bfloat16 g_B1h[EOUT*DMODEL], g_B1l[EOUT*DMODEL];  // uvqk^T  [2048][512]
__device__ __nv_bfloat16 g_B2h[DMODEL*DMODEL], g_B2l[DMODEL*DMODEL]; // o_w^T [512][512]

// ---------------------------------------------------------------------------
// mma.sync helpers (sm_80-era PTX, legal on compute_103)
// ---------------------------------------------------------------------------
__device__ __forceinline__ uint32_t smem_to_u32(const void* p) {
    uint32_t a;
    asm("{ .reg .u64 t; cvta.to.shared.u64 t, %1; cvt.u32.u64 %0, t; }" : "=r"(a) : "l"(p));
    return a;
}
__device__ __forceinline__ void ldsm4(uint32_t* r, uint32_t addr) {
    asm volatile("ldmatrix.sync.aligned.m8n8.x4.shared.b16 {%0,%1,%2,%3}, [%4];"
        : "=r"(r[0]), "=r"(r[1]), "=r"(r[2]), "=r"(r[3]) : "r"(addr));
}
__device__ __forceinline__ void ldsm4t(uint32_t* r, uint32_t addr) {
    asm volatile("ldmatrix.sync.aligned.m8n8.x4.trans.shared.b16 {%0,%1,%2,%3}, [%4];"
        : "=r"(r[0]), "=r"(r[1]), "=r"(r[2]), "=r"(r[3]) : "r"(addr));
}
__device__ __forceinline__ void mma16816(float* c, const uint32_t* a, const uint32_t* b) {
    asm volatile("mma.sync.aligned.m16n8k16.row.col.f32.bf16.bf16.f32 "
        "{%0,%1,%2,%3}, {%4,%5,%6,%7}, {%8,%9}, {%0,%1,%2,%3};"
        : "+f"(c[0]), "+f"(c[1]), "+f"(c[2]), "+f"(c[3])
        : "r"(a[0]), "r"(a[1]), "r"(a[2]), "r"(a[3]), "r"(b[0]), "r"(b[1]));
}
__device__ __forceinline__ void cp16(uint32_t s, const void* g) {
    asm volatile("cp.async.cg.shared.global [%0], [%1], 16;" :: "r"(s), "l"(g));
}
#define CP_COMMIT() asm volatile("cp.async.commit_group;")
#define CP_WAIT(N)  asm volatile("cp.async.wait_group %0;" :: "n"(N))

__device__ __forceinline__ uint32_t pack_hi(float a, float b) {
    __nv_bfloat162 t = __floats2bfloat162_rn(a, b);
    return *(uint32_t*)&t;
}
__device__ __forceinline__ uint32_t pack_lo(float a, float b, uint32_t hi) {
    __nv_bfloat162 h = *(__nv_bfloat162*)&hi;
    __nv_bfloat162 t = __floats2bfloat162_rn(a - __bfloat162float(h.x),
                                             b - __bfloat162float(h.y));
    return *(uint32_t*)&t;
}

// ---------------------------------------------------------------------------
// Block reduction (256 threads)
// ---------------------------------------------------------------------------
__device__ __forceinline__ float blk_reduce_sum(float v, float* sm) {
    int tid = threadIdx.x;
    #pragma unroll
    for (int o = 16; o > 0; o >>= 1) v += __shfl_down_sync(0xffffffffu, v, o);
    if ((tid & 31) == 0) sm[tid >> 5] = v;
    __syncthreads();
    if (tid < 32) {
        float t = (tid < 8) ? sm[tid] : 0.0f;
        #pragma unroll
        for (int o = 4; o > 0; o >>= 1) t += __shfl_down_sync(0xffffffffu, t, o);
        if (tid == 0) sm[0] = t;
    }
    __syncthreads();
    float r = sm[0];
    __syncthreads();
    return r;
}

__device__ __forceinline__ void split_write(__nv_bfloat16* ph, __nv_bfloat16* pl,
                                            size_t idx, float v) {
    __nv_bfloat16 h = __float2bfloat16(v);
    ph[idx] = h;
    pl[idx] = __float2bfloat16(v - __bfloat162float(h));
}

// ---------------------------------------------------------------------------
// Kernel: relative bias precompute.  grid=4096 (b*1024+i), block=256 (4 j each)
// ---------------------------------------------------------------------------
__global__ void bias_kernel(const int* __restrict__ ts,
                            const float* __restrict__ tw,
                            const float* __restrict__ pw) {
    int bi = blockIdx.x, b = bi >> 10, i = bi & 1023;
    int j = threadIdx.x * 4;
    int ip = i + 1; if (ip > NSEQ - 1) ip = NSEQ - 1;
    int tl = ts[(b << 10) + ip];
    int4 tj = *(const int4*)&ts[(b << 10) + j];
    float4 o;
    {
        int d = tl - tj.x; if (d < 0) d = -d; if (d < 1) d = 1;
        int bk = (int)(__logf((float)d) * 3.3222591f);
        bk = min(max(bk, 0), 64);
        o.x = pw[j - i + NSEQ - 1] + tw[bk];
    }
    {
        int d = tl - tj.y; if (d < 0) d = -d; if (d < 1) d = 1;
        int bk = (int)(__logf((float)d) * 3.3222591f);
        bk = min(max(bk, 0), 64);
        o.y = pw[j + 1 - i + NSEQ - 1] + tw[bk];
    }
    {
        int d = tl - tj.z; if (d < 0) d = -d; if (d < 1) d = 1;
        int bk = (int)(__logf((float)d) * 3.3222591f);
        bk = min(max(bk, 0), 64);
        o.z = pw[j + 2 - i + NSEQ - 1] + tw[bk];
    }
    {
        int d = tl - tj.w; if (d < 0) d = -d; if (d < 1) d = 1;
        int bk = (int)(__logf((float)d) * 3.3222591f);
        bk = min(max(bk, 0), 64);
        o.w = pw[j + 3 - i + NSEQ - 1] + tw[bk];
    }
    *(float4*)&g_bias[((size_t)(b << 10) + i) * NSEQ + j] = o;
}

// ---------------------------------------------------------------------------
// Kernel 1: LayerNorm(x) -> g_nxh/g_nxl          grid=4096, block=256
// ---------------------------------------------------------------------------
__global__ void ln_x_kernel(const float* __restrict__ x,
                            const float* __restrict__ w,
                            const float* __restrict__ b) {
    __shared__ float sm[8];
    int r = blockIdx.x, tid = threadIdx.x;
    const float* xr = x + (size_t)r * DMODEL;
    float v0 = xr[tid], v1 = xr[tid + 256];
    float mean = blk_reduce_sum(v0 + v1, sm) * (1.0f / DMODEL);
    float d0 = v0 - mean, d1 = v1 - mean;
    float var = blk_reduce_sum(d0*d0 + d1*d1, sm) * (1.0f / DMODEL);
    float inv = rsqrtf(var + 1e-5f);
    split_write(g_nxh, g_nxl, (size_t)r*DMODEL + tid,       d0*inv*w[tid]       + b[tid]);
    split_write(g_nxh, g_nxl, (size_t)r*DMODEL + tid + 256, d1*inv*w[tid + 256] + b[tid + 256]);
}

// ---------------------------------------------------------------------------
// Kernel 4: t = u * LayerNorm(ao0 [+ ao1])  -> g_th/g_tl   grid=4096, block=256
// ---------------------------------------------------------------------------
__global__ void ln_a_kernel(const float* __restrict__ w,
                            const float* __restrict__ b) {
    __shared__ float sm[8];
    int r = blockIdx.x, tid = threadIdx.x;
    const bool two = (r & 1023) >= 512;
    size_t base = (size_t)r * DMODEL;
    float v0 = g_ao0[base + tid], v1 = g_ao0[base + tid + 256];
    if (two) { v0 += g_ao1[base + tid]; v1 += g_ao1[base + tid + 256]; }
    float mean = blk_reduce_sum(v0 + v1, sm) * (1.0f / DMODEL);
    float d0 = v0 - mean, d1 = v1 - mean;
    float var = blk_reduce_sum(d0*d0 + d1*d1, sm) * (1.0f / DMODEL);
    float inv = rsqrtf(var + 1e-5f);
    size_t ub = (size_t)r * EOUT;
    float u0 = __bfloat162float(g_uoh[ub + tid])       + __bfloat162float(g_uol[ub + tid]);
    float u1 = __bfloat162float(g_uoh[ub + tid + 256]) + __bfloat162float(g_uol[ub + tid + 256]);
    split_write(g_th, g_tl, base + tid,       (d0*inv*w[tid]       + b[tid])       * u0);
    split_write(g_th, g_tl, base + tid + 256, (d1*inv*w[tid + 256] + b[tid + 256]) * u1);
}

// ---------------------------------------------------------------------------
// Transpose + bf16 split: in[K][N] fp32 -> oh/ol[N][K] bf16
// ---------------------------------------------------------------------------
__global__ void tsplit_kernel(const float* __restrict__ in,
                              __nv_bfloat16* __restrict__ oh,
                              __nv_bfloat16* __restrict__ ol,
                              int K, int N) {
    __shared__ float tile[32][33];
    int n0 = blockIdx.x * 32, k0 = blockIdx.y * 32;
    int tx = threadIdx.x, ty = threadIdx.y;
    #pragma unroll
    for (int i = 0; i < 4; i++)
        tile[ty + i*8][tx] = in[(size_t)(k0 + ty + i*8) * N + n0 + tx];
    __syncthreads();
    #pragma unroll
    for (int i = 0; i < 4; i++) {
        float v = tile[tx][ty + i*8];
        __nv_bfloat16 h = __float2bfloat16(v);
        size_t o = (size_t)(n0 + ty + i*8) * K + k0 + tx;
        oh[o] = h;
        ol[o] = __float2bfloat16(v - __bfloat162float(h));
    }
}

// ---------------------------------------------------------------------------
// 3-stage cp.async bf16-split GEMM (HMMA), 64x64 warp tiles.
// CTA 128x128, 4 warps (2m x 2n), K chunks of 64, 1 compute sync/chunk.
// EPI 0: silu -> hi/lo bf16.  EPI 1: fp32 +bias+resid, pm mask.
// ---------------------------------------------------------------------------
#define KSEG   512
#define NCHUNK 24
#define SPAD   72
#define GSTAGE (2*128*SPAD*2)        // bytes per stage (A tile + B tile)
#define SMEM_GEMM (3*GSTAGE)

template<int EPI>
__global__ void __launch_bounds__(128)
mma_gemm(const __nv_bfloat16* __restrict__ A0, const __nv_bfloat16* __restrict__ A1,
         const __nv_bfloat16* __restrict__ A2,
         const __nv_bfloat16* __restrict__ B0, const __nv_bfloat16* __restrict__ B1,
         const __nv_bfloat16* __restrict__ B2,
         float* __restrict__ C,
         __nv_bfloat16* __restrict__ Ch, __nv_bfloat16* __restrict__ Cl, int N,
         const float* __restrict__ bias, const float* __restrict__ resid,
         const unsigned char* __restrict__ pm) {
    const int tid = threadIdx.x, wid = tid >> 5, lane = tid & 31;
    const int bm = blockIdx.y * 128, bn = blockIdx.x * 128;
    const int wm = wid & 1, wn = wid >> 1;   // warp tile (wm*64, wn*64)

    const __nv_bfloat16* Aseg[3] = {A0, A1, A2};
    const __nv_bfloat16* Bseg[3] = {B0, B1, B2};

    const uint32_t sbase = smem_to_u32(dynsmem);
    const int lrow = lane & 15, lcol = (lane >> 4) * 8;

    float acc[4][8][4];
    #pragma unroll
    for (int i = 0; i < 4; i++)
        #pragma unroll
        for (int j = 0; j < 8; j++)
            #pragma unroll
            for (int k = 0; k < 4; k++) acc[i][j][k] = 0.0f;

    auto issue = [&](int c, int stg) {
        const __nv_bfloat16* Ab = Aseg[c >> 3];
        const __nv_bfloat16* Bb = Bseg[c >> 3];
        const int kc = (c & 7) * 64;
        const uint32_t st = sbase + stg * GSTAGE;
        #pragma unroll
        for (int i = 0; i < 8; i++) {
            int id = i*128 + tid;                 // 0..1023
            int row = id >> 3, col = (id & 7) * 8;
            cp16(st + (row*SPAD + col)*2,
                 Ab + (size_t)(bm + row)*KSEG + kc + col);
            cp16(st + (128*SPAD + row*SPAD + col)*2,
                 Bb + (size_t)(bn + row)*KSEG + kc + col);
        }
        CP_COMMIT();
    };

    issue(0, 0);
    issue(1, 1);
    int stg = 0;
    for (int c = 0; c < NCHUNK; c++) {
        if (c + 1 < NCHUNK) { CP_WAIT(1); } else { CP_WAIT(0); }
        __syncthreads();
        if (c + 2 < NCHUNK) {
            int ns = stg + 2; if (ns >= 3) ns -= 3;
            issue(c + 2, ns);
        }
        const uint32_t sa = sbase + stg * GSTAGE;
        const uint32_t sb = sa + 128*SPAD*2;
        #pragma unroll
        for (int ks = 0; ks < 4; ks++) {
            uint32_t af[4][4], bf[4][4];
            #pragma unroll
            for (int fm = 0; fm < 4; fm++)
                ldsm4(af[fm], sa + ((wm*64 + fm*16 + lrow)*SPAD + ks*16 + lcol)*2);
            #pragma unroll
            for (int g = 0; g < 4; g++)
                ldsm4(bf[g], sb + ((wn*64 + g*16 + lrow)*SPAD + ks*16 + lcol)*2);
            #pragma unroll
            for (int fm = 0; fm < 4; fm++)
                #pragma unroll
                for (int fn = 0; fn < 8; fn++) {
                    uint32_t bb[2] = { bf[fn >> 1][(fn & 1) + 0],
                                       bf[fn >> 1][(fn & 1) + 2] };
                    mma16816(acc[fm][fn], af[fm], bb);
                }
        }
        if (++stg == 3) stg = 0;
    }

    #pragma unroll
    for (int fm = 0; fm < 4; fm++) {
        #pragma unroll
        for (int half = 0; half < 2; half++) {
            int r = bm + wm*64 + fm*16 + (lane >> 2) + half*8;
            #pragma unroll
            for (int fn = 0; fn < 8; fn++) {
                int cc = bn + wn*64 + fn*8 + (lane & 3)*2;
                float vx = acc[fm][fn][half*2 + 0];
                float vy = acc[fm][fn][half*2 + 1];
                if (EPI == 0) {
                    vx = vx / (1.0f + __expf(-vx));
                    vy = vy / (1.0f + __expf(-vy));
                    uint32_t hi = pack_hi(vx, vy);
                    uint32_t lo = pack_lo(vx, vy, hi);
                    *(uint32_t*)&Ch[(size_t)r*N + cc] = hi;
                    *(uint32_t*)&Cl[(size_t)r*N + cc] = lo;
                } else {
                    vx += bias[cc]     + resid[(size_t)r*N + cc];
                    vy += bias[cc + 1] + resid[(size_t)r*N + cc + 1];
                    if (pm[r]) { vx = 0.0f; vy = 0.0f; }
                    float2 v = {vx, vy};
                    *(float2*)&C[(size_t)r*N + cc] = v;
                }
            }
        }
    }
}

// ---------------------------------------------------------------------------
// Kernel 3: causal silu-attention (HMMA), precomputed bias,
// double-buffered K/V cp.async pipeline.
// grid (32 bh, 24 work), block 128.  Work mapping (big-first) as R8.
// ---------------------------------------------------------------------------
#define ATPAD 72
#define ATILE (64*ATPAD*2)           // 9216 B per bf16 tile
#define ATT_KV (2*ATILE)             // after Qh,Ql
#define ATT_PM (ATT_KV + 8*ATILE)    // pmj[2][64]
#define SMEM_ATTN (ATT_PM + 2*64*4)

__global__ void __launch_bounds__(128)
attn_kernel(const unsigned char* __restrict__ pm) {
    unsigned char* sm = dynsmem;
    int* pmj = (int*)(sm + ATT_PM);

    const int bh = blockIdx.x, b = bh >> 3, h = bh & 7;
    const int wy = blockIdx.y;
    int it, jlo, jhi, dst;
    if (wy < 16) {
        it = 15 - (wy >> 1);
        int m = (it + 2) >> 1;
        if (wy & 1) { jlo = m; jhi = it + 1; dst = 1; }
        else        { jlo = 0; jhi = m;      dst = 0; }
    } else {
        it = 23 - wy; jlo = 0; jhi = it + 1; dst = 0;
    }
    const int i0 = it * 64;
    const int tid = threadIdx.x, wq = tid >> 5, lane = tid & 31;
    const int lrow = lane & 15, lcol = (lane >> 4) * 8;

    const uint32_t sqh = smem_to_u32(sm);
    const uint32_t sql = sqh + ATILE;

    auto issue_kv = [&](int jt, int s) {
        const uint32_t kh = sqh + ATT_KV + (s*4 + 0)*ATILE;
        const uint32_t kl = sqh + ATT_KV + (s*4 + 1)*ATILE;
        const uint32_t vh = sqh + ATT_KV + (s*4 + 2)*ATILE;
        const uint32_t vl = sqh + ATT_KV + (s*4 + 3)*ATILE;
        const int j0 = jt * 64;
        #pragma unroll
        for (int i = 0; i < 4; i++) {
            int id = i*128 + tid, row = id >> 3, col = (id & 7) * 8;
            size_t bkv = (size_t)(b*NSEQ + j0 + row)*EOUT + h*64 + col;
            uint32_t so = (row*ATPAD + col)*2;
            cp16(kh + so, &g_uoh[bkv + 1536]);
            cp16(kl + so, &g_uol[bkv + 1536]);
            cp16(vh + so, &g_uoh[bkv + 512]);
            cp16(vl + so, &g_uol[bkv + 512]);
        }
        if (tid < 64) pmj[s*64 + tid] = pm[b*NSEQ + j0 + tid];
        CP_COMMIT();
    };

    // Q tiles (cols 1024 + h*64)
    #pragma unroll
    for (int i = 0; i < 4; i++) {
        int id = i*128 + tid, row = id >> 3, col = (id & 7) * 8;
        size_t src = (size_t)(b*NSEQ + i0 + row)*EOUT + 1024 + h*64 + col;
        cp16(sqh + (row*ATPAD + col)*2, &g_uoh[src]);
        cp16(sql + (row*ATPAD + col)*2, &g_uol[src]);
    }
    CP_COMMIT();
    issue_kv(jlo, 0);

    float of[8][4];
    #pragma unroll
    for (int f = 0; f < 8; f++)
        #pragma unroll
        for (int r = 0; r < 4; r++) of[f][r] = 0.0f;

    const int row_lo = wq*16 + (lane >> 2);
    const int col_in = (lane & 3) * 2;

    for (int jt = jlo; jt < jhi; jt++) {
        const int j0 = jt * 64;
        const int s = (jt - jlo) & 1;
        if (jt + 1 < jhi) { issue_kv(jt + 1, s ^ 1); CP_WAIT(1); }
        else              { CP_WAIT(0); }
        __syncthreads();

        const uint32_t skh = sqh + ATT_KV + (s*4 + 0)*ATILE;
        const uint32_t skl = sqh + ATT_KV + (s*4 + 1)*ATILE;
        const uint32_t svh = sqh + ATT_KV + (s*4 + 2)*ATILE;
        const uint32_t svl = sqh + ATT_KV + (s*4 + 3)*ATILE;
        const int* pms = pmj + s*64;

        // ---- Phase A: S = Q K^T (3-term split) ----
        float sc[8][4];
        #pragma unroll
        for (int f = 0; f < 8; f++)
            #pragma unroll
            for (int r = 0; r < 4; r++) sc[f][r] = 0.0f;

        #pragma unroll
        for (int ks = 0; ks < 4; ks++) {
            uint32_t ah[4], al[4], kh[4][4], kl[4][4];
            ldsm4(ah, sqh + ((wq*16 + lrow)*ATPAD + ks*16 + lcol)*2);
            ldsm4(al, sql + ((wq*16 + lrow)*ATPAD + ks*16 + lcol)*2);
            #pragma unroll
            for (int g = 0; g < 4; g++) {
                ldsm4(kh[g], skh + ((g*16 + lrow)*ATPAD + ks*16 + lcol)*2);
                ldsm4(kl[g], skl + ((g*16 + lrow)*ATPAD + ks*16 + lcol)*2);
            }
            #pragma unroll
            for (int fn = 0; fn < 8; fn++) {
                uint32_t bh_[2] = { kh[fn >> 1][(fn & 1) + 0], kh[fn >> 1][(fn & 1) + 2] };
                uint32_t bl_[2] = { kl[fn >> 1][(fn & 1) + 0], kl[fn >> 1][(fn & 1) + 2] };
                mma16816(sc[fn], ah, bh_);
                mma16816(sc[fn], al, bh_);
                mma16816(sc[fn], ah, bl_);
            }
        }

        // ---- Epilogue: +bias (precomputed), silu/N, mask ----
        #pragma unroll
        for (int f = 0; f < 8; f++) {
            int jb = j0 + f*8 + col_in;
            float2 b0 = *(const float2*)&g_bias[((size_t)(b << 10) + i0 + row_lo)     * NSEQ + jb];
            float2 b1 = *(const float2*)&g_bias[((size_t)(b << 10) + i0 + row_lo + 8) * NSEQ + jb];
            #pragma unroll
            for (int r = 0; r < 4; r++) {
                int il = row_lo + ((r >> 1) ? 8 : 0);
                int jl = f*8 + col_in + (r & 1);
                int ig = i0 + il, jg = j0 + jl;
                float bb = (r < 2) ? ((r & 1) ? b0.y : b0.x) : ((r & 1) ? b1.y : b1.x);
                float s2 = sc[f][r] + bb;
                s2 = s2 / (1.0f + __expf(-s2)) * (1.0f / NSEQ);
                if (jg > ig || pms[jl]) s2 = 0.0f;
                sc[f][r] = s2;
            }
        }

        // ---- Phase B: O += S @ V (3-term split; S packed from C-frags) ----
        #pragma unroll
        for (int ks = 0; ks < 4; ks++) {
            uint32_t ah[4], al[4];
            ah[0] = pack_hi(sc[2*ks][0],   sc[2*ks][1]);
            ah[1] = pack_hi(sc[2*ks][2],   sc[2*ks][3]);
            ah[2] = pack_hi(sc[2*ks+1][0], sc[2*ks+1][1]);
            ah[3] = pack_hi(sc[2*ks+1][2], sc[2*ks+1][3]);
            al[0] = pack_lo(sc[2*ks][0],   sc[2*ks][1],   ah[0]);
            al[1] = pack_lo(sc[2*ks][2],   sc[2*ks][3],   ah[1]);
            al[2] = pack_lo(sc[2*ks+1][0], sc[2*ks+1][1], ah[2]);
            al[3] = pack_lo(sc[2*ks+1][2], sc[2*ks+1][3], ah[3]);
            uint32_t voff = ((ks*16 + ((lane >> 3) & 1)*8 + (lane & 7))*ATPAD
                            + (lane >> 4)*8) * 2;
            #pragma unroll
            for (int dg = 0; dg < 4; dg++) {
                uint32_t vh[4], vl[4];
                ldsm4t(vh, svh + voff + dg*16*2);
                ldsm4t(vl, svl + voff + dg*16*2);
                #pragma unroll
                for (int half = 0; half < 2; half++) {
                    int fd = dg*2 + half;
                    uint32_t bh_[2] = { vh[half*2], vh[half*2 + 1] };
                    uint32_t bl_[2] = { vl[half*2], vl[half*2 + 1] };
                    mma16816(of[fd], ah, bh_);
                    mma16816(of[fd], al, bh_);
                    mma16816(of[fd], ah, bl_);
                }
            }
        }
        __syncthreads();   // stage s reusable only after all warps done
    }

    // ---- write O partial ----
    float* aop = dst ? g_ao1 : g_ao0;
    #pragma unroll
    for (int fd = 0; fd < 8; fd++) {
        #pragma unroll
        for (int half = 0; half < 2; half++) {
            int row = i0 + row_lo + half*8;
            int col = h*64 + fd*8 + col_in;
            float2 v = { of[fd][half*2], of[fd][half*2 + 1] };
            *(float2*)&aop[(size_t)(b*NSEQ + row)*DMODEL + col] = v;
        }
    }
}

// ---------------------------------------------------------------------------
// Launch
// ---------------------------------------------------------------------------
extern "C" void kernel_launch(void* const* d_in, const int* in_sizes, int n_in,
                              void* d_out, int out_size) {
    const float*          x      = (const float*)d_in[0];
    const int*            ts     = (const int*)d_in[1];     // int32 (JAX x64 off)
    /* d_in[2] = cm — analytic triu(k=1), unused */
    const unsigned char*  pm     = (const unsigned char*)d_in[3];
    const float*          uvqk   = (const float*)d_in[4];
    const float*          o_w    = (const float*)d_in[5];
    const float*          o_b    = (const float*)d_in[6];
    const float*          ln_x_w = (const float*)d_in[7];
    const float*          ln_x_b = (const float*)d_in[8];
    const float*          ln_a_w = (const float*)d_in[9];
    const float*          ln_a_b = (const float*)d_in[10];
    const float*          ts_w   = (const float*)d_in[11];
    const float*          pos_w  = (const float*)d_in[12];
    float*                out    = (float*)d_out;

    __nv_bfloat16 *p_uoh, *p_uol, *p_nxh, *p_nxl, *p_th, *p_tl;
    __nv_bfloat16 *p_B1h, *p_B1l, *p_B2h, *p_B2l;
    cudaGetSymbolAddress((void**)&p_uoh, g_uoh);
    cudaGetSymbolAddress((void**)&p_uol, g_uol);
    cudaGetSymbolAddress((void**)&p_nxh, g_nxh);
    cudaGetSymbolAddress((void**)&p_nxl, g_nxl);
    cudaGetSymbolAddress((void**)&p_th,  g_th);
    cudaGetSymbolAddress((void**)&p_tl,  g_tl);
    cudaGetSymbolAddress((void**)&p_B1h, g_B1h);
    cudaGetSymbolAddress((void**)&p_B1l, g_B1l);
    cudaGetSymbolAddress((void**)&p_B2h, g_B2h);
    cudaGetSymbolAddress((void**)&p_B2l, g_B2l);

    cudaFuncSetAttribute(mma_gemm<0>, cudaFuncAttributeMaxDynamicSharedMemorySize, SMEM_GEMM);
    cudaFuncSetAttribute(mma_gemm<1>, cudaFuncAttributeMaxDynamicSharedMemorySize, SMEM_GEMM);
    cudaFuncSetAttribute(attn_kernel, cudaFuncAttributeMaxDynamicSharedMemorySize, SMEM_ATTN);

    // 0. weight transpose+split, bias precompute
    tsplit_kernel<<<dim3(EOUT/32, DMODEL/32), dim3(32, 8)>>>(uvqk, p_B1h, p_B1l, DMODEL, EOUT);
    tsplit_kernel<<<dim3(DMODEL/32, DMODEL/32), dim3(32, 8)>>>(o_w, p_B2h, p_B2l, DMODEL, DMODEL);
    bias_kernel<<<NB*NSEQ, 256>>>(ts, ts_w, pos_w);

    // 1. LN(x) -> bf16 hi/lo
    ln_x_kernel<<<ROWS, 256>>>(x, ln_x_w, ln_x_b);

    // 2. uvqk GEMM + silu -> hi/lo bf16
    mma_gemm<0><<<dim3(EOUT/128, ROWS/128), 128, SMEM_GEMM>>>(
        p_nxh, p_nxl, p_nxh, p_B1h, p_B1h, p_B1l,
        nullptr, p_uoh, p_uol, EOUT, nullptr, nullptr, nullptr);

    // 3. attention (HMMA, split long query tiles, double-buffered K/V)
    attn_kernel<<<dim3(NB*NH, 24), 128, SMEM_ATTN>>>(pm);

    // 4. t = u * LN(ao)
    ln_a_kernel<<<ROWS, 256>>>(ln_a_w, ln_a_b);

    // 5. y = t @ o_w + o_b + x (pm-masked)
    mma_gemm<1><<<dim3(DMODEL/128, ROWS/128), 128, SMEM_GEMM>>>(
        p_th, p_tl, p_th, p_B2h, p_B2h, p_B2l,
        out, nullptr, nullptr, DMODEL, o_b, x, pm);
}

// round 11
// speedup vs baseline: 1.1979x; 1.1979x over previous
#include <cuda_runtime.h>
#include <cuda_bf16.h>
#include <cstdint>
#include <math.h>

// Problem constants
#define NB     4
#define NSEQ   1024
#define DMODEL 512
#define NH     8
#define HD     64
#define EOUT   2048          // 2*H*Dv + 2*H*Dq
#define ROWS   (NB*NSEQ)     // 4096

// Single dynamic-smem symbol (typed via casts in each kernel)
extern __shared__ __align__(128) unsigned char dynsmem[];

// ---------------------------------------------------------------------------
// Scratch (allocation-free -> __device__ globals)
// ---------------------------------------------------------------------------
__device__ float g_ao0[ROWS*DMODEL];  // attention output (split 0)
__device__ float g_ao1[ROWS*DMODEL];  // attention output (split 1, rows i>=512)
__device__ float g_bias[(size_t)NB*NSEQ*NSEQ];                    // rel-bias, head-invariant
__device__ __nv_bfloat16 g_uoh[ROWS*EOUT], g_uol[ROWS*EOUT];      // silu(nx@uvqk) hi/lo
__device__ __nv_bfloat16 g_nxh[ROWS*DMODEL], g_nxl[ROWS*DMODEL];  // LN(x) hi/lo
__device__ __nv_bfloat16 g_th [ROWS*DMODEL], g_tl [ROWS*DMODEL];  // u*LN(ao) hi/lo
__device__ __nv_bfloat16 g_B1h[EOUT*DMODEL], g_B1l[EOUT*DMODEL];  // uvqk^T  [2048][512]
__device__ __nv_bfloat16 g_B2h[DMODEL*DMODEL], g_B2l[DMODEL*DMODEL]; // o_w^T [512][512]

// ---------------------------------------------------------------------------
// mma.sync helpers (sm_80-era PTX, legal on compute_103)
// ---------------------------------------------------------------------------
__device__ __forceinline__ uint32_t smem_to_u32(const void* p) {
    uint32_t a;
    asm("{ .reg .u64 t; cvta.to.shared.u64 t, %1; cvt.u32.u64 %0, t; }" : "=r"(a) : "l"(p));
    return a;
}
__device__ __forceinline__ void ldsm4(uint32_t* r, uint32_t addr) {
    asm volatile("ldmatrix.sync.aligned.m8n8.x4.shared.b16 {%0,%1,%2,%3}, [%4];"
        : "=r"(r[0]), "=r"(r[1]), "=r"(r[2]), "=r"(r[3]) : "r"(addr));
}
__device__ __forceinline__ void ldsm4t(uint32_t* r, uint32_t addr) {
    asm volatile("ldmatrix.sync.aligned.m8n8.x4.trans.shared.b16 {%0,%1,%2,%3}, [%4];"
        : "=r"(r[0]), "=r"(r[1]), "=r"(r[2]), "=r"(r[3]) : "r"(addr));
}
__device__ __forceinline__ void mma16816(float* c, const uint32_t* a, const uint32_t* b) {
    asm volatile("mma.sync.aligned.m16n8k16.row.col.f32.bf16.bf16.f32 "
        "{%0,%1,%2,%3}, {%4,%5,%6,%7}, {%8,%9}, {%0,%1,%2,%3};"
        : "+f"(c[0]), "+f"(c[1]), "+f"(c[2]), "+f"(c[3])
        : "r"(a[0]), "r"(a[1]), "r"(a[2]), "r"(a[3]), "r"(b[0]), "r"(b[1]));
}
__device__ __forceinline__ void cp16(uint32_t s, const void* g) {
    asm volatile("cp.async.cg.shared.global [%0], [%1], 16;" :: "r"(s), "l"(g));
}
#define CP_COMMIT() asm volatile("cp.async.commit_group;")
#define CP_WAIT(N)  asm volatile("cp.async.wait_group %0;" :: "n"(N))

__device__ __forceinline__ uint32_t pack_hi(float a, float b) {
    __nv_bfloat162 t = __floats2bfloat162_rn(a, b);
    return *(uint32_t*)&t;
}
__device__ __forceinline__ uint32_t pack_lo(float a, float b, uint32_t hi) {
    __nv_bfloat162 h = *(__nv_bfloat162*)&hi;
    __nv_bfloat162 t = __floats2bfloat162_rn(a - __bfloat162float(h.x),
                                             b - __bfloat162float(h.y));
    return *(uint32_t*)&t;
}

// ---------------------------------------------------------------------------
// Block reduction (256 threads)
// ---------------------------------------------------------------------------
__device__ __forceinline__ float blk_reduce_sum(float v, float* sm) {
    int tid = threadIdx.x;
    #pragma unroll
    for (int o = 16; o > 0; o >>= 1) v += __shfl_down_sync(0xffffffffu, v, o);
    if ((tid & 31) == 0) sm[tid >> 5] = v;
    __syncthreads();
    if (tid < 32) {
        float t = (tid < 8) ? sm[tid] : 0.0f;
        #pragma unroll
        for (int o = 4; o > 0; o >>= 1) t += __shfl_down_sync(0xffffffffu, t, o);
        if (tid == 0) sm[0] = t;
    }
    __syncthreads();
    float r = sm[0];
    __syncthreads();
    return r;
}

__device__ __forceinline__ void split_write(__nv_bfloat16* ph, __nv_bfloat16* pl,
                                            size_t idx, float v) {
    __nv_bfloat16 h = __float2bfloat16(v);
    ph[idx] = h;
    pl[idx] = __float2bfloat16(v - __bfloat162float(h));
}

// ---------------------------------------------------------------------------
// Kernel: relative bias precompute.  grid=4096 (b*1024+i), block=256 (4 j each)
// ---------------------------------------------------------------------------
__global__ void bias_kernel(const int* __restrict__ ts,
                            const float* __restrict__ tw,
                            const float* __restrict__ pw) {
    int bi = blockIdx.x, b = bi >> 10, i = bi & 1023;
    int j = threadIdx.x * 4;
    int ip = i + 1; if (ip > NSEQ - 1) ip = NSEQ - 1;
    int tl = ts[(b << 10) + ip];
    int4 tj = *(const int4*)&ts[(b << 10) + j];
    float4 o;
    {
        int d = tl - tj.x; if (d < 0) d = -d; if (d < 1) d = 1;
        int bk = (int)(__logf((float)d) * 3.3222591f);
        bk = min(max(bk, 0), 64);
        o.x = pw[j - i + NSEQ - 1] + tw[bk];
    }
    {
        int d = tl - tj.y; if (d < 0) d = -d; if (d < 1) d = 1;
        int bk = (int)(__logf((float)d) * 3.3222591f);
        bk = min(max(bk, 0), 64);
        o.y = pw[j + 1 - i + NSEQ - 1] + tw[bk];
    }
    {
        int d = tl - tj.z; if (d < 0) d = -d; if (d < 1) d = 1;
        int bk = (int)(__logf((float)d) * 3.3222591f);
        bk = min(max(bk, 0), 64);
        o.z = pw[j + 2 - i + NSEQ - 1] + tw[bk];
    }
    {
        int d = tl - tj.w; if (d < 0) d = -d; if (d < 1) d = 1;
        int bk = (int)(__logf((float)d) * 3.3222591f);
        bk = min(max(bk, 0), 64);
        o.w = pw[j + 3 - i + NSEQ - 1] + tw[bk];
    }
    *(float4*)&g_bias[((size_t)(b << 10) + i) * NSEQ + j] = o;
}

// ---------------------------------------------------------------------------
// Kernel 1: LayerNorm(x) -> g_nxh/g_nxl          grid=4096, block=256
// ---------------------------------------------------------------------------
__global__ void ln_x_kernel(const float* __restrict__ x,
                            const float* __restrict__ w,
                            const float* __restrict__ b) {
    __shared__ float sm[8];
    int r = blockIdx.x, tid = threadIdx.x;
    const float* xr = x + (size_t)r * DMODEL;
    float v0 = xr[tid], v1 = xr[tid + 256];
    float mean = blk_reduce_sum(v0 + v1, sm) * (1.0f / DMODEL);
    float d0 = v0 - mean, d1 = v1 - mean;
    float var = blk_reduce_sum(d0*d0 + d1*d1, sm) * (1.0f / DMODEL);
    float inv = rsqrtf(var + 1e-5f);
    split_write(g_nxh, g_nxl, (size_t)r*DMODEL + tid,       d0*inv*w[tid]       + b[tid]);
    split_write(g_nxh, g_nxl, (size_t)r*DMODEL + tid + 256, d1*inv*w[tid + 256] + b[tid + 256]);
}

// ---------------------------------------------------------------------------
// Kernel 4: t = u * LayerNorm(ao0 [+ ao1])  -> g_th/g_tl   grid=4096, block=256
// ---------------------------------------------------------------------------
__global__ void ln_a_kernel(const float* __restrict__ w,
                            const float* __restrict__ b) {
    __shared__ float sm[8];
    int r = blockIdx.x, tid = threadIdx.x;
    const bool two = (r & 1023) >= 512;
    size_t base = (size_t)r * DMODEL;
    float v0 = g_ao0[base + tid], v1 = g_ao0[base + tid + 256];
    if (two) { v0 += g_ao1[base + tid]; v1 += g_ao1[base + tid + 256]; }
    float mean = blk_reduce_sum(v0 + v1, sm) * (1.0f / DMODEL);
    float d0 = v0 - mean, d1 = v1 - mean;
    float var = blk_reduce_sum(d0*d0 + d1*d1, sm) * (1.0f / DMODEL);
    float inv = rsqrtf(var + 1e-5f);
    size_t ub = (size_t)r * EOUT;
    float u0 = __bfloat162float(g_uoh[ub + tid])       + __bfloat162float(g_uol[ub + tid]);
    float u1 = __bfloat162float(g_uoh[ub + tid + 256]) + __bfloat162float(g_uol[ub + tid + 256]);
    split_write(g_th, g_tl, base + tid,       (d0*inv*w[tid]       + b[tid])       * u0);
    split_write(g_th, g_tl, base + tid + 256, (d1*inv*w[tid + 256] + b[tid + 256]) * u1);
}

// ---------------------------------------------------------------------------
// Transpose + bf16 split: in[K][N] fp32 -> oh/ol[N][K] bf16
// ---------------------------------------------------------------------------
__global__ void tsplit_kernel(const float* __restrict__ in,
                              __nv_bfloat16* __restrict__ oh,
                              __nv_bfloat16* __restrict__ ol,
                              int K, int N) {
    __shared__ float tile[32][33];
    int n0 = blockIdx.x * 32, k0 = blockIdx.y * 32;
    int tx = threadIdx.x, ty = threadIdx.y;
    #pragma unroll
    for (int i = 0; i < 4; i++)
        tile[ty + i*8][tx] = in[(size_t)(k0 + ty + i*8) * N + n0 + tx];
    __syncthreads();
    #pragma unroll
    for (int i = 0; i < 4; i++) {
        float v = tile[tx][ty + i*8];
        __nv_bfloat16 h = __float2bfloat16(v);
        size_t o = (size_t)(n0 + ty + i*8) * K + k0 + tx;
        oh[o] = h;
        ol[o] = __float2bfloat16(v - __bfloat162float(h));
    }
}

// ---------------------------------------------------------------------------
// Fused 3-term bf16-split GEMM (HMMA): C = Ah@Bh^T + Al@Bh^T + Ah@Bl^T.
// Loads the 4 distinct tiles (Ah,Al,Bh,Bl) ONCE per K-chunk; all 3 terms run
// out of registers.  CTA 128x128, 8 warps (2m x 4n, 64x32 warp tile),
// K chunks of 32, 2-stage cp.async pipeline.  2 CTAs/SM (smem 80KB, regs<=128).
// EPI 0: silu -> hi/lo bf16.  EPI 1: fp32 +bias+resid, pm mask.
// ---------------------------------------------------------------------------
#define KSEG   512
#define KCH    32
#define NCH    (KSEG/KCH)            // 16
#define TPAD   40                    // 32 + 8 elems -> 80B row stride, conflict-free
#define TBYTES (128*TPAD*2)          // 10240 B per tile
#define STAGE4 (4*TBYTES)            // Ah,Al,Bh,Bl per stage
#define SMEM_GEMM (2*STAGE4)         // 81920 B

template<int EPI>
__global__ void __launch_bounds__(256, 2)
mma_gemm(const __nv_bfloat16* __restrict__ Ah, const __nv_bfloat16* __restrict__ Al,
         const __nv_bfloat16* __restrict__ Bh, const __nv_bfloat16* __restrict__ Bl,
         float* __restrict__ C,
         __nv_bfloat16* __restrict__ Ch, __nv_bfloat16* __restrict__ Cl, int N,
         const float* __restrict__ bias, const float* __restrict__ resid,
         const unsigned char* __restrict__ pm) {
    const int tid = threadIdx.x, wid = tid >> 5, lane = tid & 31;
    const int bm = blockIdx.y * 128, bn = blockIdx.x * 128;
    const int wm = wid & 1, wn = wid >> 1;     // warp tile (wm*64, wn*32)

    const uint32_t sbase = smem_to_u32(dynsmem);
    const int lrow = lane & 15, lcol = (lane >> 4) * 8;
    const int crow = tid >> 2, ccol = (tid & 3) * 8;  // cp coords: 64 rows/pass, 4x16B/row

    float acc[4][4][4];
    #pragma unroll
    for (int i = 0; i < 4; i++)
        #pragma unroll
        for (int j = 0; j < 4; j++)
            #pragma unroll
            for (int k = 0; k < 4; k++) acc[i][j][k] = 0.0f;

    auto issue = [&](int c, int stg) {
        const int kc = c * KCH;
        const uint32_t st = sbase + stg * STAGE4;
        #pragma unroll
        for (int i = 0; i < 2; i++) {
            int row = crow + i*64;
            uint32_t so = (row*TPAD + ccol)*2;
            cp16(st + 0*TBYTES + so, Ah + (size_t)(bm + row)*KSEG + kc + ccol);
            cp16(st + 1*TBYTES + so, Al + (size_t)(bm + row)*KSEG + kc + ccol);
            cp16(st + 2*TBYTES + so, Bh + (size_t)(bn + row)*KSEG + kc + ccol);
            cp16(st + 3*TBYTES + so, Bl + (size_t)(bn + row)*KSEG + kc + ccol);
        }
        CP_COMMIT();
    };

    issue(0, 0);
    for (int c = 0; c < NCH; c++) {
        if (c + 1 < NCH) { issue(c + 1, (c + 1) & 1); CP_WAIT(1); }
        else             { CP_WAIT(0); }
        __syncthreads();
        const uint32_t st = sbase + (c & 1) * STAGE4;
        const uint32_t sah = st, sal = st + TBYTES;
        const uint32_t sbh = st + 2*TBYTES, sbl = st + 3*TBYTES;
        #pragma unroll
        for (int ks = 0; ks < 2; ks++) {
            const int ko = ks * 16;
            uint32_t afh[4][4], afl[4][4], bfh[2][4], bfl[2][4];
            #pragma unroll
            for (int fm = 0; fm < 4; fm++) {
                afh[fm][0] = 0;  // placate compiler; overwritten by ldsm
                ldsm4(afh[fm], sah + ((wm*64 + fm*16 + lrow)*TPAD + ko + lcol)*2);
            }
            #pragma unroll
            for (int g = 0; g < 2; g++)
                ldsm4(bfh[g], sbh + ((wn*32 + g*16 + lrow)*TPAD + ko + lcol)*2);
            // term 1: Ah * Bh
            #pragma unroll
            for (int fm = 0; fm < 4; fm++)
                #pragma unroll
                for (int fn = 0; fn < 4; fn++) {
                    uint32_t bb[2] = { bfh[fn >> 1][(fn & 1) + 0],
                                       bfh[fn >> 1][(fn & 1) + 2] };
                    mma16816(acc[fm][fn], afh[fm], bb);
                }
            // term 2: Al * Bh
            #pragma unroll
            for (int fm = 0; fm < 4; fm++)
                ldsm4(afl[fm], sal + ((wm*64 + fm*16 + lrow)*TPAD + ko + lcol)*2);
            #pragma unroll
            for (int fm = 0; fm < 4; fm++)
                #pragma unroll
                for (int fn = 0; fn < 4; fn++) {
                    uint32_t bb[2] = { bfh[fn >> 1][(fn & 1) + 0],
                                       bfh[fn >> 1][(fn & 1) + 2] };
                    mma16816(acc[fm][fn], afl[fm], bb);
                }
            // term 3: Ah * Bl
            #pragma unroll
            for (int g = 0; g < 2; g++)
                ldsm4(bfl[g], sbl + ((wn*32 + g*16 + lrow)*TPAD + ko + lcol)*2);
            #pragma unroll
            for (int fm = 0; fm < 4; fm++)
                #pragma unroll
                for (int fn = 0; fn < 4; fn++) {
                    uint32_t bb[2] = { bfl[fn >> 1][(fn & 1) + 0],
                                       bfl[fn >> 1][(fn & 1) + 2] };
                    mma16816(acc[fm][fn], afh[fm], bb);
                }
        }
        __syncthreads();
    }

    #pragma unroll
    for (int fm = 0; fm < 4; fm++) {
        #pragma unroll
        for (int half = 0; half < 2; half++) {
            int r = bm + wm*64 + fm*16 + (lane >> 2) + half*8;
            #pragma unroll
            for (int fn = 0; fn < 4; fn++) {
                int cc = bn + wn*32 + fn*8 + (lane & 3)*2;
                float vx = acc[fm][fn][half*2 + 0];
                float vy = acc[fm][fn][half*2 + 1];
                if (EPI == 0) {
                    vx = vx / (1.0f + __expf(-vx));
                    vy = vy / (1.0f + __expf(-vy));
                    uint32_t hi = pack_hi(vx, vy);
                    uint32_t lo = pack_lo(vx, vy, hi);
                    *(uint32_t*)&Ch[(size_t)r*N + cc] = hi;
                    *(uint32_t*)&Cl[(size_t)r*N + cc] = lo;
                } else {
                    vx += bias[cc]     + resid[(size_t)r*N + cc];
                    vy += bias[cc + 1] + resid[(size_t)r*N + cc + 1];
                    if (pm[r]) { vx = 0.0f; vy = 0.0f; }
                    float2 v = {vx, vy};
                    *(float2*)&C[(size_t)r*N + cc] = v;
                }
            }
        }
    }
}

// ---------------------------------------------------------------------------
// Kernel 3: causal silu-attention (HMMA) with precomputed bias.  (R8-proven)
// grid (32 bh, 24 work), block 128.  Work mapping (big-first):
//   wy<16:  it = 15-(wy>>1), split half (wy&1)
//   wy>=16: it = 23-wy (7..0), full range
// ---------------------------------------------------------------------------
#define ATPAD 72
#define ATILE (64*ATPAD*2)           // 9216 B per bf16 tile
#define ATT_QH 0
#define ATT_QL (1*ATILE)
#define ATT_KH (2*ATILE)
#define ATT_KL (3*ATILE)
#define ATT_VH (4*ATILE)
#define ATT_VL (5*ATILE)
#define ATT_PM (6*ATILE)
#define SMEM_ATTN (ATT_PM + 64*4)

__global__ void __launch_bounds__(128)
attn_kernel(const unsigned char* __restrict__ pm) {
    unsigned char* sm = dynsmem;
    int* pmj = (int*)(sm + ATT_PM);

    const int bh = blockIdx.x, b = bh >> 3, h = bh & 7;
    const int wy = blockIdx.y;
    int it, jlo, jhi, dst;
    if (wy < 16) {
        it = 15 - (wy >> 1);
        int m = (it + 2) >> 1;
        if (wy & 1) { jlo = m; jhi = it + 1; dst = 1; }
        else        { jlo = 0; jhi = m;      dst = 0; }
    } else {
        it = 23 - wy; jlo = 0; jhi = it + 1; dst = 0;
    }
    const int i0 = it * 64;
    const int tid = threadIdx.x, wq = tid >> 5, lane = tid & 31;
    const int lrow = lane & 15, lcol = (lane >> 4) * 8;

    const uint32_t sqh = smem_to_u32(sm);
    const uint32_t sql = sqh + (ATT_QL - ATT_QH);
    const uint32_t skh = sqh + (ATT_KH - ATT_QH), skl = sqh + (ATT_KL - ATT_QH);
    const uint32_t svh = sqh + (ATT_VH - ATT_QH), svl = sqh + (ATT_VL - ATT_QH);

    // Q tiles (cols 1024 + h*64) via cp.async
    #pragma unroll
    for (int i = 0; i < 4; i++) {
        int id = i*128 + tid, row = id >> 3, col = (id & 7) * 8;
        size_t src = (size_t)(b*NSEQ + i0 + row)*EOUT + 1024 + h*64 + col;
        cp16(sqh + (row*ATPAD + col)*2, &g_uoh[src]);
        cp16(sql + (row*ATPAD + col)*2, &g_uol[src]);
    }
    CP_COMMIT(); CP_WAIT(0);
    __syncthreads();

    float of[8][4];
    #pragma unroll
    for (int f = 0; f < 8; f++)
        #pragma unroll
        for (int r = 0; r < 4; r++) of[f][r] = 0.0f;

    const int row_lo = wq*16 + (lane >> 2);
    const int col_in = (lane & 3) * 2;

    for (int jt = jlo; jt < jhi; jt++) {
        const int j0 = jt * 64;
        __syncthreads();   // protect K/V from previous iteration's phase B
        #pragma unroll
        for (int i = 0; i < 4; i++) {
            int id = i*128 + tid, row = id >> 3, col = (id & 7) * 8;
            size_t bkv = (size_t)(b*NSEQ + j0 + row)*EOUT + h*64 + col;
            cp16(skh + (row*ATPAD + col)*2, &g_uoh[bkv + 1536]);
            cp16(skl + (row*ATPAD + col)*2, &g_uol[bkv + 1536]);
            cp16(svh + (row*ATPAD + col)*2, &g_uoh[bkv + 512]);
            cp16(svl + (row*ATPAD + col)*2, &g_uol[bkv + 512]);
        }
        if (tid < 64) pmj[tid] = pm[b*NSEQ + j0 + tid];
        CP_COMMIT(); CP_WAIT(0);
        __syncthreads();

        // ---- Phase A: S = Q K^T (3-term split) ----
        float sc[8][4];
        #pragma unroll
        for (int f = 0; f < 8; f++)
            #pragma unroll
            for (int r = 0; r < 4; r++) sc[f][r] = 0.0f;

        #pragma unroll
        for (int ks = 0; ks < 4; ks++) {
            uint32_t ah[4], al[4], kh[4][4], kl[4][4];
            ldsm4(ah, sqh + ((wq*16 + lrow)*ATPAD + ks*16 + lcol)*2);
            ldsm4(al, sql + ((wq*16 + lrow)*ATPAD + ks*16 + lcol)*2);
            #pragma unroll
            for (int g = 0; g < 4; g++) {
                ldsm4(kh[g], skh + ((g*16 + lrow)*ATPAD + ks*16 + lcol)*2);
                ldsm4(kl[g], skl + ((g*16 + lrow)*ATPAD + ks*16 + lcol)*2);
            }
            #pragma unroll
            for (int fn = 0; fn < 8; fn++) {
                uint32_t bh_[2] = { kh[fn >> 1][(fn & 1) + 0], kh[fn >> 1][(fn & 1) + 2] };
                uint32_t bl_[2] = { kl[fn >> 1][(fn & 1) + 0], kl[fn >> 1][(fn & 1) + 2] };
                mma16816(sc[fn], ah, bh_);
                mma16816(sc[fn], al, bh_);
                mma16816(sc[fn], ah, bl_);
            }
        }

        // ---- Epilogue: +bias (precomputed), silu/N, mask ----
        #pragma unroll
        for (int f = 0; f < 8; f++) {
            int jb = j0 + f*8 + col_in;
            float2 b0 = *(const float2*)&g_bias[((size_t)(b << 10) + i0 + row_lo)     * NSEQ + jb];
            float2 b1 = *(const float2*)&g_bias[((size_t)(b << 10) + i0 + row_lo + 8) * NSEQ + jb];
            #pragma unroll
            for (int r = 0; r < 4; r++) {
                int il = row_lo + ((r >> 1) ? 8 : 0);
                int jl = f*8 + col_in + (r & 1);
                int ig = i0 + il, jg = j0 + jl;
                float bb = (r < 2) ? ((r & 1) ? b0.y : b0.x) : ((r & 1) ? b1.y : b1.x);
                float s = sc[f][r] + bb;
                s = s / (1.0f + __expf(-s)) * (1.0f / NSEQ);
                if (jg > ig || pmj[jl]) s = 0.0f;
                sc[f][r] = s;
            }
        }

        // ---- Phase B: O += S @ V (3-term split; S packed from C-frags) ----
        #pragma unroll
        for (int ks = 0; ks < 4; ks++) {
            uint32_t ah[4], al[4];
            ah[0] = pack_hi(sc[2*ks][0],   sc[2*ks][1]);
            ah[1] = pack_hi(sc[2*ks][2],   sc[2*ks][3]);
            ah[2] = pack_hi(sc[2*ks+1][0], sc[2*ks+1][1]);
            ah[3] = pack_hi(sc[2*ks+1][2], sc[2*ks+1][3]);
            al[0] = pack_lo(sc[2*ks][0],   sc[2*ks][1],   ah[0]);
            al[1] = pack_lo(sc[2*ks][2],   sc[2*ks][3],   ah[1]);
            al[2] = pack_lo(sc[2*ks+1][0], sc[2*ks+1][1], ah[2]);
            al[3] = pack_lo(sc[2*ks+1][2], sc[2*ks+1][3], ah[3]);
            uint32_t voff = ((ks*16 + ((lane >> 3) & 1)*8 + (lane & 7))*ATPAD
                            + (lane >> 4)*8) * 2;
            #pragma unroll
            for (int dg = 0; dg < 4; dg++) {
                uint32_t vh[4], vl[4];
                ldsm4t(vh, svh + voff + dg*16*2);
                ldsm4t(vl, svl + voff + dg*16*2);
                #pragma unroll
                for (int half = 0; half < 2; half++) {
                    int fd = dg*2 + half;
                    uint32_t bh_[2] = { vh[half*2], vh[half*2 + 1] };
                    uint32_t bl_[2] = { vl[half*2], vl[half*2 + 1] };
                    mma16816(of[fd], ah, bh_);
                    mma16816(of[fd], al, bh_);
                    mma16816(of[fd], ah, bl_);
                }
            }
        }
    }

    // ---- write O partial ----
    float* aop = dst ? g_ao1 : g_ao0;
    #pragma unroll
    for (int fd = 0; fd < 8; fd++) {
        #pragma unroll
        for (int half = 0; half < 2; half++) {
            int row = i0 + row_lo + half*8;
            int col = h*64 + fd*8 + col_in;
            float2 v = { of[fd][half*2], of[fd][half*2 + 1] };
            *(float2*)&aop[(size_t)(b*NSEQ + row)*DMODEL + col] = v;
        }
    }
}

// ---------------------------------------------------------------------------
// Launch
// ---------------------------------------------------------------------------
extern "C" void kernel_launch(void* const* d_in, const int* in_sizes, int n_in,
                              void* d_out, int out_size) {
    const float*          x      = (const float*)d_in[0];
    const int*            ts     = (const int*)d_in[1];     // int32 (JAX x64 off)
    /* d_in[2] = cm — analytic triu(k=1), unused */
    const unsigned char*  pm     = (const unsigned char*)d_in[3];
    const float*          uvqk   = (const float*)d_in[4];
    const float*          o_w    = (const float*)d_in[5];
    const float*          o_b    = (const float*)d_in[6];
    const float*          ln_x_w = (const float*)d_in[7];
    const float*          ln_x_b = (const float*)d_in[8];
    const float*          ln_a_w = (const float*)d_in[9];
    const float*          ln_a_b = (const float*)d_in[10];
    const float*          ts_w   = (const float*)d_in[11];
    const float*          pos_w  = (const float*)d_in[12];
    float*                out    = (float*)d_out;

    __nv_bfloat16 *p_uoh, *p_uol, *p_nxh, *p_nxl, *p_th, *p_tl;
    __nv_bfloat16 *p_B1h, *p_B1l, *p_B2h, *p_B2l;
    cudaGetSymbolAddress((void**)&p_uoh, g_uoh);
    cudaGetSymbolAddress((void**)&p_uol, g_uol);
    cudaGetSymbolAddress((void**)&p_nxh, g_nxh);
    cudaGetSymbolAddress((void**)&p_nxl, g_nxl);
    cudaGetSymbolAddress((void**)&p_th,  g_th);
    cudaGetSymbolAddress((void**)&p_tl,  g_tl);
    cudaGetSymbolAddress((void**)&p_B1h, g_B1h);
    cudaGetSymbolAddress((void**)&p_B1l, g_B1l);
    cudaGetSymbolAddress((void**)&p_B2h, g_B2h);
    cudaGetSymbolAddress((void**)&p_B2l, g_B2l);

    cudaFuncSetAttribute(mma_gemm<0>, cudaFuncAttributeMaxDynamicSharedMemorySize, SMEM_GEMM);
    cudaFuncSetAttribute(mma_gemm<1>, cudaFuncAttributeMaxDynamicSharedMemorySize, SMEM_GEMM);
    cudaFuncSetAttribute(attn_kernel, cudaFuncAttributeMaxDynamicSharedMemorySize, SMEM_ATTN);

    // 0. weight transpose+split, bias precompute
    tsplit_kernel<<<dim3(EOUT/32, DMODEL/32), dim3(32, 8)>>>(uvqk, p_B1h, p_B1l, DMODEL, EOUT);
    tsplit_kernel<<<dim3(DMODEL/32, DMODEL/32), dim3(32, 8)>>>(o_w, p_B2h, p_B2l, DMODEL, DMODEL);
    bias_kernel<<<NB*NSEQ, 256>>>(ts, ts_w, pos_w);

    // 1. LN(x) -> bf16 hi/lo
    ln_x_kernel<<<ROWS, 256>>>(x, ln_x_w, ln_x_b);

    // 2. uvqk GEMM + silu -> hi/lo bf16  (fused 3-term)
    mma_gemm<0><<<dim3(EOUT/128, ROWS/128), 256, SMEM_GEMM>>>(
        p_nxh, p_nxl, p_B1h, p_B1l,
        nullptr, p_uoh, p_uol, EOUT, nullptr, nullptr, nullptr);

    // 3. attention (HMMA, split long query tiles)
    attn_kernel<<<dim3(NB*NH, 24), 128, SMEM_ATTN>>>(pm);

    // 4. t = u * LN(ao)
    ln_a_kernel<<<ROWS, 256>>>(ln_a_w, ln_a_b);

    // 5. y = t @ o_w + o_b + x (pm-masked)  (fused 3-term)
    mma_gemm<1><<<dim3(DMODEL/128, ROWS/128), 256, SMEM_GEMM>>>(
        p_th, p_tl, p_B2h, p_B2l,
        out, nullptr, nullptr, DMODEL, o_b, x, pm);
}

// round 12
// speedup vs baseline: 1.2200x; 1.0185x over previous
#include <cuda_runtime.h>
#include <cuda_bf16.h>
#include <cstdint>
#include <math.h>

// Problem constants
#define NB     4
#define NSEQ   1024
#define DMODEL 512
#define NH     8
#define HD     64
#define EOUT   2048          // 2*H*Dv + 2*H*Dq
#define ROWS   (NB*NSEQ)     // 4096

// Single dynamic-smem symbol (typed via casts in each kernel)
extern __shared__ __align__(128) unsigned char dynsmem[];

// ---------------------------------------------------------------------------
// Scratch (allocation-free -> __device__ globals)
// ---------------------------------------------------------------------------
__device__ float g_ao0[ROWS*DMODEL];  // attention output (split 0)
__device__ float g_ao1[ROWS*DMODEL];  // attention output (split 1, rows i>=512)
__device__ float g_bias[(size_t)NB*NSEQ*NSEQ];                    // rel-bias, head-invariant
__device__ __nv_bfloat16 g_uoh[ROWS*EOUT], g_uol[ROWS*EOUT];      // silu(nx@uvqk) hi/lo
__device__ __nv_bfloat16 g_nxh[ROWS*DMODEL], g_nxl[ROWS*DMODEL];  // LN(x) hi/lo
__device__ __nv_bfloat16 g_th [ROWS*DMODEL], g_tl [ROWS*DMODEL];  // u*LN(ao) hi/lo
__device__ __nv_bfloat16 g_B1h[EOUT*DMODEL], g_B1l[EOUT*DMODEL];  // uvqk^T  [2048][512]
__device__ __nv_bfloat16 g_B2h[DMODEL*DMODEL], g_B2l[DMODEL*DMODEL]; // o_w^T [512][512]

// ---------------------------------------------------------------------------
// mma.sync helpers (sm_80-era PTX, legal on compute_103)
// ---------------------------------------------------------------------------
__device__ __forceinline__ uint32_t smem_to_u32(const void* p) {
    uint32_t a;
    asm("{ .reg .u64 t; cvta.to.shared.u64 t, %1; cvt.u32.u64 %0, t; }" : "=r"(a) : "l"(p));
    return a;
}
__device__ __forceinline__ void ldsm4(uint32_t* r, uint32_t addr) {
    asm volatile("ldmatrix.sync.aligned.m8n8.x4.shared.b16 {%0,%1,%2,%3}, [%4];"
        : "=r"(r[0]), "=r"(r[1]), "=r"(r[2]), "=r"(r[3]) : "r"(addr));
}
__device__ __forceinline__ void ldsm4t(uint32_t* r, uint32_t addr) {
    asm volatile("ldmatrix.sync.aligned.m8n8.x4.trans.shared.b16 {%0,%1,%2,%3}, [%4];"
        : "=r"(r[0]), "=r"(r[1]), "=r"(r[2]), "=r"(r[3]) : "r"(addr));
}
__device__ __forceinline__ void mma16816(float* c, const uint32_t* a, const uint32_t* b) {
    asm volatile("mma.sync.aligned.m16n8k16.row.col.f32.bf16.bf16.f32 "
        "{%0,%1,%2,%3}, {%4,%5,%6,%7}, {%8,%9}, {%0,%1,%2,%3};"
        : "+f"(c[0]), "+f"(c[1]), "+f"(c[2]), "+f"(c[3])
        : "r"(a[0]), "r"(a[1]), "r"(a[2]), "r"(a[3]), "r"(b[0]), "r"(b[1]));
}
__device__ __forceinline__ void cp16(uint32_t s, const void* g) {
    asm volatile("cp.async.cg.shared.global [%0], [%1], 16;" :: "r"(s), "l"(g));
}
#define CP_COMMIT() asm volatile("cp.async.commit_group;")
#define CP_WAIT(N)  asm volatile("cp.async.wait_group %0;" :: "n"(N))

__device__ __forceinline__ uint32_t pack_hi(float a, float b) {
    __nv_bfloat162 t = __floats2bfloat162_rn(a, b);
    return *(uint32_t*)&t;
}
__device__ __forceinline__ uint32_t pack_lo(float a, float b, uint32_t hi) {
    __nv_bfloat162 h = *(__nv_bfloat162*)&hi;
    __nv_bfloat162 t = __floats2bfloat162_rn(a - __bfloat162float(h.x),
                                             b - __bfloat162float(h.y));
    return *(uint32_t*)&t;
}

// ---------------------------------------------------------------------------
// Block reduction (256 threads)
// ---------------------------------------------------------------------------
__device__ __forceinline__ float blk_reduce_sum(float v, float* sm) {
    int tid = threadIdx.x;
    #pragma unroll
    for (int o = 16; o > 0; o >>= 1) v += __shfl_down_sync(0xffffffffu, v, o);
    if ((tid & 31) == 0) sm[tid >> 5] = v;
    __syncthreads();
    if (tid < 32) {
        float t = (tid < 8) ? sm[tid] : 0.0f;
        #pragma unroll
        for (int o = 4; o > 0; o >>= 1) t += __shfl_down_sync(0xffffffffu, t, o);
        if (tid == 0) sm[0] = t;
    }
    __syncthreads();
    float r = sm[0];
    __syncthreads();
    return r;
}

__device__ __forceinline__ void split_write(__nv_bfloat16* ph, __nv_bfloat16* pl,
                                            size_t idx, float v) {
    __nv_bfloat16 h = __float2bfloat16(v);
    ph[idx] = h;
    pl[idx] = __float2bfloat16(v - __bfloat162float(h));
}

// ---------------------------------------------------------------------------
// MEGA prep kernel: 4 independent tasks dispatched by block range.
//   [0, 4096)        : ln_x  (row = bid)
//   [4096, 8192)     : bias  (bi = bid-4096)
//   [8192, 9216)     : tsplit uvqk  (64 x 16 tiles)
//   [9216, 9472)     : tsplit o_w   (16 x 16 tiles)
// block = 256 threads.
// ---------------------------------------------------------------------------
__device__ __forceinline__ void tsplit_body(const float* __restrict__ in,
                                            __nv_bfloat16* __restrict__ oh,
                                            __nv_bfloat16* __restrict__ ol,
                                            int K, int N, int bx, int by,
                                            float (*tile)[33]) {
    int tid = threadIdx.x;
    int tx = tid & 31, ty = tid >> 5;
    int n0 = bx * 32, k0 = by * 32;
    #pragma unroll
    for (int i = 0; i < 4; i++)
        tile[ty + i*8][tx] = in[(size_t)(k0 + ty + i*8) * N + n0 + tx];
    __syncthreads();
    #pragma unroll
    for (int i = 0; i < 4; i++) {
        float v = tile[tx][ty + i*8];
        __nv_bfloat16 h = __float2bfloat16(v);
        size_t o = (size_t)(n0 + ty + i*8) * K + k0 + tx;
        oh[o] = h;
        ol[o] = __float2bfloat16(v - __bfloat162float(h));
    }
}

__global__ void prep_kernel(const float* __restrict__ x,
                            const float* __restrict__ lnw,
                            const float* __restrict__ lnb,
                            const float* __restrict__ uvqk,
                            const float* __restrict__ o_w,
                            const int*   __restrict__ ts,
                            const float* __restrict__ tw,
                            const float* __restrict__ pw) {
    __shared__ float sm[8];
    __shared__ float tile[32][33];
    int bid = blockIdx.x, tid = threadIdx.x;

    if (bid < 4096) {
        // ---- ln_x ----
        int r = bid;
        const float* xr = x + (size_t)r * DMODEL;
        float v0 = xr[tid], v1 = xr[tid + 256];
        float mean = blk_reduce_sum(v0 + v1, sm) * (1.0f / DMODEL);
        float d0 = v0 - mean, d1 = v1 - mean;
        float var = blk_reduce_sum(d0*d0 + d1*d1, sm) * (1.0f / DMODEL);
        float inv = rsqrtf(var + 1e-5f);
        split_write(g_nxh, g_nxl, (size_t)r*DMODEL + tid,       d0*inv*lnw[tid]       + lnb[tid]);
        split_write(g_nxh, g_nxl, (size_t)r*DMODEL + tid + 256, d1*inv*lnw[tid + 256] + lnb[tid + 256]);
    } else if (bid < 8192) {
        // ---- bias precompute ----
        int bi = bid - 4096, b = bi >> 10, i = bi & 1023;
        int j = tid * 4;
        int ip = i + 1; if (ip > NSEQ - 1) ip = NSEQ - 1;
        int tl = ts[(b << 10) + ip];
        int4 tj = *(const int4*)&ts[(b << 10) + j];
        float4 o;
        {
            int d = tl - tj.x; if (d < 0) d = -d; if (d < 1) d = 1;
            int bk = (int)(__logf((float)d) * 3.3222591f);
            bk = min(max(bk, 0), 64);
            o.x = pw[j - i + NSEQ - 1] + tw[bk];
        }
        {
            int d = tl - tj.y; if (d < 0) d = -d; if (d < 1) d = 1;
            int bk = (int)(__logf((float)d) * 3.3222591f);
            bk = min(max(bk, 0), 64);
            o.y = pw[j + 1 - i + NSEQ - 1] + tw[bk];
        }
        {
            int d = tl - tj.z; if (d < 0) d = -d; if (d < 1) d = 1;
            int bk = (int)(__logf((float)d) * 3.3222591f);
            bk = min(max(bk, 0), 64);
            o.z = pw[j + 2 - i + NSEQ - 1] + tw[bk];
        }
        {
            int d = tl - tj.w; if (d < 0) d = -d; if (d < 1) d = 1;
            int bk = (int)(__logf((float)d) * 3.3222591f);
            bk = min(max(bk, 0), 64);
            o.w = pw[j + 3 - i + NSEQ - 1] + tw[bk];
        }
        *(float4*)&g_bias[((size_t)(b << 10) + i) * NSEQ + j] = o;
    } else if (bid < 8192 + 1024) {
        // ---- tsplit uvqk [512][2048] -> [2048][512] ----
        int t = bid - 8192;
        tsplit_body(uvqk, g_B1h, g_B1l, DMODEL, EOUT, t & 63, t >> 6, tile);
    } else {
        // ---- tsplit o_w [512][512] -> [512][512] ----
        int t = bid - 9216;
        tsplit_body(o_w, g_B2h, g_B2l, DMODEL, DMODEL, t & 15, t >> 4, tile);
    }
}

// ---------------------------------------------------------------------------
// Kernel 4: t = u * LayerNorm(ao0 [+ ao1])  -> g_th/g_tl   grid=4096, block=256
// ---------------------------------------------------------------------------
__global__ void ln_a_kernel(const float* __restrict__ w,
                            const float* __restrict__ b) {
    __shared__ float sm[8];
    int r = blockIdx.x, tid = threadIdx.x;
    const bool two = (r & 1023) >= 512;
    size_t base = (size_t)r * DMODEL;
    float v0 = g_ao0[base + tid], v1 = g_ao0[base + tid + 256];
    if (two) { v0 += g_ao1[base + tid]; v1 += g_ao1[base + tid + 256]; }
    float mean = blk_reduce_sum(v0 + v1, sm) * (1.0f / DMODEL);
    float d0 = v0 - mean, d1 = v1 - mean;
    float var = blk_reduce_sum(d0*d0 + d1*d1, sm) * (1.0f / DMODEL);
    float inv = rsqrtf(var + 1e-5f);
    size_t ub = (size_t)r * EOUT;
    float u0 = __bfloat162float(g_uoh[ub + tid])       + __bfloat162float(g_uol[ub + tid]);
    float u1 = __bfloat162float(g_uoh[ub + tid + 256]) + __bfloat162float(g_uol[ub + tid + 256]);
    split_write(g_th, g_tl, base + tid,       (d0*inv*w[tid]       + b[tid])       * u0);
    split_write(g_th, g_tl, base + tid + 256, (d1*inv*w[tid + 256] + b[tid + 256]) * u1);
}

// ---------------------------------------------------------------------------
// Fused 3-term bf16-split GEMM (HMMA): C = Ah@Bh^T + Al@Bh^T + Ah@Bl^T.
// CTA 128x128, 8 warps (2m x 4n, 64x32 warp tile), K chunks of 32,
// 2-stage cp.async pipeline, 2 CTAs/SM.   (R11-proven)
// ---------------------------------------------------------------------------
#define KSEG   512
#define KCH    32
#define NCH    (KSEG/KCH)            // 16
#define TPAD   40                    // 32 + 8 elems -> 80B row stride
#define TBYTES (128*TPAD*2)          // 10240 B per tile
#define STAGE4 (4*TBYTES)            // Ah,Al,Bh,Bl per stage
#define SMEM_GEMM (2*STAGE4)         // 81920 B

template<int EPI>
__global__ void __launch_bounds__(256, 2)
mma_gemm(const __nv_bfloat16* __restrict__ Ah, const __nv_bfloat16* __restrict__ Al,
         const __nv_bfloat16* __restrict__ Bh, const __nv_bfloat16* __restrict__ Bl,
         float* __restrict__ C,
         __nv_bfloat16* __restrict__ Ch, __nv_bfloat16* __restrict__ Cl, int N,
         const float* __restrict__ bias, const float* __restrict__ resid,
         const unsigned char* __restrict__ pm) {
    const int tid = threadIdx.x, wid = tid >> 5, lane = tid & 31;
    const int bm = blockIdx.y * 128, bn = blockIdx.x * 128;
    const int wm = wid & 1, wn = wid >> 1;     // warp tile (wm*64, wn*32)

    const uint32_t sbase = smem_to_u32(dynsmem);
    const int lrow = lane & 15, lcol = (lane >> 4) * 8;
    const int crow = tid >> 2, ccol = (tid & 3) * 8;

    float acc[4][4][4];
    #pragma unroll
    for (int i = 0; i < 4; i++)
        #pragma unroll
        for (int j = 0; j < 4; j++)
            #pragma unroll
            for (int k = 0; k < 4; k++) acc[i][j][k] = 0.0f;

    auto issue = [&](int c, int stg) {
        const int kc = c * KCH;
        const uint32_t st = sbase + stg * STAGE4;
        #pragma unroll
        for (int i = 0; i < 2; i++) {
            int row = crow + i*64;
            uint32_t so = (row*TPAD + ccol)*2;
            cp16(st + 0*TBYTES + so, Ah + (size_t)(bm + row)*KSEG + kc + ccol);
            cp16(st + 1*TBYTES + so, Al + (size_t)(bm + row)*KSEG + kc + ccol);
            cp16(st + 2*TBYTES + so, Bh + (size_t)(bn + row)*KSEG + kc + ccol);
            cp16(st + 3*TBYTES + so, Bl + (size_t)(bn + row)*KSEG + kc + ccol);
        }
        CP_COMMIT();
    };

    issue(0, 0);
    for (int c = 0; c < NCH; c++) {
        if (c + 1 < NCH) { issue(c + 1, (c + 1) & 1); CP_WAIT(1); }
        else             { CP_WAIT(0); }
        __syncthreads();
        const uint32_t st = sbase + (c & 1) * STAGE4;
        const uint32_t sah = st, sal = st + TBYTES;
        const uint32_t sbh = st + 2*TBYTES, sbl = st + 3*TBYTES;
        #pragma unroll
        for (int ks = 0; ks < 2; ks++) {
            const int ko = ks * 16;
            uint32_t afh[4][4], afl[4][4], bfh[2][4], bfl[2][4];
            #pragma unroll
            for (int fm = 0; fm < 4; fm++)
                ldsm4(afh[fm], sah + ((wm*64 + fm*16 + lrow)*TPAD + ko + lcol)*2);
            #pragma unroll
            for (int g = 0; g < 2; g++)
                ldsm4(bfh[g], sbh + ((wn*32 + g*16 + lrow)*TPAD + ko + lcol)*2);
            #pragma unroll
            for (int fm = 0; fm < 4; fm++)
                #pragma unroll
                for (int fn = 0; fn < 4; fn++) {
                    uint32_t bb[2] = { bfh[fn >> 1][(fn & 1) + 0],
                                       bfh[fn >> 1][(fn & 1) + 2] };
                    mma16816(acc[fm][fn], afh[fm], bb);
                }
            #pragma unroll
            for (int fm = 0; fm < 4; fm++)
                ldsm4(afl[fm], sal + ((wm*64 + fm*16 + lrow)*TPAD + ko + lcol)*2);
            #pragma unroll
            for (int fm = 0; fm < 4; fm++)
                #pragma unroll
                for (int fn = 0; fn < 4; fn++) {
                    uint32_t bb[2] = { bfh[fn >> 1][(fn & 1) + 0],
                                       bfh[fn >> 1][(fn & 1) + 2] };
                    mma16816(acc[fm][fn], afl[fm], bb);
                }
            #pragma unroll
            for (int g = 0; g < 2; g++)
                ldsm4(bfl[g], sbl + ((wn*32 + g*16 + lrow)*TPAD + ko + lcol)*2);
            #pragma unroll
            for (int fm = 0; fm < 4; fm++)
                #pragma unroll
                for (int fn = 0; fn < 4; fn++) {
                    uint32_t bb[2] = { bfl[fn >> 1][(fn & 1) + 0],
                                       bfl[fn >> 1][(fn & 1) + 2] };
                    mma16816(acc[fm][fn], afh[fm], bb);
                }
        }
        __syncthreads();
    }

    #pragma unroll
    for (int fm = 0; fm < 4; fm++) {
        #pragma unroll
        for (int half = 0; half < 2; half++) {
            int r = bm + wm*64 + fm*16 + (lane >> 2) + half*8;
            #pragma unroll
            for (int fn = 0; fn < 4; fn++) {
                int cc = bn + wn*32 + fn*8 + (lane & 3)*2;
                float vx = acc[fm][fn][half*2 + 0];
                float vy = acc[fm][fn][half*2 + 1];
                if (EPI == 0) {
                    vx = vx / (1.0f + __expf(-vx));
                    vy = vy / (1.0f + __expf(-vy));
                    uint32_t hi = pack_hi(vx, vy);
                    uint32_t lo = pack_lo(vx, vy, hi);
                    *(uint32_t*)&Ch[(size_t)r*N + cc] = hi;
                    *(uint32_t*)&Cl[(size_t)r*N + cc] = lo;
                } else {
                    vx += bias[cc]     + resid[(size_t)r*N + cc];
                    vy += bias[cc + 1] + resid[(size_t)r*N + cc + 1];
                    if (pm[r]) { vx = 0.0f; vy = 0.0f; }
                    float2 v = {vx, vy};
                    *(float2*)&C[(size_t)r*N + cc] = v;
                }
            }
        }
    }
}

// ---------------------------------------------------------------------------
// Kernel 3: causal silu-attention (HMMA), precomputed bias, pipelined K/V
// loads via split commit groups (smem layout unchanged -> 4 CTAs/SM).
// grid (32 bh, 24 work), block 128.  Work mapping (big-first) as R8.
// Per iter: wait K(jt) -> phaseA -> sync -> issue K(jt+1) -> epilogue ->
//           wait V(jt) -> sync -> phaseB -> sync -> issue V(jt+1)
// ---------------------------------------------------------------------------
#define ATPAD 72
#define ATILE (64*ATPAD*2)           // 9216 B per bf16 tile
#define ATT_QH 0
#define ATT_QL (1*ATILE)
#define ATT_KH (2*ATILE)
#define ATT_KL (3*ATILE)
#define ATT_VH (4*ATILE)
#define ATT_VL (5*ATILE)
#define ATT_PM (6*ATILE)             // pmj[2][64]
#define SMEM_ATTN (ATT_PM + 2*64*4)

__global__ void __launch_bounds__(128)
attn_kernel(const unsigned char* __restrict__ pm) {
    unsigned char* sm = dynsmem;
    int* pmj = (int*)(sm + ATT_PM);

    const int bh = blockIdx.x, b = bh >> 3, h = bh & 7;
    const int wy = blockIdx.y;
    int it, jlo, jhi, dst;
    if (wy < 16) {
        it = 15 - (wy >> 1);
        int m = (it + 2) >> 1;
        if (wy & 1) { jlo = m; jhi = it + 1; dst = 1; }
        else        { jlo = 0; jhi = m;      dst = 0; }
    } else {
        it = 23 - wy; jlo = 0; jhi = it + 1; dst = 0;
    }
    const int i0 = it * 64;
    const int tid = threadIdx.x, wq = tid >> 5, lane = tid & 31;
    const int lrow = lane & 15, lcol = (lane >> 4) * 8;

    const uint32_t sqh = smem_to_u32(sm);
    const uint32_t sql = sqh + ATT_QL;
    const uint32_t skh = sqh + ATT_KH, skl = sqh + ATT_KL;
    const uint32_t svh = sqh + ATT_VH, svl = sqh + ATT_VL;

    auto issue_k = [&](int jt, int slot) {
        const int j0 = jt * 64;
        #pragma unroll
        for (int i = 0; i < 4; i++) {
            int id = i*128 + tid, row = id >> 3, col = (id & 7) * 8;
            size_t bkv = (size_t)(b*NSEQ + j0 + row)*EOUT + h*64 + col;
            uint32_t so = (row*ATPAD + col)*2;
            cp16(skh + so, &g_uoh[bkv + 1536]);
            cp16(skl + so, &g_uol[bkv + 1536]);
        }
        if (tid < 64) pmj[slot*64 + tid] = pm[b*NSEQ + j0 + tid];
        CP_COMMIT();
    };
    auto issue_v = [&](int jt) {
        const int j0 = jt * 64;
        #pragma unroll
        for (int i = 0; i < 4; i++) {
            int id = i*128 + tid, row = id >> 3, col = (id & 7) * 8;
            size_t bkv = (size_t)(b*NSEQ + j0 + row)*EOUT + h*64 + col;
            uint32_t so = (row*ATPAD + col)*2;
            cp16(svh + so, &g_uoh[bkv + 512]);
            cp16(svl + so, &g_uol[bkv + 512]);
        }
        CP_COMMIT();
    };

    // Q tiles (cols 1024 + h*64)
    #pragma unroll
    for (int i = 0; i < 4; i++) {
        int id = i*128 + tid, row = id >> 3, col = (id & 7) * 8;
        size_t src = (size_t)(b*NSEQ + i0 + row)*EOUT + 1024 + h*64 + col;
        cp16(sqh + (row*ATPAD + col)*2, &g_uoh[src]);
        cp16(sql + (row*ATPAD + col)*2, &g_uol[src]);
    }
    CP_COMMIT(); CP_WAIT(0);
    __syncthreads();

    // prologue: K(jlo) then V(jlo) as separate groups
    issue_k(jlo, 0);
    issue_v(jlo);

    float of[8][4];
    #pragma unroll
    for (int f = 0; f < 8; f++)
        #pragma unroll
        for (int r = 0; r < 4; r++) of[f][r] = 0.0f;

    const int row_lo = wq*16 + (lane >> 2);
    const int col_in = (lane & 3) * 2;

    for (int jt = jlo; jt < jhi; jt++) {
        const int j0 = jt * 64;
        const int slot = (jt - jlo) & 1;
        // K(jt) ready (V(jt) may still be in flight)
        CP_WAIT(1);
        __syncthreads();

        // ---- Phase A: S = Q K^T (3-term split) ----
        float sc[8][4];
        #pragma unroll
        for (int f = 0; f < 8; f++)
            #pragma unroll
            for (int r = 0; r < 4; r++) sc[f][r] = 0.0f;

        #pragma unroll
        for (int ks = 0; ks < 4; ks++) {
            uint32_t ah[4], al[4], kh[4][4], kl[4][4];
            ldsm4(ah, sqh + ((wq*16 + lrow)*ATPAD + ks*16 + lcol)*2);
            ldsm4(al, sql + ((wq*16 + lrow)*ATPAD + ks*16 + lcol)*2);
            #pragma unroll
            for (int g = 0; g < 4; g++) {
                ldsm4(kh[g], skh + ((g*16 + lrow)*ATPAD + ks*16 + lcol)*2);
                ldsm4(kl[g], skl + ((g*16 + lrow)*ATPAD + ks*16 + lcol)*2);
            }
            #pragma unroll
            for (int fn = 0; fn < 8; fn++) {
                uint32_t bh_[2] = { kh[fn >> 1][(fn & 1) + 0], kh[fn >> 1][(fn & 1) + 2] };
                uint32_t bl_[2] = { kl[fn >> 1][(fn & 1) + 0], kl[fn >> 1][(fn & 1) + 2] };
                mma16816(sc[fn], ah, bh_);
                mma16816(sc[fn], al, bh_);
                mma16816(sc[fn], ah, bl_);
            }
        }
        __syncthreads();                       // all warps done reading K(jt)
        if (jt + 1 < jhi) issue_k(jt + 1, slot ^ 1);

        // ---- Epilogue: +bias (precomputed), silu/N, mask ----
        const int* pms = pmj + slot*64;
        #pragma unroll
        for (int f = 0; f < 8; f++) {
            int jb = j0 + f*8 + col_in;
            float2 b0 = *(const float2*)&g_bias[((size_t)(b << 10) + i0 + row_lo)     * NSEQ + jb];
            float2 b1 = *(const float2*)&g_bias[((size_t)(b << 10) + i0 + row_lo + 8) * NSEQ + jb];
            #pragma unroll
            for (int r = 0; r < 4; r++) {
                int il = row_lo + ((r >> 1) ? 8 : 0);
                int jl = f*8 + col_in + (r & 1);
                int ig = i0 + il, jg = j0 + jl;
                float bb = (r < 2) ? ((r & 1) ? b0.y : b0.x) : ((r & 1) ? b1.y : b1.x);
                float s = sc[f][r] + bb;
                s = s / (1.0f + __expf(-s)) * (1.0f / NSEQ);
                if (jg > ig || pms[jl]) s = 0.0f;
                sc[f][r] = s;
            }
        }

        // V(jt) ready (K(jt+1) may still be in flight)
        if (jt + 1 < jhi) { CP_WAIT(1); } else { CP_WAIT(0); }
        __syncthreads();

        // ---- Phase B: O += S @ V (3-term split; S packed from C-frags) ----
        #pragma unroll
        for (int ks = 0; ks < 4; ks++) {
            uint32_t ah[4], al[4];
            ah[0] = pack_hi(sc[2*ks][0],   sc[2*ks][1]);
            ah[1] = pack_hi(sc[2*ks][2],   sc[2*ks][3]);
            ah[2] = pack_hi(sc[2*ks+1][0], sc[2*ks+1][1]);
            ah[3] = pack_hi(sc[2*ks+1][2], sc[2*ks+1][3]);
            al[0] = pack_lo(sc[2*ks][0],   sc[2*ks][1],   ah[0]);
            al[1] = pack_lo(sc[2*ks][2],   sc[2*ks][3],   ah[1]);
            al[2] = pack_lo(sc[2*ks+1][0], sc[2*ks+1][1], ah[2]);
            al[3] = pack_lo(sc[2*ks+1][2], sc[2*ks+1][3], ah[3]);
            uint32_t voff = ((ks*16 + ((lane >> 3) & 1)*8 + (lane & 7))*ATPAD
                            + (lane >> 4)*8) * 2;
            #pragma unroll
            for (int dg = 0; dg < 4; dg++) {
                uint32_t vh[4], vl[4];
                ldsm4t(vh, svh + voff + dg*16*2);
                ldsm4t(vl, svl + voff + dg*16*2);
                #pragma unroll
                for (int half = 0; half < 2; half++) {
                    int fd = dg*2 + half;
                    uint32_t bh_[2] = { vh[half*2], vh[half*2 + 1] };
                    uint32_t bl_[2] = { vl[half*2], vl[half*2 + 1] };
                    mma16816(of[fd], ah, bh_);
                    mma16816(of[fd], al, bh_);
                    mma16816(of[fd], ah, bl_);
                }
            }
        }
        __syncthreads();                       // all warps done reading V(jt)
        if (jt + 1 < jhi) issue_v(jt + 1);
    }

    // ---- write O partial ----
    float* aop = dst ? g_ao1 : g_ao0;
    #pragma unroll
    for (int fd = 0; fd < 8; fd++) {
        #pragma unroll
        for (int half = 0; half < 2; half++) {
            int row = i0 + row_lo + half*8;
            int col = h*64 + fd*8 + col_in;
            float2 v = { of[fd][half*2], of[fd][half*2 + 1] };
            *(float2*)&aop[(size_t)(b*NSEQ + row)*DMODEL + col] = v;
        }
    }
}

// ---------------------------------------------------------------------------
// Launch
// ---------------------------------------------------------------------------
extern "C" void kernel_launch(void* const* d_in, const int* in_sizes, int n_in,
                              void* d_out, int out_size) {
    const float*          x      = (const float*)d_in[0];
    const int*            ts     = (const int*)d_in[1];     // int32 (JAX x64 off)
    /* d_in[2] = cm — analytic triu(k=1), unused */
    const unsigned char*  pm     = (const unsigned char*)d_in[3];
    const float*          uvqk   = (const float*)d_in[4];
    const float*          o_w    = (const float*)d_in[5];
    const float*          o_b    = (const float*)d_in[6];
    const float*          ln_x_w = (const float*)d_in[7];
    const float*          ln_x_b = (const float*)d_in[8];
    const float*          ln_a_w = (const float*)d_in[9];
    const float*          ln_a_b = (const float*)d_in[10];
    const float*          ts_w   = (const float*)d_in[11];
    const float*          pos_w  = (const float*)d_in[12];
    float*                out    = (float*)d_out;

    __nv_bfloat16 *p_uoh, *p_uol, *p_nxh, *p_nxl, *p_th, *p_tl;
    __nv_bfloat16 *p_B1h, *p_B1l, *p_B2h, *p_B2l;
    cudaGetSymbolAddress((void**)&p_uoh, g_uoh);
    cudaGetSymbolAddress((void**)&p_uol, g_uol);
    cudaGetSymbolAddress((void**)&p_nxh, g_nxh);
    cudaGetSymbolAddress((void**)&p_nxl, g_nxl);
    cudaGetSymbolAddress((void**)&p_th,  g_th);
    cudaGetSymbolAddress((void**)&p_tl,  g_tl);
    cudaGetSymbolAddress((void**)&p_B1h, g_B1h);
    cudaGetSymbolAddress((void**)&p_B1l, g_B1l);
    cudaGetSymbolAddress((void**)&p_B2h, g_B2h);
    cudaGetSymbolAddress((void**)&p_B2l, g_B2l);

    cudaFuncSetAttribute(mma_gemm<0>, cudaFuncAttributeMaxDynamicSharedMemorySize, SMEM_GEMM);
    cudaFuncSetAttribute(mma_gemm<1>, cudaFuncAttributeMaxDynamicSharedMemorySize, SMEM_GEMM);
    cudaFuncSetAttribute(attn_kernel, cudaFuncAttributeMaxDynamicSharedMemorySize, SMEM_ATTN);

    // 0. all prep in one launch: ln_x + bias + tsplit(uvqk) + tsplit(o_w)
    prep_kernel<<<9472, 256>>>(x, ln_x_w, ln_x_b, uvqk, o_w, ts, ts_w, pos_w);

    // 1. uvqk GEMM + silu -> hi/lo bf16  (fused 3-term)
    mma_gemm<0><<<dim3(EOUT/128, ROWS/128), 256, SMEM_GEMM>>>(
        p_nxh, p_nxl, p_B1h, p_B1l,
        nullptr, p_uoh, p_uol, EOUT, nullptr, nullptr, nullptr);

    // 2. attention (HMMA, split long query tiles, pipelined K/V)
    attn_kernel<<<dim3(NB*NH, 24), 128, SMEM_ATTN>>>(pm);

    // 3. t = u * LN(ao)
    ln_a_kernel<<<ROWS, 256>>>(ln_a_w, ln_a_b);

    // 4. y = t @ o_w + o_b + x (pm-masked)  (fused 3-term)
    mma_gemm<1><<<dim3(DMODEL/128, ROWS/128), 256, SMEM_GEMM>>>(
        p_th, p_tl, p_B2h, p_B2l,
        out, nullptr, nullptr, DMODEL, o_b, x, pm);
}

// round 13
// speedup vs baseline: 1.2652x; 1.0371x over previous
#include <cuda_runtime.h>
#include <cuda_bf16.h>
#include <cstdint>
#include <math.h>

// Problem constants
#define NB     4
#define NSEQ   1024
#define DMODEL 512
#define NH     8
#define HD     64
#define EOUT   2048          // 2*H*Dv + 2*H*Dq
#define ROWS   (NB*NSEQ)     // 4096

// Single dynamic-smem symbol (typed via casts in each kernel)
extern __shared__ __align__(128) unsigned char dynsmem[];

// ---------------------------------------------------------------------------
// Scratch (allocation-free -> __device__ globals)
// ---------------------------------------------------------------------------
__device__ float g_ao0[ROWS*DMODEL];  // attention output (split 0)
__device__ float g_ao1[ROWS*DMODEL];  // attention output (split 1, rows i>=512)
__device__ float g_bias[(size_t)NB*NSEQ*NSEQ];                    // rel-bias, head-invariant
__device__ __nv_bfloat16 g_uoh[ROWS*EOUT], g_uol[ROWS*EOUT];      // silu(nx@uvqk) hi/lo
__device__ __nv_bfloat16 g_nxh[ROWS*DMODEL], g_nxl[ROWS*DMODEL];  // LN(x) hi/lo
__device__ __nv_bfloat16 g_th [ROWS*DMODEL], g_tl [ROWS*DMODEL];  // u*LN(ao) hi/lo
__device__ __nv_bfloat16 g_B1h[EOUT*DMODEL], g_B1l[EOUT*DMODEL];  // uvqk^T  [2048][512]
__device__ __nv_bfloat16 g_B2h[DMODEL*DMODEL], g_B2l[DMODEL*DMODEL]; // o_w^T [512][512]

// ---------------------------------------------------------------------------
// mma.sync helpers (sm_80-era PTX, legal on compute_103)
// ---------------------------------------------------------------------------
__device__ __forceinline__ uint32_t smem_to_u32(const void* p) {
    uint32_t a;
    asm("{ .reg .u64 t; cvta.to.shared.u64 t, %1; cvt.u32.u64 %0, t; }" : "=r"(a) : "l"(p));
    return a;
}
__device__ __forceinline__ void ldsm4(uint32_t* r, uint32_t addr) {
    asm volatile("ldmatrix.sync.aligned.m8n8.x4.shared.b16 {%0,%1,%2,%3}, [%4];"
        : "=r"(r[0]), "=r"(r[1]), "=r"(r[2]), "=r"(r[3]) : "r"(addr));
}
__device__ __forceinline__ void ldsm4t(uint32_t* r, uint32_t addr) {
    asm volatile("ldmatrix.sync.aligned.m8n8.x4.trans.shared.b16 {%0,%1,%2,%3}, [%4];"
        : "=r"(r[0]), "=r"(r[1]), "=r"(r[2]), "=r"(r[3]) : "r"(addr));
}
__device__ __forceinline__ void mma16816(float* c, const uint32_t* a, const uint32_t* b) {
    asm volatile("mma.sync.aligned.m16n8k16.row.col.f32.bf16.bf16.f32 "
        "{%0,%1,%2,%3}, {%4,%5,%6,%7}, {%8,%9}, {%0,%1,%2,%3};"
        : "+f"(c[0]), "+f"(c[1]), "+f"(c[2]), "+f"(c[3])
        : "r"(a[0]), "r"(a[1]), "r"(a[2]), "r"(a[3]), "r"(b[0]), "r"(b[1]));
}
__device__ __forceinline__ void cp16(uint32_t s, const void* g) {
    asm volatile("cp.async.cg.shared.global [%0], [%1], 16;" :: "r"(s), "l"(g));
}
#define CP_COMMIT() asm volatile("cp.async.commit_group;")
#define CP_WAIT(N)  asm volatile("cp.async.wait_group %0;" :: "n"(N))

__device__ __forceinline__ uint32_t pack_hi(float a, float b) {
    __nv_bfloat162 t = __floats2bfloat162_rn(a, b);
    return *(uint32_t*)&t;
}
__device__ __forceinline__ uint32_t pack_lo(float a, float b, uint32_t hi) {
    __nv_bfloat162 h = *(__nv_bfloat162*)&hi;
    __nv_bfloat162 t = __floats2bfloat162_rn(a - __bfloat162float(h.x),
                                             b - __bfloat162float(h.y));
    return *(uint32_t*)&t;
}

// ---------------------------------------------------------------------------
// Block reduction (256 threads)
// ---------------------------------------------------------------------------
__device__ __forceinline__ float blk_reduce_sum(float v, float* sm) {
    int tid = threadIdx.x;
    #pragma unroll
    for (int o = 16; o > 0; o >>= 1) v += __shfl_down_sync(0xffffffffu, v, o);
    if ((tid & 31) == 0) sm[tid >> 5] = v;
    __syncthreads();
    if (tid < 32) {
        float t = (tid < 8) ? sm[tid] : 0.0f;
        #pragma unroll
        for (int o = 4; o > 0; o >>= 1) t += __shfl_down_sync(0xffffffffu, t, o);
        if (tid == 0) sm[0] = t;
    }
    __syncthreads();
    float r = sm[0];
    __syncthreads();
    return r;
}

__device__ __forceinline__ void split_write(__nv_bfloat16* ph, __nv_bfloat16* pl,
                                            size_t idx, float v) {
    __nv_bfloat16 h = __float2bfloat16(v);
    ph[idx] = h;
    pl[idx] = __float2bfloat16(v - __bfloat162float(h));
}

// ---------------------------------------------------------------------------
// tsplit body (transpose + bf16 split): in[K][N] fp32 -> oh/ol[N][K]
// ---------------------------------------------------------------------------
__device__ __forceinline__ void tsplit_body(const float* __restrict__ in,
                                            __nv_bfloat16* __restrict__ oh,
                                            __nv_bfloat16* __restrict__ ol,
                                            int K, int N, int bx, int by,
                                            float (*tile)[33]) {
    int tid = threadIdx.x;
    int tx = tid & 31, ty = tid >> 5;
    int n0 = bx * 32, k0 = by * 32;
    #pragma unroll
    for (int i = 0; i < 4; i++)
        tile[ty + i*8][tx] = in[(size_t)(k0 + ty + i*8) * N + n0 + tx];
    __syncthreads();
    #pragma unroll
    for (int i = 0; i < 4; i++) {
        float v = tile[tx][ty + i*8];
        __nv_bfloat16 h = __float2bfloat16(v);
        size_t o = (size_t)(n0 + ty + i*8) * K + k0 + tx;
        oh[o] = h;
        ol[o] = __float2bfloat16(v - __bfloat162float(h));
    }
}

// ---------------------------------------------------------------------------
// prep_core (stream 0, feeds gemm_vqk/gemm_u):
//   [0, 4096)     : ln_x   (row = bid)
//   [4096, 5120)  : tsplit uvqk (64 x 16 tiles)
// ---------------------------------------------------------------------------
__global__ void prep_core_kernel(const float* __restrict__ x,
                                 const float* __restrict__ lnw,
                                 const float* __restrict__ lnb,
                                 const float* __restrict__ uvqk) {
    __shared__ float sm[8];
    __shared__ float tile[32][33];
    int bid = blockIdx.x, tid = threadIdx.x;
    if (bid < 4096) {
        int r = bid;
        const float* xr = x + (size_t)r * DMODEL;
        float v0 = xr[tid], v1 = xr[tid + 256];
        float mean = blk_reduce_sum(v0 + v1, sm) * (1.0f / DMODEL);
        float d0 = v0 - mean, d1 = v1 - mean;
        float var = blk_reduce_sum(d0*d0 + d1*d1, sm) * (1.0f / DMODEL);
        float inv = rsqrtf(var + 1e-5f);
        split_write(g_nxh, g_nxl, (size_t)r*DMODEL + tid,       d0*inv*lnw[tid]       + lnb[tid]);
        split_write(g_nxh, g_nxl, (size_t)r*DMODEL + tid + 256, d1*inv*lnw[tid + 256] + lnb[tid + 256]);
    } else {
        int t = bid - 4096;
        tsplit_body(uvqk, g_B1h, g_B1l, DMODEL, EOUT, t & 63, t >> 6, tile);
    }
}

// ---------------------------------------------------------------------------
// prep_aux (stream B, feeds attention / gemm1):
//   [0, 4096)     : bias precompute
//   [4096, 4352)  : tsplit o_w (16 x 16 tiles)
// ---------------------------------------------------------------------------
__global__ void prep_aux_kernel(const float* __restrict__ o_w,
                                const int*   __restrict__ ts,
                                const float* __restrict__ tw,
                                const float* __restrict__ pw) {
    __shared__ float tile[32][33];
    int bid = blockIdx.x, tid = threadIdx.x;
    if (bid < 4096) {
        int b = bid >> 10, i = bid & 1023;
        int j = tid * 4;
        int ip = i + 1; if (ip > NSEQ - 1) ip = NSEQ - 1;
        int tl = ts[(b << 10) + ip];
        int4 tj = *(const int4*)&ts[(b << 10) + j];
        float4 o;
        {
            int d = tl - tj.x; if (d < 0) d = -d; if (d < 1) d = 1;
            int bk = (int)(__logf((float)d) * 3.3222591f);
            bk = min(max(bk, 0), 64);
            o.x = pw[j - i + NSEQ - 1] + tw[bk];
        }
        {
            int d = tl - tj.y; if (d < 0) d = -d; if (d < 1) d = 1;
            int bk = (int)(__logf((float)d) * 3.3222591f);
            bk = min(max(bk, 0), 64);
            o.y = pw[j + 1 - i + NSEQ - 1] + tw[bk];
        }
        {
            int d = tl - tj.z; if (d < 0) d = -d; if (d < 1) d = 1;
            int bk = (int)(__logf((float)d) * 3.3222591f);
            bk = min(max(bk, 0), 64);
            o.z = pw[j + 2 - i + NSEQ - 1] + tw[bk];
        }
        {
            int d = tl - tj.w; if (d < 0) d = -d; if (d < 1) d = 1;
            int bk = (int)(__logf((float)d) * 3.3222591f);
            bk = min(max(bk, 0), 64);
            o.w = pw[j + 3 - i + NSEQ - 1] + tw[bk];
        }
        *(float4*)&g_bias[((size_t)(b << 10) + i) * NSEQ + j] = o;
    } else {
        int t = bid - 4096;
        tsplit_body(o_w, g_B2h, g_B2l, DMODEL, DMODEL, t & 15, t >> 4, tile);
    }
}

// ---------------------------------------------------------------------------
// Kernel 4: t = u * LayerNorm(ao0 [+ ao1])  -> g_th/g_tl   grid=4096, block=256
// ---------------------------------------------------------------------------
__global__ void ln_a_kernel(const float* __restrict__ w,
                            const float* __restrict__ b) {
    __shared__ float sm[8];
    int r = blockIdx.x, tid = threadIdx.x;
    const bool two = (r & 1023) >= 512;
    size_t base = (size_t)r * DMODEL;
    float v0 = g_ao0[base + tid], v1 = g_ao0[base + tid + 256];
    if (two) { v0 += g_ao1[base + tid]; v1 += g_ao1[base + tid + 256]; }
    float mean = blk_reduce_sum(v0 + v1, sm) * (1.0f / DMODEL);
    float d0 = v0 - mean, d1 = v1 - mean;
    float var = blk_reduce_sum(d0*d0 + d1*d1, sm) * (1.0f / DMODEL);
    float inv = rsqrtf(var + 1e-5f);
    size_t ub = (size_t)r * EOUT;
    float u0 = __bfloat162float(g_uoh[ub + tid])       + __bfloat162float(g_uol[ub + tid]);
    float u1 = __bfloat162float(g_uoh[ub + tid + 256]) + __bfloat162float(g_uol[ub + tid + 256]);
    split_write(g_th, g_tl, base + tid,       (d0*inv*w[tid]       + b[tid])       * u0);
    split_write(g_th, g_tl, base + tid + 256, (d1*inv*w[tid + 256] + b[tid + 256]) * u1);
}

// ---------------------------------------------------------------------------
// Fused 3-term bf16-split GEMM (HMMA): C = Ah@Bh^T + Al@Bh^T + Ah@Bl^T.
// CTA 128x128, 8 warps (2m x 4n, 64x32 warp tile), K chunks of 32,
// 2-stage cp.async pipeline, 2 CTAs/SM.   (R11-proven)
// ---------------------------------------------------------------------------
#define KSEG   512
#define KCH    32
#define NCH    (KSEG/KCH)            // 16
#define TPAD   40                    // 32 + 8 elems -> 80B row stride
#define TBYTES (128*TPAD*2)          // 10240 B per tile
#define STAGE4 (4*TBYTES)            // Ah,Al,Bh,Bl per stage
#define SMEM_GEMM (2*STAGE4)         // 81920 B

template<int EPI>
__global__ void __launch_bounds__(256, 2)
mma_gemm(const __nv_bfloat16* __restrict__ Ah, const __nv_bfloat16* __restrict__ Al,
         const __nv_bfloat16* __restrict__ Bh, const __nv_bfloat16* __restrict__ Bl,
         float* __restrict__ C,
         __nv_bfloat16* __restrict__ Ch, __nv_bfloat16* __restrict__ Cl, int N,
         const float* __restrict__ bias, const float* __restrict__ resid,
         const unsigned char* __restrict__ pm) {
    const int tid = threadIdx.x, wid = tid >> 5, lane = tid & 31;
    const int bm = blockIdx.y * 128, bn = blockIdx.x * 128;
    const int wm = wid & 1, wn = wid >> 1;     // warp tile (wm*64, wn*32)

    const uint32_t sbase = smem_to_u32(dynsmem);
    const int lrow = lane & 15, lcol = (lane >> 4) * 8;
    const int crow = tid >> 2, ccol = (tid & 3) * 8;

    float acc[4][4][4];
    #pragma unroll
    for (int i = 0; i < 4; i++)
        #pragma unroll
        for (int j = 0; j < 4; j++)
            #pragma unroll
            for (int k = 0; k < 4; k++) acc[i][j][k] = 0.0f;

    auto issue = [&](int c, int stg) {
        const int kc = c * KCH;
        const uint32_t st = sbase + stg * STAGE4;
        #pragma unroll
        for (int i = 0; i < 2; i++) {
            int row = crow + i*64;
            uint32_t so = (row*TPAD + ccol)*2;
            cp16(st + 0*TBYTES + so, Ah + (size_t)(bm + row)*KSEG + kc + ccol);
            cp16(st + 1*TBYTES + so, Al + (size_t)(bm + row)*KSEG + kc + ccol);
            cp16(st + 2*TBYTES + so, Bh + (size_t)(bn + row)*KSEG + kc + ccol);
            cp16(st + 3*TBYTES + so, Bl + (size_t)(bn + row)*KSEG + kc + ccol);
        }
        CP_COMMIT();
    };

    issue(0, 0);
    for (int c = 0; c < NCH; c++) {
        if (c + 1 < NCH) { issue(c + 1, (c + 1) & 1); CP_WAIT(1); }
        else             { CP_WAIT(0); }
        __syncthreads();
        const uint32_t st = sbase + (c & 1) * STAGE4;
        const uint32_t sah = st, sal = st + TBYTES;
        const uint32_t sbh = st + 2*TBYTES, sbl = st + 3*TBYTES;
        #pragma unroll
        for (int ks = 0; ks < 2; ks++) {
            const int ko = ks * 16;
            uint32_t afh[4][4], afl[4][4], bfh[2][4], bfl[2][4];
            #pragma unroll
            for (int fm = 0; fm < 4; fm++)
                ldsm4(afh[fm], sah + ((wm*64 + fm*16 + lrow)*TPAD + ko + lcol)*2);
            #pragma unroll
            for (int g = 0; g < 2; g++)
                ldsm4(bfh[g], sbh + ((wn*32 + g*16 + lrow)*TPAD + ko + lcol)*2);
            #pragma unroll
            for (int fm = 0; fm < 4; fm++)
                #pragma unroll
                for (int fn = 0; fn < 4; fn++) {
                    uint32_t bb[2] = { bfh[fn >> 1][(fn & 1) + 0],
                                       bfh[fn >> 1][(fn & 1) + 2] };
                    mma16816(acc[fm][fn], afh[fm], bb);
                }
            #pragma unroll
            for (int fm = 0; fm < 4; fm++)
                ldsm4(afl[fm], sal + ((wm*64 + fm*16 + lrow)*TPAD + ko + lcol)*2);
            #pragma unroll
            for (int fm = 0; fm < 4; fm++)
                #pragma unroll
                for (int fn = 0; fn < 4; fn++) {
                    uint32_t bb[2] = { bfh[fn >> 1][(fn & 1) + 0],
                                       bfh[fn >> 1][(fn & 1) + 2] };
                    mma16816(acc[fm][fn], afl[fm], bb);
                }
            #pragma unroll
            for (int g = 0; g < 2; g++)
                ldsm4(bfl[g], sbl + ((wn*32 + g*16 + lrow)*TPAD + ko + lcol)*2);
            #pragma unroll
            for (int fm = 0; fm < 4; fm++)
                #pragma unroll
                for (int fn = 0; fn < 4; fn++) {
                    uint32_t bb[2] = { bfl[fn >> 1][(fn & 1) + 0],
                                       bfl[fn >> 1][(fn & 1) + 2] };
                    mma16816(acc[fm][fn], afh[fm], bb);
                }
        }
        __syncthreads();
    }

    #pragma unroll
    for (int fm = 0; fm < 4; fm++) {
        #pragma unroll
        for (int half = 0; half < 2; half++) {
            int r = bm + wm*64 + fm*16 + (lane >> 2) + half*8;
            #pragma unroll
            for (int fn = 0; fn < 4; fn++) {
                int cc = bn + wn*32 + fn*8 + (lane & 3)*2;
                float vx = acc[fm][fn][half*2 + 0];
                float vy = acc[fm][fn][half*2 + 1];
                if (EPI == 0) {
                    vx = vx / (1.0f + __expf(-vx));
                    vy = vy / (1.0f + __expf(-vy));
                    uint32_t hi = pack_hi(vx, vy);
                    uint32_t lo = pack_lo(vx, vy, hi);
                    *(uint32_t*)&Ch[(size_t)r*N + cc] = hi;
                    *(uint32_t*)&Cl[(size_t)r*N + cc] = lo;
                } else {
                    vx += bias[cc]     + resid[(size_t)r*N + cc];
                    vy += bias[cc + 1] + resid[(size_t)r*N + cc + 1];
                    if (pm[r]) { vx = 0.0f; vy = 0.0f; }
                    float2 v = {vx, vy};
                    *(float2*)&C[(size_t)r*N + cc] = v;
                }
            }
        }
    }
}

// ---------------------------------------------------------------------------
// Kernel 3: causal silu-attention (HMMA), precomputed bias, pipelined K/V.
// (R12-proven, unchanged)
// ---------------------------------------------------------------------------
#define ATPAD 72
#define ATILE (64*ATPAD*2)           // 9216 B per bf16 tile
#define ATT_QH 0
#define ATT_QL (1*ATILE)
#define ATT_KH (2*ATILE)
#define ATT_KL (3*ATILE)
#define ATT_VH (4*ATILE)
#define ATT_VL (5*ATILE)
#define ATT_PM (6*ATILE)             // pmj[2][64]
#define SMEM_ATTN (ATT_PM + 2*64*4)

__global__ void __launch_bounds__(128)
attn_kernel(const unsigned char* __restrict__ pm) {
    unsigned char* sm = dynsmem;
    int* pmj = (int*)(sm + ATT_PM);

    const int bh = blockIdx.x, b = bh >> 3, h = bh & 7;
    const int wy = blockIdx.y;
    int it, jlo, jhi, dst;
    if (wy < 16) {
        it = 15 - (wy >> 1);
        int m = (it + 2) >> 1;
        if (wy & 1) { jlo = m; jhi = it + 1; dst = 1; }
        else        { jlo = 0; jhi = m;      dst = 0; }
    } else {
        it = 23 - wy; jlo = 0; jhi = it + 1; dst = 0;
    }
    const int i0 = it * 64;
    const int tid = threadIdx.x, wq = tid >> 5, lane = tid & 31;
    const int lrow = lane & 15, lcol = (lane >> 4) * 8;

    const uint32_t sqh = smem_to_u32(sm);
    const uint32_t sql = sqh + ATT_QL;
    const uint32_t skh = sqh + ATT_KH, skl = sqh + ATT_KL;
    const uint32_t svh = sqh + ATT_VH, svl = sqh + ATT_VL;

    auto issue_k = [&](int jt, int slot) {
        const int j0 = jt * 64;
        #pragma unroll
        for (int i = 0; i < 4; i++) {
            int id = i*128 + tid, row = id >> 3, col = (id & 7) * 8;
            size_t bkv = (size_t)(b*NSEQ + j0 + row)*EOUT + h*64 + col;
            uint32_t so = (row*ATPAD + col)*2;
            cp16(skh + so, &g_uoh[bkv + 1536]);
            cp16(skl + so, &g_uol[bkv + 1536]);
        }
        if (tid < 64) pmj[slot*64 + tid] = pm[b*NSEQ + j0 + tid];
        CP_COMMIT();
    };
    auto issue_v = [&](int jt) {
        const int j0 = jt * 64;
        #pragma unroll
        for (int i = 0; i < 4; i++) {
            int id = i*128 + tid, row = id >> 3, col = (id & 7) * 8;
            size_t bkv = (size_t)(b*NSEQ + j0 + row)*EOUT + h*64 + col;
            uint32_t so = (row*ATPAD + col)*2;
            cp16(svh + so, &g_uoh[bkv + 512]);
            cp16(svl + so, &g_uol[bkv + 512]);
        }
        CP_COMMIT();
    };

    // Q tiles (cols 1024 + h*64)
    #pragma unroll
    for (int i = 0; i < 4; i++) {
        int id = i*128 + tid, row = id >> 3, col = (id & 7) * 8;
        size_t src = (size_t)(b*NSEQ + i0 + row)*EOUT + 1024 + h*64 + col;
        cp16(sqh + (row*ATPAD + col)*2, &g_uoh[src]);
        cp16(sql + (row*ATPAD + col)*2, &g_uol[src]);
    }
    CP_COMMIT(); CP_WAIT(0);
    __syncthreads();

    issue_k(jlo, 0);
    issue_v(jlo);

    float of[8][4];
    #pragma unroll
    for (int f = 0; f < 8; f++)
        #pragma unroll
        for (int r = 0; r < 4; r++) of[f][r] = 0.0f;

    const int row_lo = wq*16 + (lane >> 2);
    const int col_in = (lane & 3) * 2;

    for (int jt = jlo; jt < jhi; jt++) {
        const int j0 = jt * 64;
        const int slot = (jt - jlo) & 1;
        CP_WAIT(1);
        __syncthreads();

        // ---- Phase A: S = Q K^T (3-term split) ----
        float sc[8][4];
        #pragma unroll
        for (int f = 0; f < 8; f++)
            #pragma unroll
            for (int r = 0; r < 4; r++) sc[f][r] = 0.0f;

        #pragma unroll
        for (int ks = 0; ks < 4; ks++) {
            uint32_t ah[4], al[4], kh[4][4], kl[4][4];
            ldsm4(ah, sqh + ((wq*16 + lrow)*ATPAD + ks*16 + lcol)*2);
            ldsm4(al, sql + ((wq*16 + lrow)*ATPAD + ks*16 + lcol)*2);
            #pragma unroll
            for (int g = 0; g < 4; g++) {
                ldsm4(kh[g], skh + ((g*16 + lrow)*ATPAD + ks*16 + lcol)*2);
                ldsm4(kl[g], skl + ((g*16 + lrow)*ATPAD + ks*16 + lcol)*2);
            }
            #pragma unroll
            for (int fn = 0; fn < 8; fn++) {
                uint32_t bh_[2] = { kh[fn >> 1][(fn & 1) + 0], kh[fn >> 1][(fn & 1) + 2] };
                uint32_t bl_[2] = { kl[fn >> 1][(fn & 1) + 0], kl[fn >> 1][(fn & 1) + 2] };
                mma16816(sc[fn], ah, bh_);
                mma16816(sc[fn], al, bh_);
                mma16816(sc[fn], ah, bl_);
            }
        }
        __syncthreads();
        if (jt + 1 < jhi) issue_k(jt + 1, slot ^ 1);

        // ---- Epilogue: +bias (precomputed), silu/N, mask ----
        const int* pms = pmj + slot*64;
        #pragma unroll
        for (int f = 0; f < 8; f++) {
            int jb = j0 + f*8 + col_in;
            float2 b0 = *(const float2*)&g_bias[((size_t)(b << 10) + i0 + row_lo)     * NSEQ + jb];
            float2 b1 = *(const float2*)&g_bias[((size_t)(b << 10) + i0 + row_lo + 8) * NSEQ + jb];
            #pragma unroll
            for (int r = 0; r < 4; r++) {
                int il = row_lo + ((r >> 1) ? 8 : 0);
                int jl = f*8 + col_in + (r & 1);
                int ig = i0 + il, jg = j0 + jl;
                float bb = (r < 2) ? ((r & 1) ? b0.y : b0.x) : ((r & 1) ? b1.y : b1.x);
                float s = sc[f][r] + bb;
                s = s / (1.0f + __expf(-s)) * (1.0f / NSEQ);
                if (jg > ig || pms[jl]) s = 0.0f;
                sc[f][r] = s;
            }
        }

        if (jt + 1 < jhi) { CP_WAIT(1); } else { CP_WAIT(0); }
        __syncthreads();

        // ---- Phase B: O += S @ V (3-term split; S packed from C-frags) ----
        #pragma unroll
        for (int ks = 0; ks < 4; ks++) {
            uint32_t ah[4], al[4];
            ah[0] = pack_hi(sc[2*ks][0],   sc[2*ks][1]);
            ah[1] = pack_hi(sc[2*ks][2],   sc[2*ks][3]);
            ah[2] = pack_hi(sc[2*ks+1][0], sc[2*ks+1][1]);
            ah[3] = pack_hi(sc[2*ks+1][2], sc[2*ks+1][3]);
            al[0] = pack_lo(sc[2*ks][0],   sc[2*ks][1],   ah[0]);
            al[1] = pack_lo(sc[2*ks][2],   sc[2*ks][3],   ah[1]);
            al[2] = pack_lo(sc[2*ks+1][0], sc[2*ks+1][1], ah[2]);
            al[3] = pack_lo(sc[2*ks+1][2], sc[2*ks+1][3], ah[3]);
            uint32_t voff = ((ks*16 + ((lane >> 3) & 1)*8 + (lane & 7))*ATPAD
                            + (lane >> 4)*8) * 2;
            #pragma unroll
            for (int dg = 0; dg < 4; dg++) {
                uint32_t vh[4], vl[4];
                ldsm4t(vh, svh + voff + dg*16*2);
                ldsm4t(vl, svl + voff + dg*16*2);
                #pragma unroll
                for (int half = 0; half < 2; half++) {
                    int fd = dg*2 + half;
                    uint32_t bh_[2] = { vh[half*2], vh[half*2 + 1] };
                    uint32_t bl_[2] = { vl[half*2], vl[half*2 + 1] };
                    mma16816(of[fd], ah, bh_);
                    mma16816(of[fd], al, bh_);
                    mma16816(of[fd], ah, bl_);
                }
            }
        }
        __syncthreads();
        if (jt + 1 < jhi) issue_v(jt + 1);
    }

    // ---- write O partial ----
    float* aop = dst ? g_ao1 : g_ao0;
    #pragma unroll
    for (int fd = 0; fd < 8; fd++) {
        #pragma unroll
        for (int half = 0; half < 2; half++) {
            int row = i0 + row_lo + half*8;
            int col = h*64 + fd*8 + col_in;
            float2 v = { of[fd][half*2], of[fd][half*2 + 1] };
            *(float2*)&aop[(size_t)(b*NSEQ + row)*DMODEL + col] = v;
        }
    }
}

// ---------------------------------------------------------------------------
// Launch — two-stream schedule:
//   stream 0:  prep_core -> gemm_vqk -> [wait aux] attn -> [wait u] ln_a -> gemm1
//   stream B:  prep_aux -> [wait core] gemm_u
// Streams/events created lazily on first (uncaptured correctness) call.
// ---------------------------------------------------------------------------
extern "C" void kernel_launch(void* const* d_in, const int* in_sizes, int n_in,
                              void* d_out, int out_size) {
    const float*          x      = (const float*)d_in[0];
    const int*            ts     = (const int*)d_in[1];     // int32 (JAX x64 off)
    /* d_in[2] = cm — analytic triu(k=1), unused */
    const unsigned char*  pm     = (const unsigned char*)d_in[3];
    const float*          uvqk   = (const float*)d_in[4];
    const float*          o_w    = (const float*)d_in[5];
    const float*          o_b    = (const float*)d_in[6];
    const float*          ln_x_w = (const float*)d_in[7];
    const float*          ln_x_b = (const float*)d_in[8];
    const float*          ln_a_w = (const float*)d_in[9];
    const float*          ln_a_b = (const float*)d_in[10];
    const float*          ts_w   = (const float*)d_in[11];
    const float*          pos_w  = (const float*)d_in[12];
    float*                out    = (float*)d_out;

    __nv_bfloat16 *p_uoh, *p_uol, *p_nxh, *p_nxl, *p_th, *p_tl;
    __nv_bfloat16 *p_B1h, *p_B1l, *p_B2h, *p_B2l;
    cudaGetSymbolAddress((void**)&p_uoh, g_uoh);
    cudaGetSymbolAddress((void**)&p_uol, g_uol);
    cudaGetSymbolAddress((void**)&p_nxh, g_nxh);
    cudaGetSymbolAddress((void**)&p_nxl, g_nxl);
    cudaGetSymbolAddress((void**)&p_th,  g_th);
    cudaGetSymbolAddress((void**)&p_tl,  g_tl);
    cudaGetSymbolAddress((void**)&p_B1h, g_B1h);
    cudaGetSymbolAddress((void**)&p_B1l, g_B1l);
    cudaGetSymbolAddress((void**)&p_B2h, g_B2h);
    cudaGetSymbolAddress((void**)&p_B2l, g_B2l);

    cudaFuncSetAttribute(mma_gemm<0>, cudaFuncAttributeMaxDynamicSharedMemorySize, SMEM_GEMM);
    cudaFuncSetAttribute(mma_gemm<1>, cudaFuncAttributeMaxDynamicSharedMemorySize, SMEM_GEMM);
    cudaFuncSetAttribute(attn_kernel, cudaFuncAttributeMaxDynamicSharedMemorySize, SMEM_ATTN);

    // Lazy one-time stream/event creation (first call = uncaptured correctness
    // run; subsequent captured calls reuse the same handles).
    static cudaStream_t sB = nullptr;
    static cudaEvent_t evStart, evAux, evCore, evU;
    if (sB == nullptr) {
        cudaStreamCreateWithFlags(&sB, cudaStreamNonBlocking);
        cudaEventCreateWithFlags(&evStart, cudaEventDisableTiming);
        cudaEventCreateWithFlags(&evAux,   cudaEventDisableTiming);
        cudaEventCreateWithFlags(&evCore,  cudaEventDisableTiming);
        cudaEventCreateWithFlags(&evU,     cudaEventDisableTiming);
    }

    // fork stream B
    cudaEventRecord(evStart, 0);
    cudaStreamWaitEvent(sB, evStart, 0);

    // stream B: bias + tsplit(o_w)
    prep_aux_kernel<<<4352, 256, 0, sB>>>(o_w, ts, ts_w, pos_w);
    cudaEventRecord(evAux, sB);

    // stream 0: ln_x + tsplit(uvqk)
    prep_core_kernel<<<5120, 256>>>(x, ln_x_w, ln_x_b, uvqk);
    cudaEventRecord(evCore, 0);

    // stream 0: vqk GEMM (cols 512..2048) + silu -> hi/lo bf16
    mma_gemm<0><<<dim3(12, ROWS/128), 256, SMEM_GEMM>>>(
        p_nxh, p_nxl, p_B1h + (size_t)512*KSEG, p_B1l + (size_t)512*KSEG,
        nullptr, p_uoh + 512, p_uol + 512, EOUT, nullptr, nullptr, nullptr);

    // stream B: u GEMM (cols 0..512) after prep_core
    cudaStreamWaitEvent(sB, evCore, 0);
    mma_gemm<0><<<dim3(4, ROWS/128), 256, SMEM_GEMM, sB>>>(
        p_nxh, p_nxl, p_B1h, p_B1l,
        nullptr, p_uoh, p_uol, EOUT, nullptr, nullptr, nullptr);
    cudaEventRecord(evU, sB);

    // stream 0: attention (needs vqk + bias)
    cudaStreamWaitEvent(0, evAux, 0);
    attn_kernel<<<dim3(NB*NH, 24), 128, SMEM_ATTN>>>(pm);

    // stream 0: ln_a (needs attention + u)
    cudaStreamWaitEvent(0, evU, 0);
    ln_a_kernel<<<ROWS, 256>>>(ln_a_w, ln_a_b);

    // stream 0: final GEMM (needs ln_a + tsplit o_w, joined via evAux above)
    mma_gemm<1><<<dim3(DMODEL/128, ROWS/128), 256, SMEM_GEMM>>>(
        p_th, p_tl, p_B2h, p_B2l,
        out, nullptr, nullptr, DMODEL, o_b, x, pm);
}

// round 15
// speedup vs baseline: 1.3009x; 1.0282x over previous
#include <cuda_runtime.h>
#include <cuda_bf16.h>
#include <cuda_fp16.h>
#include <cstdint>
#include <math.h>

// Problem constants
#define NB     4
#define NSEQ   1024
#define DMODEL 512
#define NH     8
#define HD     64
#define EOUT   2048          // 2*H*Dv + 2*H*Dq
#define ROWS   (NB*NSEQ)     // 4096

// Single dynamic-smem symbol (typed via casts in each kernel)
extern __shared__ __align__(128) unsigned char dynsmem[];

// ---------------------------------------------------------------------------
// Scratch (allocation-free -> __device__ globals)
// ---------------------------------------------------------------------------
__device__ float g_ao0[ROWS*DMODEL];  // attention output (split 0)
__device__ float g_ao1[ROWS*DMODEL];  // attention output (split 1, rows i>=512)
__device__ float g_bias[(size_t)NB*NSEQ*NSEQ];                    // rel-bias, head-invariant
__device__ __half g_uoh[ROWS*EOUT], g_uol[ROWS*EOUT];             // silu(nx@uvqk) fp16 hi/lo
__device__ __nv_bfloat16 g_nxh[ROWS*DMODEL], g_nxl[ROWS*DMODEL];  // LN(x) hi/lo
__device__ __nv_bfloat16 g_th [ROWS*DMODEL], g_tl [ROWS*DMODEL];  // u*LN(ao) hi/lo
__device__ __nv_bfloat16 g_B1h[EOUT*DMODEL], g_B1l[EOUT*DMODEL];  // uvqk^T  [2048][512]
__device__ __nv_bfloat16 g_B2h[DMODEL*DMODEL], g_B2l[DMODEL*DMODEL]; // o_w^T [512][512]

// ---------------------------------------------------------------------------
// mma.sync helpers (sm_80-era PTX, legal on compute_103)
// ---------------------------------------------------------------------------
__device__ __forceinline__ uint32_t smem_to_u32(const void* p) {
    uint32_t a;
    asm("{ .reg .u64 t; cvta.to.shared.u64 t, %1; cvt.u32.u64 %0, t; }" : "=r"(a) : "l"(p));
    return a;
}
__device__ __forceinline__ void ldsm4(uint32_t* r, uint32_t addr) {
    asm volatile("ldmatrix.sync.aligned.m8n8.x4.shared.b16 {%0,%1,%2,%3}, [%4];"
        : "=r"(r[0]), "=r"(r[1]), "=r"(r[2]), "=r"(r[3]) : "r"(addr));
}
__device__ __forceinline__ void ldsm4t(uint32_t* r, uint32_t addr) {
    asm volatile("ldmatrix.sync.aligned.m8n8.x4.trans.shared.b16 {%0,%1,%2,%3}, [%4];"
        : "=r"(r[0]), "=r"(r[1]), "=r"(r[2]), "=r"(r[3]) : "r"(addr));
}
// bf16 MMA (GEMMs)
__device__ __forceinline__ void mma16816(float* c, const uint32_t* a, const uint32_t* b) {
    asm volatile("mma.sync.aligned.m16n8k16.row.col.f32.bf16.bf16.f32 "
        "{%0,%1,%2,%3}, {%4,%5,%6,%7}, {%8,%9}, {%0,%1,%2,%3};"
        : "+f"(c[0]), "+f"(c[1]), "+f"(c[2]), "+f"(c[3])
        : "r"(a[0]), "r"(a[1]), "r"(a[2]), "r"(a[3]), "r"(b[0]), "r"(b[1]));
}
// fp16 MMA (attention)
__device__ __forceinline__ void mma16816h(float* c, const uint32_t* a, const uint32_t* b) {
    asm volatile("mma.sync.aligned.m16n8k16.row.col.f32.f16.f16.f32 "
        "{%0,%1,%2,%3}, {%4,%5,%6,%7}, {%8,%9}, {%0,%1,%2,%3};"
        : "+f"(c[0]), "+f"(c[1]), "+f"(c[2]), "+f"(c[3])
        : "r"(a[0]), "r"(a[1]), "r"(a[2]), "r"(a[3]), "r"(b[0]), "r"(b[1]));
}
__device__ __forceinline__ void cp16(uint32_t s, const void* g) {
    asm volatile("cp.async.cg.shared.global [%0], [%1], 16;" :: "r"(s), "l"(g));
}
#define CP_COMMIT() asm volatile("cp.async.commit_group;")
#define CP_WAIT(N)  asm volatile("cp.async.wait_group %0;" :: "n"(N))

// bf16 packs (GEMM epilogue for g_th/g_tl path removed; kept for symmetry)
__device__ __forceinline__ uint32_t packh_hi(float a, float b) {
    __half2 t = __floats2half2_rn(a, b);
    return *(uint32_t*)&t;
}
__device__ __forceinline__ uint32_t packh_lo(float a, float b, uint32_t hi) {
    __half2 h = *(__half2*)&hi;
    __half2 t = __floats2half2_rn(a - __half2float(h.x), b - __half2float(h.y));
    return *(uint32_t*)&t;
}

// ---------------------------------------------------------------------------
// Block reduction (256 threads)
// ---------------------------------------------------------------------------
__device__ __forceinline__ float blk_reduce_sum(float v, float* sm) {
    int tid = threadIdx.x;
    #pragma unroll
    for (int o = 16; o > 0; o >>= 1) v += __shfl_down_sync(0xffffffffu, v, o);
    if ((tid & 31) == 0) sm[tid >> 5] = v;
    __syncthreads();
    if (tid < 32) {
        float t = (tid < 8) ? sm[tid] : 0.0f;
        #pragma unroll
        for (int o = 4; o > 0; o >>= 1) t += __shfl_down_sync(0xffffffffu, t, o);
        if (tid == 0) sm[0] = t;
    }
    __syncthreads();
    float r = sm[0];
    __syncthreads();
    return r;
}

__device__ __forceinline__ void split_write(__nv_bfloat16* ph, __nv_bfloat16* pl,
                                            size_t idx, float v) {
    __nv_bfloat16 h = __float2bfloat16(v);
    ph[idx] = h;
    pl[idx] = __float2bfloat16(v - __bfloat162float(h));
}

// ---------------------------------------------------------------------------
// tsplit body (transpose + bf16 split): in[K][N] fp32 -> oh/ol[N][K]
// ---------------------------------------------------------------------------
__device__ __forceinline__ void tsplit_body(const float* __restrict__ in,
                                            __nv_bfloat16* __restrict__ oh,
                                            __nv_bfloat16* __restrict__ ol,
                                            int K, int N, int bx, int by,
                                            float (*tile)[33]) {
    int tid = threadIdx.x;
    int tx = tid & 31, ty = tid >> 5;
    int n0 = bx * 32, k0 = by * 32;
    #pragma unroll
    for (int i = 0; i < 4; i++)
        tile[ty + i*8][tx] = in[(size_t)(k0 + ty + i*8) * N + n0 + tx];
    __syncthreads();
    #pragma unroll
    for (int i = 0; i < 4; i++) {
        float v = tile[tx][ty + i*8];
        __nv_bfloat16 h = __float2bfloat16(v);
        size_t o = (size_t)(n0 + ty + i*8) * K + k0 + tx;
        oh[o] = h;
        ol[o] = __float2bfloat16(v - __bfloat162float(h));
    }
}

// ---------------------------------------------------------------------------
// prep_core (stream 0):  [0,4096): ln_x   [4096,5120): tsplit uvqk
// ---------------------------------------------------------------------------
__global__ void prep_core_kernel(const float* __restrict__ x,
                                 const float* __restrict__ lnw,
                                 const float* __restrict__ lnb,
                                 const float* __restrict__ uvqk) {
    __shared__ float sm[8];
    __shared__ float tile[32][33];
    int bid = blockIdx.x, tid = threadIdx.x;
    if (bid < 4096) {
        int r = bid;
        const float* xr = x + (size_t)r * DMODEL;
        float v0 = xr[tid], v1 = xr[tid + 256];
        float mean = blk_reduce_sum(v0 + v1, sm) * (1.0f / DMODEL);
        float d0 = v0 - mean, d1 = v1 - mean;
        float var = blk_reduce_sum(d0*d0 + d1*d1, sm) * (1.0f / DMODEL);
        float inv = rsqrtf(var + 1e-5f);
        split_write(g_nxh, g_nxl, (size_t)r*DMODEL + tid,       d0*inv*lnw[tid]       + lnb[tid]);
        split_write(g_nxh, g_nxl, (size_t)r*DMODEL + tid + 256, d1*inv*lnw[tid + 256] + lnb[tid + 256]);
    } else {
        int t = bid - 4096;
        tsplit_body(uvqk, g_B1h, g_B1l, DMODEL, EOUT, t & 63, t >> 6, tile);
    }
}

// ---------------------------------------------------------------------------
// prep_aux (stream B):  [0,4096): bias   [4096,4352): tsplit o_w
// ---------------------------------------------------------------------------
__global__ void prep_aux_kernel(const float* __restrict__ o_w,
                                const int*   __restrict__ ts,
                                const float* __restrict__ tw,
                                const float* __restrict__ pw) {
    __shared__ float tile[32][33];
    int bid = blockIdx.x, tid = threadIdx.x;
    if (bid < 4096) {
        int b = bid >> 10, i = bid & 1023;
        int j = tid * 4;
        int ip = i + 1; if (ip > NSEQ - 1) ip = NSEQ - 1;
        int tl = ts[(b << 10) + ip];
        int4 tj = *(const int4*)&ts[(b << 10) + j];
        float4 o;
        {
            int d = tl - tj.x; if (d < 0) d = -d; if (d < 1) d = 1;
            int bk = (int)(__logf((float)d) * 3.3222591f);
            bk = min(max(bk, 0), 64);
            o.x = pw[j - i + NSEQ - 1] + tw[bk];
        }
        {
            int d = tl - tj.y; if (d < 0) d = -d; if (d < 1) d = 1;
            int bk = (int)(__logf((float)d) * 3.3222591f);
            bk = min(max(bk, 0), 64);
            o.y = pw[j + 1 - i + NSEQ - 1] + tw[bk];
        }
        {
            int d = tl - tj.z; if (d < 0) d = -d; if (d < 1) d = 1;
            int bk = (int)(__logf((float)d) * 3.3222591f);
            bk = min(max(bk, 0), 64);
            o.z = pw[j + 2 - i + NSEQ - 1] + tw[bk];
        }
        {
            int d = tl - tj.w; if (d < 0) d = -d; if (d < 1) d = 1;
            int bk = (int)(__logf((float)d) * 3.3222591f);
            bk = min(max(bk, 0), 64);
            o.w = pw[j + 3 - i + NSEQ - 1] + tw[bk];
        }
        *(float4*)&g_bias[((size_t)(b << 10) + i) * NSEQ + j] = o;
    } else {
        int t = bid - 4096;
        tsplit_body(o_w, g_B2h, g_B2l, DMODEL, DMODEL, t & 15, t >> 4, tile);
    }
}

// ---------------------------------------------------------------------------
// Kernel 4: t = u * LayerNorm(ao0 [+ ao1])  -> g_th/g_tl   grid=4096, block=256
// ---------------------------------------------------------------------------
__global__ void ln_a_kernel(const float* __restrict__ w,
                            const float* __restrict__ b) {
    __shared__ float sm[8];
    int r = blockIdx.x, tid = threadIdx.x;
    const bool two = (r & 1023) >= 512;
    size_t base = (size_t)r * DMODEL;
    float v0 = g_ao0[base + tid], v1 = g_ao0[base + tid + 256];
    if (two) { v0 += g_ao1[base + tid]; v1 += g_ao1[base + tid + 256]; }
    float mean = blk_reduce_sum(v0 + v1, sm) * (1.0f / DMODEL);
    float d0 = v0 - mean, d1 = v1 - mean;
    float var = blk_reduce_sum(d0*d0 + d1*d1, sm) * (1.0f / DMODEL);
    float inv = rsqrtf(var + 1e-5f);
    size_t ub = (size_t)r * EOUT;
    float u0 = __half2float(g_uoh[ub + tid])       + __half2float(g_uol[ub + tid]);
    float u1 = __half2float(g_uoh[ub + tid + 256]) + __half2float(g_uol[ub + tid + 256]);
    split_write(g_th, g_tl, base + tid,       (d0*inv*w[tid]       + b[tid])       * u0);
    split_write(g_th, g_tl, base + tid + 256, (d1*inv*w[tid + 256] + b[tid + 256]) * u1);
}

// ---------------------------------------------------------------------------
// Fused 3-term bf16-split GEMM (HMMA): C = Ah@Bh^T + Al@Bh^T + Ah@Bl^T.
// CTA 128x128, 8 warps (2m x 4n, 64x32 warp tile), K chunks of 32,
// 2-stage cp.async pipeline, 2 CTAs/SM.   (R11-proven)
// EPI 0: silu -> fp16 hi/lo.  EPI 1: fp32 +bias+resid, pm mask.
// ---------------------------------------------------------------------------
#define KSEG   512
#define KCH    32
#define NCH    (KSEG/KCH)            // 16
#define TPAD   40                    // 32 + 8 elems -> 80B row stride
#define TBYTES (128*TPAD*2)          // 10240 B per tile
#define STAGE4 (4*TBYTES)            // Ah,Al,Bh,Bl per stage
#define SMEM_GEMM (2*STAGE4)         // 81920 B

template<int EPI>
__global__ void __launch_bounds__(256, 2)
mma_gemm(const __nv_bfloat16* __restrict__ Ah, const __nv_bfloat16* __restrict__ Al,
         const __nv_bfloat16* __restrict__ Bh, const __nv_bfloat16* __restrict__ Bl,
         float* __restrict__ C,
         __half* __restrict__ Ch, __half* __restrict__ Cl, int N,
         const float* __restrict__ bias, const float* __restrict__ resid,
         const unsigned char* __restrict__ pm) {
    const int tid = threadIdx.x, wid = tid >> 5, lane = tid & 31;
    const int bm = blockIdx.y * 128, bn = blockIdx.x * 128;
    const int wm = wid & 1, wn = wid >> 1;     // warp tile (wm*64, wn*32)

    const uint32_t sbase = smem_to_u32(dynsmem);
    const int lrow = lane & 15, lcol = (lane >> 4) * 8;
    const int crow = tid >> 2, ccol = (tid & 3) * 8;

    float acc[4][4][4];
    #pragma unroll
    for (int i = 0; i < 4; i++)
        #pragma unroll
        for (int j = 0; j < 4; j++)
            #pragma unroll
            for (int k = 0; k < 4; k++) acc[i][j][k] = 0.0f;

    auto issue = [&](int c, int stg) {
        const int kc = c * KCH;
        const uint32_t st = sbase + stg * STAGE4;
        #pragma unroll
        for (int i = 0; i < 2; i++) {
            int row = crow + i*64;
            uint32_t so = (row*TPAD + ccol)*2;
            cp16(st + 0*TBYTES + so, Ah + (size_t)(bm + row)*KSEG + kc + ccol);
            cp16(st + 1*TBYTES + so, Al + (size_t)(bm + row)*KSEG + kc + ccol);
            cp16(st + 2*TBYTES + so, Bh + (size_t)(bn + row)*KSEG + kc + ccol);
            cp16(st + 3*TBYTES + so, Bl + (size_t)(bn + row)*KSEG + kc + ccol);
        }
        CP_COMMIT();
    };

    issue(0, 0);
    for (int c = 0; c < NCH; c++) {
        if (c + 1 < NCH) { issue(c + 1, (c + 1) & 1); CP_WAIT(1); }
        else             { CP_WAIT(0); }
        __syncthreads();
        const uint32_t st = sbase + (c & 1) * STAGE4;
        const uint32_t sah = st, sal = st + TBYTES;
        const uint32_t sbh = st + 2*TBYTES, sbl = st + 3*TBYTES;
        #pragma unroll
        for (int ks = 0; ks < 2; ks++) {
            const int ko = ks * 16;
            uint32_t afh[4][4], afl[4][4], bfh[2][4], bfl[2][4];
            #pragma unroll
            for (int fm = 0; fm < 4; fm++)
                ldsm4(afh[fm], sah + ((wm*64 + fm*16 + lrow)*TPAD + ko + lcol)*2);
            #pragma unroll
            for (int g = 0; g < 2; g++)
                ldsm4(bfh[g], sbh + ((wn*32 + g*16 + lrow)*TPAD + ko + lcol)*2);
            #pragma unroll
            for (int fm = 0; fm < 4; fm++)
                #pragma unroll
                for (int fn = 0; fn < 4; fn++) {
                    uint32_t bb[2] = { bfh[fn >> 1][(fn & 1) + 0],
                                       bfh[fn >> 1][(fn & 1) + 2] };
                    mma16816(acc[fm][fn], afh[fm], bb);
                }
            #pragma unroll
            for (int fm = 0; fm < 4; fm++)
                ldsm4(afl[fm], sal + ((wm*64 + fm*16 + lrow)*TPAD + ko + lcol)*2);
            #pragma unroll
            for (int fm = 0; fm < 4; fm++)
                #pragma unroll
                for (int fn = 0; fn < 4; fn++) {
                    uint32_t bb[2] = { bfh[fn >> 1][(fn & 1) + 0],
                                       bfh[fn >> 1][(fn & 1) + 2] };
                    mma16816(acc[fm][fn], afl[fm], bb);
                }
            #pragma unroll
            for (int g = 0; g < 2; g++)
                ldsm4(bfl[g], sbl + ((wn*32 + g*16 + lrow)*TPAD + ko + lcol)*2);
            #pragma unroll
            for (int fm = 0; fm < 4; fm++)
                #pragma unroll
                for (int fn = 0; fn < 4; fn++) {
                    uint32_t bb[2] = { bfl[fn >> 1][(fn & 1) + 0],
                                       bfl[fn >> 1][(fn & 1) + 2] };
                    mma16816(acc[fm][fn], afh[fm], bb);
                }
        }
        __syncthreads();
    }

    #pragma unroll
    for (int fm = 0; fm < 4; fm++) {
        #pragma unroll
        for (int half = 0; half < 2; half++) {
            int r = bm + wm*64 + fm*16 + (lane >> 2) + half*8;
            #pragma unroll
            for (int fn = 0; fn < 4; fn++) {
                int cc = bn + wn*32 + fn*8 + (lane & 3)*2;
                float vx = acc[fm][fn][half*2 + 0];
                float vy = acc[fm][fn][half*2 + 1];
                if (EPI == 0) {
                    vx = vx / (1.0f + __expf(-vx));
                    vy = vy / (1.0f + __expf(-vy));
                    uint32_t hi = packh_hi(vx, vy);
                    uint32_t lo = packh_lo(vx, vy, hi);
                    *(uint32_t*)&Ch[(size_t)r*N + cc] = hi;
                    *(uint32_t*)&Cl[(size_t)r*N + cc] = lo;
                } else {
                    vx += bias[cc]     + resid[(size_t)r*N + cc];
                    vy += bias[cc + 1] + resid[(size_t)r*N + cc + 1];
                    if (pm[r]) { vx = 0.0f; vy = 0.0f; }
                    float2 v = {vx, vy};
                    *(float2*)&C[(size_t)r*N + cc] = v;
                }
            }
        }
    }
}

// ---------------------------------------------------------------------------
// Kernel 3: causal silu-attention, fp16 2-term MMA, precomputed bias,
// pipelined K/V loads.  grid (32 bh, 24 work), block 128.
// Phase A: S = Qh·(Kh+Kl)  (Q single fp16, K exact fp16 split) — 2 MMAs.
// Phase B: O += Sh·(Vh+Vl) (S single fp16, V exact fp16 split) — 2 MMAs.
// ---------------------------------------------------------------------------
#define ATPAD 72
#define ATILE (64*ATPAD*2)           // 9216 B per fp16 tile
#define ATT_QH 0
#define ATT_KH (1*ATILE)
#define ATT_KL (2*ATILE)
#define ATT_VH (3*ATILE)
#define ATT_VL (4*ATILE)
#define ATT_PM (5*ATILE)             // pmj[2][64]
#define SMEM_ATTN (ATT_PM + 2*64*4)

__global__ void __launch_bounds__(128)
attn_kernel(const unsigned char* __restrict__ pm) {
    unsigned char* sm = dynsmem;
    int* pmj = (int*)(sm + ATT_PM);

    const int bh = blockIdx.x, b = bh >> 3, h = bh & 7;
    const int wy = blockIdx.y;
    int it, jlo, jhi, dst;
    if (wy < 16) {
        it = 15 - (wy >> 1);
        int m = (it + 2) >> 1;
        if (wy & 1) { jlo = m; jhi = it + 1; dst = 1; }
        else        { jlo = 0; jhi = m;      dst = 0; }
    } else {
        it = 23 - wy; jlo = 0; jhi = it + 1; dst = 0;
    }
    const int i0 = it * 64;
    const int tid = threadIdx.x, wq = tid >> 5, lane = tid & 31;
    const int lrow = lane & 15, lcol = (lane >> 4) * 8;

    const uint32_t sqh = smem_to_u32(sm);
    const uint32_t skh = sqh + ATT_KH, skl = sqh + ATT_KL;
    const uint32_t svh = sqh + ATT_VH, svl = sqh + ATT_VL;

    auto issue_k = [&](int jt, int slot) {
        const int j0 = jt * 64;
        #pragma unroll
        for (int i = 0; i < 4; i++) {
            int id = i*128 + tid, row = id >> 3, col = (id & 7) * 8;
            size_t bkv = (size_t)(b*NSEQ + j0 + row)*EOUT + h*64 + col;
            uint32_t so = (row*ATPAD + col)*2;
            cp16(skh + so, &g_uoh[bkv + 1536]);
            cp16(skl + so, &g_uol[bkv + 1536]);
        }
        if (tid < 64) pmj[slot*64 + tid] = pm[b*NSEQ + j0 + tid];
        CP_COMMIT();
    };
    auto issue_v = [&](int jt) {
        const int j0 = jt * 64;
        #pragma unroll
        for (int i = 0; i < 4; i++) {
            int id = i*128 + tid, row = id >> 3, col = (id & 7) * 8;
            size_t bkv = (size_t)(b*NSEQ + j0 + row)*EOUT + h*64 + col;
            uint32_t so = (row*ATPAD + col)*2;
            cp16(svh + so, &g_uoh[bkv + 512]);
            cp16(svl + so, &g_uol[bkv + 512]);
        }
        CP_COMMIT();
    };

    // Q tile (hi only; cols 1024 + h*64)
    #pragma unroll
    for (int i = 0; i < 4; i++) {
        int id = i*128 + tid, row = id >> 3, col = (id & 7) * 8;
        size_t src = (size_t)(b*NSEQ + i0 + row)*EOUT + 1024 + h*64 + col;
        cp16(sqh + (row*ATPAD + col)*2, &g_uoh[src]);
    }
    CP_COMMIT(); CP_WAIT(0);
    __syncthreads();

    issue_k(jlo, 0);
    issue_v(jlo);

    float of[8][4];
    #pragma unroll
    for (int f = 0; f < 8; f++)
        #pragma unroll
        for (int r = 0; r < 4; r++) of[f][r] = 0.0f;

    const int row_lo = wq*16 + (lane >> 2);
    const int col_in = (lane & 3) * 2;

    for (int jt = jlo; jt < jhi; jt++) {
        const int j0 = jt * 64;
        const int slot = (jt - jlo) & 1;
        CP_WAIT(1);
        __syncthreads();

        // ---- Phase A: S = Qh (Kh + Kl)  (2 fp16 MMAs per fragment) ----
        float sc[8][4];
        #pragma unroll
        for (int f = 0; f < 8; f++)
            #pragma unroll
            for (int r = 0; r < 4; r++) sc[f][r] = 0.0f;

        #pragma unroll
        for (int ks = 0; ks < 4; ks++) {
            uint32_t aq[4], kh[4][4], kl[4][4];
            ldsm4(aq, sqh + ((wq*16 + lrow)*ATPAD + ks*16 + lcol)*2);
            #pragma unroll
            for (int g = 0; g < 4; g++) {
                ldsm4(kh[g], skh + ((g*16 + lrow)*ATPAD + ks*16 + lcol)*2);
                ldsm4(kl[g], skl + ((g*16 + lrow)*ATPAD + ks*16 + lcol)*2);
            }
            #pragma unroll
            for (int fn = 0; fn < 8; fn++) {
                uint32_t bh_[2] = { kh[fn >> 1][(fn & 1) + 0], kh[fn >> 1][(fn & 1) + 2] };
                uint32_t bl_[2] = { kl[fn >> 1][(fn & 1) + 0], kl[fn >> 1][(fn & 1) + 2] };
                mma16816h(sc[fn], aq, bh_);
                mma16816h(sc[fn], aq, bl_);
            }
        }
        __syncthreads();
        if (jt + 1 < jhi) issue_k(jt + 1, slot ^ 1);

        // ---- Epilogue: +bias (precomputed), silu/N, mask ----
        const int* pms = pmj + slot*64;
        #pragma unroll
        for (int f = 0; f < 8; f++) {
            int jb = j0 + f*8 + col_in;
            float2 b0 = *(const float2*)&g_bias[((size_t)(b << 10) + i0 + row_lo)     * NSEQ + jb];
            float2 b1 = *(const float2*)&g_bias[((size_t)(b << 10) + i0 + row_lo + 8) * NSEQ + jb];
            #pragma unroll
            for (int r = 0; r < 4; r++) {
                int il = row_lo + ((r >> 1) ? 8 : 0);
                int jl = f*8 + col_in + (r & 1);
                int ig = i0 + il, jg = j0 + jl;
                float bb = (r < 2) ? ((r & 1) ? b0.y : b0.x) : ((r & 1) ? b1.y : b1.x);
                float s = sc[f][r] + bb;
                s = s / (1.0f + __expf(-s)) * (1.0f / NSEQ);
                if (jg > ig || pms[jl]) s = 0.0f;
                sc[f][r] = s;
            }
        }

        if (jt + 1 < jhi) { CP_WAIT(1); } else { CP_WAIT(0); }
        __syncthreads();

        // ---- Phase B: O += Sh (Vh + Vl)  (2 fp16 MMAs per fragment) ----
        #pragma unroll
        for (int ks = 0; ks < 4; ks++) {
            uint32_t ah[4];
            ah[0] = packh_hi(sc[2*ks][0],   sc[2*ks][1]);
            ah[1] = packh_hi(sc[2*ks][2],   sc[2*ks][3]);
            ah[2] = packh_hi(sc[2*ks+1][0], sc[2*ks+1][1]);
            ah[3] = packh_hi(sc[2*ks+1][2], sc[2*ks+1][3]);
            uint32_t voff = ((ks*16 + ((lane >> 3) & 1)*8 + (lane & 7))*ATPAD
                            + (lane >> 4)*8) * 2;
            #pragma unroll
            for (int dg = 0; dg < 4; dg++) {
                uint32_t vh[4], vl[4];
                ldsm4t(vh, svh + voff + dg*16*2);
                ldsm4t(vl, svl + voff + dg*16*2);
                #pragma unroll
                for (int half = 0; half < 2; half++) {
                    int fd = dg*2 + half;
                    uint32_t bh_[2] = { vh[half*2], vh[half*2 + 1] };
                    uint32_t bl_[2] = { vl[half*2], vl[half*2 + 1] };
                    mma16816h(of[fd], ah, bh_);
                    mma16816h(of[fd], ah, bl_);
                }
            }
        }
        __syncthreads();
        if (jt + 1 < jhi) issue_v(jt + 1);
    }

    // ---- write O partial ----
    float* aop = dst ? g_ao1 : g_ao0;
    #pragma unroll
    for (int fd = 0; fd < 8; fd++) {
        #pragma unroll
        for (int half = 0; half < 2; half++) {
            int row = i0 + row_lo + half*8;
            int col = h*64 + fd*8 + col_in;
            float2 v = { of[fd][half*2], of[fd][half*2 + 1] };
            *(float2*)&aop[(size_t)(b*NSEQ + row)*DMODEL + col] = v;
        }
    }
}

// ---------------------------------------------------------------------------
// Launch — two-stream schedule (R13-proven):
//   stream 0:  prep_core -> gemm_vqk -> [wait aux] attn -> [wait u] ln_a -> gemm1
//   stream B:  prep_aux -> [wait core] gemm_u
// ---------------------------------------------------------------------------
extern "C" void kernel_launch(void* const* d_in, const int* in_sizes, int n_in,
                              void* d_out, int out_size) {
    const float*          x      = (const float*)d_in[0];
    const int*            ts     = (const int*)d_in[1];     // int32 (JAX x64 off)
    /* d_in[2] = cm — analytic triu(k=1), unused */
    const unsigned char*  pm     = (const unsigned char*)d_in[3];
    const float*          uvqk   = (const float*)d_in[4];
    const float*          o_w    = (const float*)d_in[5];
    const float*          o_b    = (const float*)d_in[6];
    const float*          ln_x_w = (const float*)d_in[7];
    const float*          ln_x_b = (const float*)d_in[8];
    const float*          ln_a_w = (const float*)d_in[9];
    const float*          ln_a_b = (const float*)d_in[10];
    const float*          ts_w   = (const float*)d_in[11];
    const float*          pos_w  = (const float*)d_in[12];
    float*                out    = (float*)d_out;

    __half *p_uoh, *p_uol;
    __nv_bfloat16 *p_nxh, *p_nxl, *p_th, *p_tl;
    __nv_bfloat16 *p_B1h, *p_B1l, *p_B2h, *p_B2l;
    cudaGetSymbolAddress((void**)&p_uoh, g_uoh);
    cudaGetSymbolAddress((void**)&p_uol, g_uol);
    cudaGetSymbolAddress((void**)&p_nxh, g_nxh);
    cudaGetSymbolAddress((void**)&p_nxl, g_nxl);
    cudaGetSymbolAddress((void**)&p_th,  g_th);
    cudaGetSymbolAddress((void**)&p_tl,  g_tl);
    cudaGetSymbolAddress((void**)&p_B1h, g_B1h);
    cudaGetSymbolAddress((void**)&p_B1l, g_B1l);
    cudaGetSymbolAddress((void**)&p_B2h, g_B2h);
    cudaGetSymbolAddress((void**)&p_B2l, g_B2l);

    cudaFuncSetAttribute(mma_gemm<0>, cudaFuncAttributeMaxDynamicSharedMemorySize, SMEM_GEMM);
    cudaFuncSetAttribute(mma_gemm<1>, cudaFuncAttributeMaxDynamicSharedMemorySize, SMEM_GEMM);
    cudaFuncSetAttribute(attn_kernel, cudaFuncAttributeMaxDynamicSharedMemorySize, SMEM_ATTN);

    static cudaStream_t sB = nullptr;
    static cudaEvent_t evStart, evAux, evCore, evU;
    if (sB == nullptr) {
        cudaStreamCreateWithFlags(&sB, cudaStreamNonBlocking);
        cudaEventCreateWithFlags(&evStart, cudaEventDisableTiming);
        cudaEventCreateWithFlags(&evAux,   cudaEventDisableTiming);
        cudaEventCreateWithFlags(&evCore,  cudaEventDisableTiming);
        cudaEventCreateWithFlags(&evU,     cudaEventDisableTiming);
    }

    cudaEventRecord(evStart, 0);
    cudaStreamWaitEvent(sB, evStart, 0);

    // stream B: bias + tsplit(o_w)
    prep_aux_kernel<<<4352, 256, 0, sB>>>(o_w, ts, ts_w, pos_w);
    cudaEventRecord(evAux, sB);

    // stream 0: ln_x + tsplit(uvqk)
    prep_core_kernel<<<5120, 256>>>(x, ln_x_w, ln_x_b, uvqk);
    cudaEventRecord(evCore, 0);

    // stream 0: vqk GEMM (cols 512..2048) + silu -> fp16 hi/lo
    mma_gemm<0><<<dim3(12, ROWS/128), 256, SMEM_GEMM>>>(
        p_nxh, p_nxl, p_B1h + (size_t)512*KSEG, p_B1l + (size_t)512*KSEG,
        nullptr, p_uoh + 512, p_uol + 512, EOUT, nullptr, nullptr, nullptr);

    // stream B: u GEMM (cols 0..512) after prep_core
    cudaStreamWaitEvent(sB, evCore, 0);
    mma_gemm<0><<<dim3(4, ROWS/128), 256, SMEM_GEMM, sB>>>(
        p_nxh, p_nxl, p_B1h, p_B1l,
        nullptr, p_uoh, p_uol, EOUT, nullptr, nullptr, nullptr);
    cudaEventRecord(evU, sB);

    // stream 0: attention (needs vqk + bias)
    cudaStreamWaitEvent(0, evAux, 0);
    attn_kernel<<<dim3(NB*NH, 24), 128, SMEM_ATTN>>>(pm);

    // stream 0: ln_a (needs attention + u)
    cudaStreamWaitEvent(0, evU, 0);
    ln_a_kernel<<<ROWS, 256>>>(ln_a_w, ln_a_b);

    // stream 0: final GEMM (needs ln_a + tsplit o_w, joined via evAux above)
    mma_gemm<1><<<dim3(DMODEL/128, ROWS/128), 256, SMEM_GEMM>>>(
        p_th, p_tl, p_B2h, p_B2l,
        out, nullptr, nullptr, DMODEL, o_b, x, pm);
}

// round 16
// speedup vs baseline: 1.5293x; 1.1756x over previous
#include <cuda_runtime.h>
#include <cuda_bf16.h>
#include <cuda_fp16.h>
#include <cstdint>
#include <math.h>

// Problem constants
#define NB     4
#define NSEQ   1024
#define DMODEL 512
#define NH     8
#define HD     64
#define EOUT   2048          // 2*H*Dv + 2*H*Dq
#define ROWS   (NB*NSEQ)     // 4096

// Single dynamic-smem symbol (typed via casts in each kernel)
extern __shared__ __align__(128) unsigned char dynsmem[];

// ---------------------------------------------------------------------------
// Scratch (allocation-free -> __device__ globals)
// ---------------------------------------------------------------------------
__device__ float g_ao0[ROWS*DMODEL];  // attention output (split 0)
__device__ float g_ao1[ROWS*DMODEL];  // attention output (split 1, rows i>=512)
__device__ float g_bias[(size_t)NB*NSEQ*NSEQ];                    // rel-bias, head-invariant
__device__ __half g_uoh[ROWS*EOUT], g_uol[ROWS*EOUT];             // silu(nx@uvqk) fp16 hi/lo
__device__ __half g_nxh[ROWS*DMODEL], g_nxl[ROWS*DMODEL];         // LN(x) fp16 hi/lo
__device__ __half g_th [ROWS*DMODEL], g_tl [ROWS*DMODEL];         // u*LN(ao) fp16 hi/lo
__device__ __half g_B1[EOUT*DMODEL];                              // fl16(uvqk^T) [2048][512]
__device__ __half g_B2[DMODEL*DMODEL];                            // fl16(o_w^T)  [512][512]

// ---------------------------------------------------------------------------
// mma.sync helpers (sm_80-era PTX, legal on compute_103)
// ---------------------------------------------------------------------------
__device__ __forceinline__ uint32_t smem_to_u32(const void* p) {
    uint32_t a;
    asm("{ .reg .u64 t; cvta.to.shared.u64 t, %1; cvt.u32.u64 %0, t; }" : "=r"(a) : "l"(p));
    return a;
}
__device__ __forceinline__ void ldsm4(uint32_t* r, uint32_t addr) {
    asm volatile("ldmatrix.sync.aligned.m8n8.x4.shared.b16 {%0,%1,%2,%3}, [%4];"
        : "=r"(r[0]), "=r"(r[1]), "=r"(r[2]), "=r"(r[3]) : "r"(addr));
}
__device__ __forceinline__ void ldsm4t(uint32_t* r, uint32_t addr) {
    asm volatile("ldmatrix.sync.aligned.m8n8.x4.trans.shared.b16 {%0,%1,%2,%3}, [%4];"
        : "=r"(r[0]), "=r"(r[1]), "=r"(r[2]), "=r"(r[3]) : "r"(addr));
}
// fp16 MMA (GEMMs + attention)
__device__ __forceinline__ void mma16816h(float* c, const uint32_t* a, const uint32_t* b) {
    asm volatile("mma.sync.aligned.m16n8k16.row.col.f32.f16.f16.f32 "
        "{%0,%1,%2,%3}, {%4,%5,%6,%7}, {%8,%9}, {%0,%1,%2,%3};"
        : "+f"(c[0]), "+f"(c[1]), "+f"(c[2]), "+f"(c[3])
        : "r"(a[0]), "r"(a[1]), "r"(a[2]), "r"(a[3]), "r"(b[0]), "r"(b[1]));
}
__device__ __forceinline__ void cp16(uint32_t s, const void* g) {
    asm volatile("cp.async.cg.shared.global [%0], [%1], 16;" :: "r"(s), "l"(g));
}
#define CP_COMMIT() asm volatile("cp.async.commit_group;")
#define CP_WAIT(N)  asm volatile("cp.async.wait_group %0;" :: "n"(N))

__device__ __forceinline__ uint32_t packh_hi(float a, float b) {
    __half2 t = __floats2half2_rn(a, b);
    return *(uint32_t*)&t;
}
__device__ __forceinline__ uint32_t packh_lo(float a, float b, uint32_t hi) {
    __half2 h = *(__half2*)&hi;
    __half2 t = __floats2half2_rn(a - __half2float(h.x), b - __half2float(h.y));
    return *(uint32_t*)&t;
}

// ---------------------------------------------------------------------------
// Block reduction (256 threads)
// ---------------------------------------------------------------------------
__device__ __forceinline__ float blk_reduce_sum(float v, float* sm) {
    int tid = threadIdx.x;
    #pragma unroll
    for (int o = 16; o > 0; o >>= 1) v += __shfl_down_sync(0xffffffffu, v, o);
    if ((tid & 31) == 0) sm[tid >> 5] = v;
    __syncthreads();
    if (tid < 32) {
        float t = (tid < 8) ? sm[tid] : 0.0f;
        #pragma unroll
        for (int o = 4; o > 0; o >>= 1) t += __shfl_down_sync(0xffffffffu, t, o);
        if (tid == 0) sm[0] = t;
    }
    __syncthreads();
    float r = sm[0];
    __syncthreads();
    return r;
}

__device__ __forceinline__ void split_write_h(__half* ph, __half* pl,
                                              size_t idx, float v) {
    __half h = __float2half_rn(v);
    ph[idx] = h;
    pl[idx] = __float2half_rn(v - __half2float(h));
}

// ---------------------------------------------------------------------------
// tsplit body (transpose + fp16 round): in[K][N] fp32 -> out[N][K] fp16
// ---------------------------------------------------------------------------
__device__ __forceinline__ void tsplit_body(const float* __restrict__ in,
                                            __half* __restrict__ outp,
                                            int K, int N, int bx, int by,
                                            float (*tile)[33]) {
    int tid = threadIdx.x;
    int tx = tid & 31, ty = tid >> 5;
    int n0 = bx * 32, k0 = by * 32;
    #pragma unroll
    for (int i = 0; i < 4; i++)
        tile[ty + i*8][tx] = in[(size_t)(k0 + ty + i*8) * N + n0 + tx];
    __syncthreads();
    #pragma unroll
    for (int i = 0; i < 4; i++) {
        float v = tile[tx][ty + i*8];
        outp[(size_t)(n0 + ty + i*8) * K + k0 + tx] = __float2half_rn(v);
    }
}

// ---------------------------------------------------------------------------
// prep_core (stream 0):  [0,4096): ln_x (fp16 hi/lo)  [4096,5120): tsplit uvqk
// ---------------------------------------------------------------------------
__global__ void prep_core_kernel(const float* __restrict__ x,
                                 const float* __restrict__ lnw,
                                 const float* __restrict__ lnb,
                                 const float* __restrict__ uvqk) {
    __shared__ float sm[8];
    __shared__ float tile[32][33];
    int bid = blockIdx.x, tid = threadIdx.x;
    if (bid < 4096) {
        int r = bid;
        const float* xr = x + (size_t)r * DMODEL;
        float v0 = xr[tid], v1 = xr[tid + 256];
        float mean = blk_reduce_sum(v0 + v1, sm) * (1.0f / DMODEL);
        float d0 = v0 - mean, d1 = v1 - mean;
        float var = blk_reduce_sum(d0*d0 + d1*d1, sm) * (1.0f / DMODEL);
        float inv = rsqrtf(var + 1e-5f);
        split_write_h(g_nxh, g_nxl, (size_t)r*DMODEL + tid,       d0*inv*lnw[tid]       + lnb[tid]);
        split_write_h(g_nxh, g_nxl, (size_t)r*DMODEL + tid + 256, d1*inv*lnw[tid + 256] + lnb[tid + 256]);
    } else {
        int t = bid - 4096;
        tsplit_body(uvqk, g_B1, DMODEL, EOUT, t & 63, t >> 6, tile);
    }
}

// ---------------------------------------------------------------------------
// prep_aux (stream B):  [0,4096): bias   [4096,4352): tsplit o_w
// ---------------------------------------------------------------------------
__global__ void prep_aux_kernel(const float* __restrict__ o_w,
                                const int*   __restrict__ ts,
                                const float* __restrict__ tw,
                                const float* __restrict__ pw) {
    __shared__ float tile[32][33];
    int bid = blockIdx.x, tid = threadIdx.x;
    if (bid < 4096) {
        int b = bid >> 10, i = bid & 1023;
        int j = tid * 4;
        int ip = i + 1; if (ip > NSEQ - 1) ip = NSEQ - 1;
        int tl = ts[(b << 10) + ip];
        int4 tj = *(const int4*)&ts[(b << 10) + j];
        float4 o;
        {
            int d = tl - tj.x; if (d < 0) d = -d; if (d < 1) d = 1;
            int bk = (int)(__logf((float)d) * 3.3222591f);
            bk = min(max(bk, 0), 64);
            o.x = pw[j - i + NSEQ - 1] + tw[bk];
        }
        {
            int d = tl - tj.y; if (d < 0) d = -d; if (d < 1) d = 1;
            int bk = (int)(__logf((float)d) * 3.3222591f);
            bk = min(max(bk, 0), 64);
            o.y = pw[j + 1 - i + NSEQ - 1] + tw[bk];
        }
        {
            int d = tl - tj.z; if (d < 0) d = -d; if (d < 1) d = 1;
            int bk = (int)(__logf((float)d) * 3.3222591f);
            bk = min(max(bk, 0), 64);
            o.z = pw[j + 2 - i + NSEQ - 1] + tw[bk];
        }
        {
            int d = tl - tj.w; if (d < 0) d = -d; if (d < 1) d = 1;
            int bk = (int)(__logf((float)d) * 3.3222591f);
            bk = min(max(bk, 0), 64);
            o.w = pw[j + 3 - i + NSEQ - 1] + tw[bk];
        }
        *(float4*)&g_bias[((size_t)(b << 10) + i) * NSEQ + j] = o;
    } else {
        int t = bid - 4096;
        tsplit_body(o_w, g_B2, DMODEL, DMODEL, t & 15, t >> 4, tile);
    }
}

// ---------------------------------------------------------------------------
// Kernel 4: t = u * LayerNorm(ao0 [+ ao1])  -> g_th/g_tl   grid=4096, block=256
// ---------------------------------------------------------------------------
__global__ void ln_a_kernel(const float* __restrict__ w,
                            const float* __restrict__ b) {
    __shared__ float sm[8];
    int r = blockIdx.x, tid = threadIdx.x;
    const bool two = (r & 1023) >= 512;
    size_t base = (size_t)r * DMODEL;
    float v0 = g_ao0[base + tid], v1 = g_ao0[base + tid + 256];
    if (two) { v0 += g_ao1[base + tid]; v1 += g_ao1[base + tid + 256]; }
    float mean = blk_reduce_sum(v0 + v1, sm) * (1.0f / DMODEL);
    float d0 = v0 - mean, d1 = v1 - mean;
    float var = blk_reduce_sum(d0*d0 + d1*d1, sm) * (1.0f / DMODEL);
    float inv = rsqrtf(var + 1e-5f);
    size_t ub = (size_t)r * EOUT;
    float u0 = __half2float(g_uoh[ub + tid])       + __half2float(g_uol[ub + tid]);
    float u1 = __half2float(g_uoh[ub + tid + 256]) + __half2float(g_uol[ub + tid + 256]);
    split_write_h(g_th, g_tl, base + tid,       (d0*inv*w[tid]       + b[tid])       * u0);
    split_write_h(g_th, g_tl, base + tid + 256, (d1*inv*w[tid + 256] + b[tid + 256]) * u1);
}

// ---------------------------------------------------------------------------
// fp16 2-term GEMM (HMMA): C = (Ah+Al) @ B^T, A exact fp16 split, B fp16.
// CTA 128x128, 8 warps (2m x 4n, 64x32 warp tile), K chunks of 32,
// 2-stage cp.async pipeline (3 tiles/stage = 61.4 KB), 2 CTAs/SM.
// EPI 0: silu -> fp16 hi/lo.  EPI 1: fp32 +bias+resid, pm mask.
// ---------------------------------------------------------------------------
#define KSEG   512
#define KCH    32
#define NCH    (KSEG/KCH)            // 16
#define TPAD   40                    // 32 + 8 elems -> 80B row stride
#define TBYTES (128*TPAD*2)          // 10240 B per tile
#define STAGE3 (3*TBYTES)            // Ah,Al,B per stage
#define SMEM_GEMM (2*STAGE3)         // 61440 B

template<int EPI>
__global__ void __launch_bounds__(256, 2)
mma_gemm(const __half* __restrict__ Ah, const __half* __restrict__ Al,
         const __half* __restrict__ B,
         float* __restrict__ C,
         __half* __restrict__ Ch, __half* __restrict__ Cl, int N,
         const float* __restrict__ bias, const float* __restrict__ resid,
         const unsigned char* __restrict__ pm) {
    const int tid = threadIdx.x, wid = tid >> 5, lane = tid & 31;
    const int bm = blockIdx.y * 128, bn = blockIdx.x * 128;
    const int wm = wid & 1, wn = wid >> 1;     // warp tile (wm*64, wn*32)

    const uint32_t sbase = smem_to_u32(dynsmem);
    const int lrow = lane & 15, lcol = (lane >> 4) * 8;
    const int crow = tid >> 2, ccol = (tid & 3) * 8;

    float acc[4][4][4];
    #pragma unroll
    for (int i = 0; i < 4; i++)
        #pragma unroll
        for (int j = 0; j < 4; j++)
            #pragma unroll
            for (int k = 0; k < 4; k++) acc[i][j][k] = 0.0f;

    auto issue = [&](int c, int stg) {
        const int kc = c * KCH;
        const uint32_t st = sbase + stg * STAGE3;
        #pragma unroll
        for (int i = 0; i < 2; i++) {
            int row = crow + i*64;
            uint32_t so = (row*TPAD + ccol)*2;
            cp16(st + 0*TBYTES + so, Ah + (size_t)(bm + row)*KSEG + kc + ccol);
            cp16(st + 1*TBYTES + so, Al + (size_t)(bm + row)*KSEG + kc + ccol);
            cp16(st + 2*TBYTES + so, B  + (size_t)(bn + row)*KSEG + kc + ccol);
        }
        CP_COMMIT();
    };

    issue(0, 0);
    for (int c = 0; c < NCH; c++) {
        if (c + 1 < NCH) { issue(c + 1, (c + 1) & 1); CP_WAIT(1); }
        else             { CP_WAIT(0); }
        __syncthreads();
        const uint32_t st = sbase + (c & 1) * STAGE3;
        const uint32_t sah = st, sal = st + TBYTES, sb = st + 2*TBYTES;
        #pragma unroll
        for (int ks = 0; ks < 2; ks++) {
            const int ko = ks * 16;
            uint32_t afh[4][4], afl[4][4], bf[2][4];
            #pragma unroll
            for (int fm = 0; fm < 4; fm++)
                ldsm4(afh[fm], sah + ((wm*64 + fm*16 + lrow)*TPAD + ko + lcol)*2);
            #pragma unroll
            for (int g = 0; g < 2; g++)
                ldsm4(bf[g], sb + ((wn*32 + g*16 + lrow)*TPAD + ko + lcol)*2);
            // term 1: Ah * B
            #pragma unroll
            for (int fm = 0; fm < 4; fm++)
                #pragma unroll
                for (int fn = 0; fn < 4; fn++) {
                    uint32_t bb[2] = { bf[fn >> 1][(fn & 1) + 0],
                                       bf[fn >> 1][(fn & 1) + 2] };
                    mma16816h(acc[fm][fn], afh[fm], bb);
                }
            // term 2: Al * B
            #pragma unroll
            for (int fm = 0; fm < 4; fm++)
                ldsm4(afl[fm], sal + ((wm*64 + fm*16 + lrow)*TPAD + ko + lcol)*2);
            #pragma unroll
            for (int fm = 0; fm < 4; fm++)
                #pragma unroll
                for (int fn = 0; fn < 4; fn++) {
                    uint32_t bb[2] = { bf[fn >> 1][(fn & 1) + 0],
                                       bf[fn >> 1][(fn & 1) + 2] };
                    mma16816h(acc[fm][fn], afl[fm], bb);
                }
        }
        __syncthreads();
    }

    #pragma unroll
    for (int fm = 0; fm < 4; fm++) {
        #pragma unroll
        for (int half = 0; half < 2; half++) {
            int r = bm + wm*64 + fm*16 + (lane >> 2) + half*8;
            #pragma unroll
            for (int fn = 0; fn < 4; fn++) {
                int cc = bn + wn*32 + fn*8 + (lane & 3)*2;
                float vx = acc[fm][fn][half*2 + 0];
                float vy = acc[fm][fn][half*2 + 1];
                if (EPI == 0) {
                    vx = vx / (1.0f + __expf(-vx));
                    vy = vy / (1.0f + __expf(-vy));
                    uint32_t hi = packh_hi(vx, vy);
                    uint32_t lo = packh_lo(vx, vy, hi);
                    *(uint32_t*)&Ch[(size_t)r*N + cc] = hi;
                    *(uint32_t*)&Cl[(size_t)r*N + cc] = lo;
                } else {
                    vx += bias[cc]     + resid[(size_t)r*N + cc];
                    vy += bias[cc + 1] + resid[(size_t)r*N + cc + 1];
                    if (pm[r]) { vx = 0.0f; vy = 0.0f; }
                    float2 v = {vx, vy};
                    *(float2*)&C[(size_t)r*N + cc] = v;
                }
            }
        }
    }
}

// ---------------------------------------------------------------------------
// Kernel 3: causal silu-attention, fp16 2-term MMA, precomputed bias,
// pipelined K/V loads.  (R15-proven, unchanged)
// ---------------------------------------------------------------------------
#define ATPAD 72
#define ATILE (64*ATPAD*2)           // 9216 B per fp16 tile
#define ATT_QH 0
#define ATT_KH (1*ATILE)
#define ATT_KL (2*ATILE)
#define ATT_VH (3*ATILE)
#define ATT_VL (4*ATILE)
#define ATT_PM (5*ATILE)             // pmj[2][64]
#define SMEM_ATTN (ATT_PM + 2*64*4)

__global__ void __launch_bounds__(128)
attn_kernel(const unsigned char* __restrict__ pm) {
    unsigned char* sm = dynsmem;
    int* pmj = (int*)(sm + ATT_PM);

    const int bh = blockIdx.x, b = bh >> 3, h = bh & 7;
    const int wy = blockIdx.y;
    int it, jlo, jhi, dst;
    if (wy < 16) {
        it = 15 - (wy >> 1);
        int m = (it + 2) >> 1;
        if (wy & 1) { jlo = m; jhi = it + 1; dst = 1; }
        else        { jlo = 0; jhi = m;      dst = 0; }
    } else {
        it = 23 - wy; jlo = 0; jhi = it + 1; dst = 0;
    }
    const int i0 = it * 64;
    const int tid = threadIdx.x, wq = tid >> 5, lane = tid & 31;
    const int lrow = lane & 15, lcol = (lane >> 4) * 8;

    const uint32_t sqh = smem_to_u32(sm);
    const uint32_t skh = sqh + ATT_KH, skl = sqh + ATT_KL;
    const uint32_t svh = sqh + ATT_VH, svl = sqh + ATT_VL;

    auto issue_k = [&](int jt, int slot) {
        const int j0 = jt * 64;
        #pragma unroll
        for (int i = 0; i < 4; i++) {
            int id = i*128 + tid, row = id >> 3, col = (id & 7) * 8;
            size_t bkv = (size_t)(b*NSEQ + j0 + row)*EOUT + h*64 + col;
            uint32_t so = (row*ATPAD + col)*2;
            cp16(skh + so, &g_uoh[bkv + 1536]);
            cp16(skl + so, &g_uol[bkv + 1536]);
        }
        if (tid < 64) pmj[slot*64 + tid] = pm[b*NSEQ + j0 + tid];
        CP_COMMIT();
    };
    auto issue_v = [&](int jt) {
        const int j0 = jt * 64;
        #pragma unroll
        for (int i = 0; i < 4; i++) {
            int id = i*128 + tid, row = id >> 3, col = (id & 7) * 8;
            size_t bkv = (size_t)(b*NSEQ + j0 + row)*EOUT + h*64 + col;
            uint32_t so = (row*ATPAD + col)*2;
            cp16(svh + so, &g_uoh[bkv + 512]);
            cp16(svl + so, &g_uol[bkv + 512]);
        }
        CP_COMMIT();
    };

    // Q tile (hi only; cols 1024 + h*64)
    #pragma unroll
    for (int i = 0; i < 4; i++) {
        int id = i*128 + tid, row = id >> 3, col = (id & 7) * 8;
        size_t src = (size_t)(b*NSEQ + i0 + row)*EOUT + 1024 + h*64 + col;
        cp16(sqh + (row*ATPAD + col)*2, &g_uoh[src]);
    }
    CP_COMMIT(); CP_WAIT(0);
    __syncthreads();

    issue_k(jlo, 0);
    issue_v(jlo);

    float of[8][4];
    #pragma unroll
    for (int f = 0; f < 8; f++)
        #pragma unroll
        for (int r = 0; r < 4; r++) of[f][r] = 0.0f;

    const int row_lo = wq*16 + (lane >> 2);
    const int col_in = (lane & 3) * 2;

    for (int jt = jlo; jt < jhi; jt++) {
        const int j0 = jt * 64;
        const int slot = (jt - jlo) & 1;
        CP_WAIT(1);
        __syncthreads();

        // ---- Phase A: S = Qh (Kh + Kl) ----
        float sc[8][4];
        #pragma unroll
        for (int f = 0; f < 8; f++)
            #pragma unroll
            for (int r = 0; r < 4; r++) sc[f][r] = 0.0f;

        #pragma unroll
        for (int ks = 0; ks < 4; ks++) {
            uint32_t aq[4], kh[4][4], kl[4][4];
            ldsm4(aq, sqh + ((wq*16 + lrow)*ATPAD + ks*16 + lcol)*2);
            #pragma unroll
            for (int g = 0; g < 4; g++) {
                ldsm4(kh[g], skh + ((g*16 + lrow)*ATPAD + ks*16 + lcol)*2);
                ldsm4(kl[g], skl + ((g*16 + lrow)*ATPAD + ks*16 + lcol)*2);
            }
            #pragma unroll
            for (int fn = 0; fn < 8; fn++) {
                uint32_t bh_[2] = { kh[fn >> 1][(fn & 1) + 0], kh[fn >> 1][(fn & 1) + 2] };
                uint32_t bl_[2] = { kl[fn >> 1][(fn & 1) + 0], kl[fn >> 1][(fn & 1) + 2] };
                mma16816h(sc[fn], aq, bh_);
                mma16816h(sc[fn], aq, bl_);
            }
        }
        __syncthreads();
        if (jt + 1 < jhi) issue_k(jt + 1, slot ^ 1);

        // ---- Epilogue: +bias (precomputed), silu/N, mask ----
        const int* pms = pmj + slot*64;
        #pragma unroll
        for (int f = 0; f < 8; f++) {
            int jb = j0 + f*8 + col_in;
            float2 b0 = *(const float2*)&g_bias[((size_t)(b << 10) + i0 + row_lo)     * NSEQ + jb];
            float2 b1 = *(const float2*)&g_bias[((size_t)(b << 10) + i0 + row_lo + 8) * NSEQ + jb];
            #pragma unroll
            for (int r = 0; r < 4; r++) {
                int il = row_lo + ((r >> 1) ? 8 : 0);
                int jl = f*8 + col_in + (r & 1);
                int ig = i0 + il, jg = j0 + jl;
                float bb = (r < 2) ? ((r & 1) ? b0.y : b0.x) : ((r & 1) ? b1.y : b1.x);
                float s = sc[f][r] + bb;
                s = s / (1.0f + __expf(-s)) * (1.0f / NSEQ);
                if (jg > ig || pms[jl]) s = 0.0f;
                sc[f][r] = s;
            }
        }

        if (jt + 1 < jhi) { CP_WAIT(1); } else { CP_WAIT(0); }
        __syncthreads();

        // ---- Phase B: O += Sh (Vh + Vl) ----
        #pragma unroll
        for (int ks = 0; ks < 4; ks++) {
            uint32_t ah[4];
            ah[0] = packh_hi(sc[2*ks][0],   sc[2*ks][1]);
            ah[1] = packh_hi(sc[2*ks][2],   sc[2*ks][3]);
            ah[2] = packh_hi(sc[2*ks+1][0], sc[2*ks+1][1]);
            ah[3] = packh_hi(sc[2*ks+1][2], sc[2*ks+1][3]);
            uint32_t voff = ((ks*16 + ((lane >> 3) & 1)*8 + (lane & 7))*ATPAD
                            + (lane >> 4)*8) * 2;
            #pragma unroll
            for (int dg = 0; dg < 4; dg++) {
                uint32_t vh[4], vl[4];
                ldsm4t(vh, svh + voff + dg*16*2);
                ldsm4t(vl, svl + voff + dg*16*2);
                #pragma unroll
                for (int half = 0; half < 2; half++) {
                    int fd = dg*2 + half;
                    uint32_t bh_[2] = { vh[half*2], vh[half*2 + 1] };
                    uint32_t bl_[2] = { vl[half*2], vl[half*2 + 1] };
                    mma16816h(of[fd], ah, bh_);
                    mma16816h(of[fd], ah, bl_);
                }
            }
        }
        __syncthreads();
        if (jt + 1 < jhi) issue_v(jt + 1);
    }

    // ---- write O partial ----
    float* aop = dst ? g_ao1 : g_ao0;
    #pragma unroll
    for (int fd = 0; fd < 8; fd++) {
        #pragma unroll
        for (int half = 0; half < 2; half++) {
            int row = i0 + row_lo + half*8;
            int col = h*64 + fd*8 + col_in;
            float2 v = { of[fd][half*2], of[fd][half*2 + 1] };
            *(float2*)&aop[(size_t)(b*NSEQ + row)*DMODEL + col] = v;
        }
    }
}

// ---------------------------------------------------------------------------
// Launch — two-stream schedule (R13-proven):
//   stream 0:  prep_core -> gemm_vqk -> [wait aux] attn -> [wait u] ln_a -> gemm1
//   stream B:  prep_aux -> [wait core] gemm_u
// ---------------------------------------------------------------------------
extern "C" void kernel_launch(void* const* d_in, const int* in_sizes, int n_in,
                              void* d_out, int out_size) {
    const float*          x      = (const float*)d_in[0];
    const int*            ts     = (const int*)d_in[1];     // int32 (JAX x64 off)
    /* d_in[2] = cm — analytic triu(k=1), unused */
    const unsigned char*  pm     = (const unsigned char*)d_in[3];
    const float*          uvqk   = (const float*)d_in[4];
    const float*          o_w    = (const float*)d_in[5];
    const float*          o_b    = (const float*)d_in[6];
    const float*          ln_x_w = (const float*)d_in[7];
    const float*          ln_x_b = (const float*)d_in[8];
    const float*          ln_a_w = (const float*)d_in[9];
    const float*          ln_a_b = (const float*)d_in[10];
    const float*          ts_w   = (const float*)d_in[11];
    const float*          pos_w  = (const float*)d_in[12];
    float*                out    = (float*)d_out;

    __half *p_uoh, *p_uol, *p_nxh, *p_nxl, *p_th, *p_tl, *p_B1, *p_B2;
    cudaGetSymbolAddress((void**)&p_uoh, g_uoh);
    cudaGetSymbolAddress((void**)&p_uol, g_uol);
    cudaGetSymbolAddress((void**)&p_nxh, g_nxh);
    cudaGetSymbolAddress((void**)&p_nxl, g_nxl);
    cudaGetSymbolAddress((void**)&p_th,  g_th);
    cudaGetSymbolAddress((void**)&p_tl,  g_tl);
    cudaGetSymbolAddress((void**)&p_B1,  g_B1);
    cudaGetSymbolAddress((void**)&p_B2,  g_B2);

    cudaFuncSetAttribute(mma_gemm<0>, cudaFuncAttributeMaxDynamicSharedMemorySize, SMEM_GEMM);
    cudaFuncSetAttribute(mma_gemm<1>, cudaFuncAttributeMaxDynamicSharedMemorySize, SMEM_GEMM);
    cudaFuncSetAttribute(attn_kernel, cudaFuncAttributeMaxDynamicSharedMemorySize, SMEM_ATTN);

    static cudaStream_t sB = nullptr;
    static cudaEvent_t evStart, evAux, evCore, evU;
    if (sB == nullptr) {
        cudaStreamCreateWithFlags(&sB, cudaStreamNonBlocking);
        cudaEventCreateWithFlags(&evStart, cudaEventDisableTiming);
        cudaEventCreateWithFlags(&evAux,   cudaEventDisableTiming);
        cudaEventCreateWithFlags(&evCore,  cudaEventDisableTiming);
        cudaEventCreateWithFlags(&evU,     cudaEventDisableTiming);
    }

    cudaEventRecord(evStart, 0);
    cudaStreamWaitEvent(sB, evStart, 0);

    // stream B: bias + tsplit(o_w)
    prep_aux_kernel<<<4352, 256, 0, sB>>>(o_w, ts, ts_w, pos_w);
    cudaEventRecord(evAux, sB);

    // stream 0: ln_x + tsplit(uvqk)
    prep_core_kernel<<<5120, 256>>>(x, ln_x_w, ln_x_b, uvqk);
    cudaEventRecord(evCore, 0);

    // stream 0: vqk GEMM (cols 512..2048) + silu -> fp16 hi/lo
    mma_gemm<0><<<dim3(12, ROWS/128), 256, SMEM_GEMM>>>(
        p_nxh, p_nxl, p_B1 + (size_t)512*KSEG,
        nullptr, p_uoh + 512, p_uol + 512, EOUT, nullptr, nullptr, nullptr);

    // stream B: u GEMM (cols 0..512) after prep_core
    cudaStreamWaitEvent(sB, evCore, 0);
    mma_gemm<0><<<dim3(4, ROWS/128), 256, SMEM_GEMM, sB>>>(
        p_nxh, p_nxl, p_B1,
        nullptr, p_uoh, p_uol, EOUT, nullptr, nullptr, nullptr);
    cudaEventRecord(evU, sB);

    // stream 0: attention (needs vqk + bias)
    cudaStreamWaitEvent(0, evAux, 0);
    attn_kernel<<<dim3(NB*NH, 24), 128, SMEM_ATTN>>>(pm);

    // stream 0: ln_a (needs attention + u)
    cudaStreamWaitEvent(0, evU, 0);
    ln_a_kernel<<<ROWS, 256>>>(ln_a_w, ln_a_b);

    // stream 0: final GEMM (needs ln_a + tsplit o_w, joined via evAux above)
    mma_gemm<1><<<dim3(DMODEL/128, ROWS/128), 256, SMEM_GEMM>>>(
        p_th, p_tl, p_B2,
        out, nullptr, nullptr, DMODEL, o_b, x, pm);
}

// round 17
// speedup vs baseline: 1.5867x; 1.0376x over previous
#include <cuda_runtime.h>
#include <cuda_bf16.h>
#include <cuda_fp16.h>
#include <cstdint>
#include <math.h>

// Problem constants
#define NB     4
#define NSEQ   1024
#define DMODEL 512
#define NH     8
#define HD     64
#define EOUT   2048          // 2*H*Dv + 2*H*Dq
#define ROWS   (NB*NSEQ)     // 4096

// Single dynamic-smem symbol (typed via casts in each kernel)
extern __shared__ __align__(128) unsigned char dynsmem[];

// ---------------------------------------------------------------------------
// Scratch (allocation-free -> __device__ globals)
// ---------------------------------------------------------------------------
__device__ float g_ao0[ROWS*DMODEL];  // attention output (split 0)
__device__ float g_ao1[ROWS*DMODEL];  // attention output (split 1, rows i>=512)
__device__ float g_bias[(size_t)NB*NSEQ*NSEQ];                    // rel-bias, head-invariant
__device__ __half g_uoh[ROWS*EOUT], g_uol[ROWS*EOUT];             // silu(nx@uvqk) fp16 hi(/lo: u only)
__device__ __half g_nxh[ROWS*DMODEL], g_nxl[ROWS*DMODEL];         // LN(x) fp16 hi/lo
__device__ __half g_th [ROWS*DMODEL], g_tl [ROWS*DMODEL];         // u*LN(ao) fp16 hi/lo
__device__ __half g_B1[EOUT*DMODEL];                              // fl16(uvqk^T) [2048][512]
__device__ __half g_B2[DMODEL*DMODEL];                            // fl16(o_w^T)  [512][512]

// ---------------------------------------------------------------------------
// mma.sync helpers (sm_80-era PTX, legal on compute_103)
// ---------------------------------------------------------------------------
__device__ __forceinline__ uint32_t smem_to_u32(const void* p) {
    uint32_t a;
    asm("{ .reg .u64 t; cvta.to.shared.u64 t, %1; cvt.u32.u64 %0, t; }" : "=r"(a) : "l"(p));
    return a;
}
__device__ __forceinline__ void ldsm4(uint32_t* r, uint32_t addr) {
    asm volatile("ldmatrix.sync.aligned.m8n8.x4.shared.b16 {%0,%1,%2,%3}, [%4];"
        : "=r"(r[0]), "=r"(r[1]), "=r"(r[2]), "=r"(r[3]) : "r"(addr));
}
__device__ __forceinline__ void ldsm4t(uint32_t* r, uint32_t addr) {
    asm volatile("ldmatrix.sync.aligned.m8n8.x4.trans.shared.b16 {%0,%1,%2,%3}, [%4];"
        : "=r"(r[0]), "=r"(r[1]), "=r"(r[2]), "=r"(r[3]) : "r"(addr));
}
__device__ __forceinline__ void mma16816h(float* c, const uint32_t* a, const uint32_t* b) {
    asm volatile("mma.sync.aligned.m16n8k16.row.col.f32.f16.f16.f32 "
        "{%0,%1,%2,%3}, {%4,%5,%6,%7}, {%8,%9}, {%0,%1,%2,%3};"
        : "+f"(c[0]), "+f"(c[1]), "+f"(c[2]), "+f"(c[3])
        : "r"(a[0]), "r"(a[1]), "r"(a[2]), "r"(a[3]), "r"(b[0]), "r"(b[1]));
}
__device__ __forceinline__ void cp16(uint32_t s, const void* g) {
    asm volatile("cp.async.cg.shared.global [%0], [%1], 16;" :: "r"(s), "l"(g));
}
#define CP_COMMIT() asm volatile("cp.async.commit_group;")
#define CP_WAIT(N)  asm volatile("cp.async.wait_group %0;" :: "n"(N))

__device__ __forceinline__ uint32_t packh_hi(float a, float b) {
    __half2 t = __floats2half2_rn(a, b);
    return *(uint32_t*)&t;
}
__device__ __forceinline__ uint32_t packh_lo(float a, float b, uint32_t hi) {
    __half2 h = *(__half2*)&hi;
    __half2 t = __floats2half2_rn(a - __half2float(h.x), b - __half2float(h.y));
    return *(uint32_t*)&t;
}

// ---------------------------------------------------------------------------
// Block reduction (256 threads)
// ---------------------------------------------------------------------------
__device__ __forceinline__ float blk_reduce_sum(float v, float* sm) {
    int tid = threadIdx.x;
    #pragma unroll
    for (int o = 16; o > 0; o >>= 1) v += __shfl_down_sync(0xffffffffu, v, o);
    if ((tid & 31) == 0) sm[tid >> 5] = v;
    __syncthreads();
    if (tid < 32) {
        float t = (tid < 8) ? sm[tid] : 0.0f;
        #pragma unroll
        for (int o = 4; o > 0; o >>= 1) t += __shfl_down_sync(0xffffffffu, t, o);
        if (tid == 0) sm[0] = t;
    }
    __syncthreads();
    float r = sm[0];
    __syncthreads();
    return r;
}

__device__ __forceinline__ void split_write_h(__half* ph, __half* pl,
                                              size_t idx, float v) {
    __half h = __float2half_rn(v);
    ph[idx] = h;
    pl[idx] = __float2half_rn(v - __half2float(h));
}

// ---------------------------------------------------------------------------
// tsplit body (transpose + fp16 round): in[K][N] fp32 -> out[N][K] fp16
// ---------------------------------------------------------------------------
__device__ __forceinline__ void tsplit_body(const float* __restrict__ in,
                                            __half* __restrict__ outp,
                                            int K, int N, int bx, int by,
                                            float (*tile)[33]) {
    int tid = threadIdx.x;
    int tx = tid & 31, ty = tid >> 5;
    int n0 = bx * 32, k0 = by * 32;
    #pragma unroll
    for (int i = 0; i < 4; i++)
        tile[ty + i*8][tx] = in[(size_t)(k0 + ty + i*8) * N + n0 + tx];
    __syncthreads();
    #pragma unroll
    for (int i = 0; i < 4; i++) {
        float v = tile[tx][ty + i*8];
        outp[(size_t)(n0 + ty + i*8) * K + k0 + tx] = __float2half_rn(v);
    }
}

// ---------------------------------------------------------------------------
// prep_core (stream 0):  [0,4096): ln_x (fp16 hi/lo)  [4096,5120): tsplit uvqk
// ---------------------------------------------------------------------------
__global__ void prep_core_kernel(const float* __restrict__ x,
                                 const float* __restrict__ lnw,
                                 const float* __restrict__ lnb,
                                 const float* __restrict__ uvqk) {
    __shared__ float sm[8];
    __shared__ float tile[32][33];
    int bid = blockIdx.x, tid = threadIdx.x;
    if (bid < 4096) {
        int r = bid;
        const float* xr = x + (size_t)r * DMODEL;
        float v0 = xr[tid], v1 = xr[tid + 256];
        float mean = blk_reduce_sum(v0 + v1, sm) * (1.0f / DMODEL);
        float d0 = v0 - mean, d1 = v1 - mean;
        float var = blk_reduce_sum(d0*d0 + d1*d1, sm) * (1.0f / DMODEL);
        float inv = rsqrtf(var + 1e-5f);
        split_write_h(g_nxh, g_nxl, (size_t)r*DMODEL + tid,       d0*inv*lnw[tid]       + lnb[tid]);
        split_write_h(g_nxh, g_nxl, (size_t)r*DMODEL + tid + 256, d1*inv*lnw[tid + 256] + lnb[tid + 256]);
    } else {
        int t = bid - 4096;
        tsplit_body(uvqk, g_B1, DMODEL, EOUT, t & 63, t >> 6, tile);
    }
}

// ---------------------------------------------------------------------------
// prep_aux (stream B):  [0,4096): bias   [4096,4352): tsplit o_w
// ---------------------------------------------------------------------------
__global__ void prep_aux_kernel(const float* __restrict__ o_w,
                                const int*   __restrict__ ts,
                                const float* __restrict__ tw,
                                const float* __restrict__ pw) {
    __shared__ float tile[32][33];
    int bid = blockIdx.x, tid = threadIdx.x;
    if (bid < 4096) {
        int b = bid >> 10, i = bid & 1023;
        int j = tid * 4;
        int ip = i + 1; if (ip > NSEQ - 1) ip = NSEQ - 1;
        int tl = ts[(b << 10) + ip];
        int4 tj = *(const int4*)&ts[(b << 10) + j];
        float4 o;
        {
            int d = tl - tj.x; if (d < 0) d = -d; if (d < 1) d = 1;
            int bk = (int)(__logf((float)d) * 3.3222591f);
            bk = min(max(bk, 0), 64);
            o.x = pw[j - i + NSEQ - 1] + tw[bk];
        }
        {
            int d = tl - tj.y; if (d < 0) d = -d; if (d < 1) d = 1;
            int bk = (int)(__logf((float)d) * 3.3222591f);
            bk = min(max(bk, 0), 64);
            o.y = pw[j + 1 - i + NSEQ - 1] + tw[bk];
        }
        {
            int d = tl - tj.z; if (d < 0) d = -d; if (d < 1) d = 1;
            int bk = (int)(__logf((float)d) * 3.3222591f);
            bk = min(max(bk, 0), 64);
            o.z = pw[j + 2 - i + NSEQ - 1] + tw[bk];
        }
        {
            int d = tl - tj.w; if (d < 0) d = -d; if (d < 1) d = 1;
            int bk = (int)(__logf((float)d) * 3.3222591f);
            bk = min(max(bk, 0), 64);
            o.w = pw[j + 3 - i + NSEQ - 1] + tw[bk];
        }
        *(float4*)&g_bias[((size_t)(b << 10) + i) * NSEQ + j] = o;
    } else {
        int t = bid - 4096;
        tsplit_body(o_w, g_B2, DMODEL, DMODEL, t & 15, t >> 4, tile);
    }
}

// ---------------------------------------------------------------------------
// Kernel 4: t = u * LayerNorm(ao0 [+ ao1])  -> g_th/g_tl   grid=4096, block=256
// ---------------------------------------------------------------------------
__global__ void ln_a_kernel(const float* __restrict__ w,
                            const float* __restrict__ b) {
    __shared__ float sm[8];
    int r = blockIdx.x, tid = threadIdx.x;
    const bool two = (r & 1023) >= 512;
    size_t base = (size_t)r * DMODEL;
    float v0 = g_ao0[base + tid], v1 = g_ao0[base + tid + 256];
    if (two) { v0 += g_ao1[base + tid]; v1 += g_ao1[base + tid + 256]; }
    float mean = blk_reduce_sum(v0 + v1, sm) * (1.0f / DMODEL);
    float d0 = v0 - mean, d1 = v1 - mean;
    float var = blk_reduce_sum(d0*d0 + d1*d1, sm) * (1.0f / DMODEL);
    float inv = rsqrtf(var + 1e-5f);
    size_t ub = (size_t)r * EOUT;
    float u0 = __half2float(g_uoh[ub + tid])       + __half2float(g_uol[ub + tid]);
    float u1 = __half2float(g_uoh[ub + tid + 256]) + __half2float(g_uol[ub + tid + 256]);
    split_write_h(g_th, g_tl, base + tid,       (d0*inv*w[tid]       + b[tid])       * u0);
    split_write_h(g_th, g_tl, base + tid + 256, (d1*inv*w[tid + 256] + b[tid + 256]) * u1);
}

// ---------------------------------------------------------------------------
// fp16 2-term GEMM (HMMA): C = (Ah+Al) @ B^T, A exact fp16 split, B fp16.
// CTA 128x128, 8 warps (2m x 4n, 64x32 warp tile), K chunks of 32,
// 2-stage cp.async pipeline (3 tiles/stage = 61.4 KB), 2 CTAs/SM.
// EPI 0: silu -> fp16 hi/lo.  EPI 1: fp32 +bias+resid, pm mask.
// EPI 2: silu -> fp16 hi only (vqk path; lo never consumed).
// ---------------------------------------------------------------------------
#define KSEG   512
#define KCH    32
#define NCH    (KSEG/KCH)            // 16
#define TPAD   40                    // 32 + 8 elems -> 80B row stride
#define TBYTES (128*TPAD*2)          // 10240 B per tile
#define STAGE3 (3*TBYTES)            // Ah,Al,B per stage
#define SMEM_GEMM (2*STAGE3)         // 61440 B

template<int EPI>
__global__ void __launch_bounds__(256, 2)
mma_gemm(const __half* __restrict__ Ah, const __half* __restrict__ Al,
         const __half* __restrict__ B,
         float* __restrict__ C,
         __half* __restrict__ Ch, __half* __restrict__ Cl, int N,
         const float* __restrict__ bias, const float* __restrict__ resid,
         const unsigned char* __restrict__ pm) {
    const int tid = threadIdx.x, wid = tid >> 5, lane = tid & 31;
    const int bm = blockIdx.y * 128, bn = blockIdx.x * 128;
    const int wm = wid & 1, wn = wid >> 1;     // warp tile (wm*64, wn*32)

    const uint32_t sbase = smem_to_u32(dynsmem);
    const int lrow = lane & 15, lcol = (lane >> 4) * 8;
    const int crow = tid >> 2, ccol = (tid & 3) * 8;

    float acc[4][4][4];
    #pragma unroll
    for (int i = 0; i < 4; i++)
        #pragma unroll
        for (int j = 0; j < 4; j++)
            #pragma unroll
            for (int k = 0; k < 4; k++) acc[i][j][k] = 0.0f;

    auto issue = [&](int c, int stg) {
        const int kc = c * KCH;
        const uint32_t st = sbase + stg * STAGE3;
        #pragma unroll
        for (int i = 0; i < 2; i++) {
            int row = crow + i*64;
            uint32_t so = (row*TPAD + ccol)*2;
            cp16(st + 0*TBYTES + so, Ah + (size_t)(bm + row)*KSEG + kc + ccol);
            cp16(st + 1*TBYTES + so, Al + (size_t)(bm + row)*KSEG + kc + ccol);
            cp16(st + 2*TBYTES + so, B  + (size_t)(bn + row)*KSEG + kc + ccol);
        }
        CP_COMMIT();
    };

    issue(0, 0);
    for (int c = 0; c < NCH; c++) {
        if (c + 1 < NCH) { issue(c + 1, (c + 1) & 1); CP_WAIT(1); }
        else             { CP_WAIT(0); }
        __syncthreads();
        const uint32_t st = sbase + (c & 1) * STAGE3;
        const uint32_t sah = st, sal = st + TBYTES, sb = st + 2*TBYTES;
        #pragma unroll
        for (int ks = 0; ks < 2; ks++) {
            const int ko = ks * 16;
            uint32_t afh[4][4], afl[4][4], bf[2][4];
            #pragma unroll
            for (int fm = 0; fm < 4; fm++)
                ldsm4(afh[fm], sah + ((wm*64 + fm*16 + lrow)*TPAD + ko + lcol)*2);
            #pragma unroll
            for (int g = 0; g < 2; g++)
                ldsm4(bf[g], sb + ((wn*32 + g*16 + lrow)*TPAD + ko + lcol)*2);
            // term 1: Ah * B
            #pragma unroll
            for (int fm = 0; fm < 4; fm++)
                #pragma unroll
                for (int fn = 0; fn < 4; fn++) {
                    uint32_t bb[2] = { bf[fn >> 1][(fn & 1) + 0],
                                       bf[fn >> 1][(fn & 1) + 2] };
                    mma16816h(acc[fm][fn], afh[fm], bb);
                }
            // term 2: Al * B
            #pragma unroll
            for (int fm = 0; fm < 4; fm++)
                ldsm4(afl[fm], sal + ((wm*64 + fm*16 + lrow)*TPAD + ko + lcol)*2);
            #pragma unroll
            for (int fm = 0; fm < 4; fm++)
                #pragma unroll
                for (int fn = 0; fn < 4; fn++) {
                    uint32_t bb[2] = { bf[fn >> 1][(fn & 1) + 0],
                                       bf[fn >> 1][(fn & 1) + 2] };
                    mma16816h(acc[fm][fn], afl[fm], bb);
                }
        }
        __syncthreads();
    }

    #pragma unroll
    for (int fm = 0; fm < 4; fm++) {
        #pragma unroll
        for (int half = 0; half < 2; half++) {
            int r = bm + wm*64 + fm*16 + (lane >> 2) + half*8;
            #pragma unroll
            for (int fn = 0; fn < 4; fn++) {
                int cc = bn + wn*32 + fn*8 + (lane & 3)*2;
                float vx = acc[fm][fn][half*2 + 0];
                float vy = acc[fm][fn][half*2 + 1];
                if (EPI == 0 || EPI == 2) {
                    vx = vx / (1.0f + __expf(-vx));
                    vy = vy / (1.0f + __expf(-vy));
                    uint32_t hi = packh_hi(vx, vy);
                    *(uint32_t*)&Ch[(size_t)r*N + cc] = hi;
                    if (EPI == 0) {
                        uint32_t lo = packh_lo(vx, vy, hi);
                        *(uint32_t*)&Cl[(size_t)r*N + cc] = lo;
                    }
                } else {
                    vx += bias[cc]     + resid[(size_t)r*N + cc];
                    vy += bias[cc + 1] + resid[(size_t)r*N + cc + 1];
                    if (pm[r]) { vx = 0.0f; vy = 0.0f; }
                    float2 v = {vx, vy};
                    *(float2*)&C[(size_t)r*N + cc] = v;
                }
            }
        }
    }
}

// ---------------------------------------------------------------------------
// Kernel 3: causal silu-attention, single-fp16 MMA (Q,K,V,S all single),
// precomputed bias, pipelined K/V loads via split commit groups.
// smem: Q,K,V tiles + pm = ~28 KB -> high occupancy.
// grid (32 bh, 24 work), block 128.  Work mapping (big-first) as R8.
// ---------------------------------------------------------------------------
#define ATPAD 72
#define ATILE (64*ATPAD*2)           // 9216 B per fp16 tile
#define ATT_QH 0
#define ATT_KH (1*ATILE)
#define ATT_VH (2*ATILE)
#define ATT_PM (3*ATILE)             // pmj[2][64]
#define SMEM_ATTN (ATT_PM + 2*64*4)

__global__ void __launch_bounds__(128)
attn_kernel(const unsigned char* __restrict__ pm) {
    unsigned char* sm = dynsmem;
    int* pmj = (int*)(sm + ATT_PM);

    const int bh = blockIdx.x, b = bh >> 3, h = bh & 7;
    const int wy = blockIdx.y;
    int it, jlo, jhi, dst;
    if (wy < 16) {
        it = 15 - (wy >> 1);
        int m = (it + 2) >> 1;
        if (wy & 1) { jlo = m; jhi = it + 1; dst = 1; }
        else        { jlo = 0; jhi = m;      dst = 0; }
    } else {
        it = 23 - wy; jlo = 0; jhi = it + 1; dst = 0;
    }
    const int i0 = it * 64;
    const int tid = threadIdx.x, wq = tid >> 5, lane = tid & 31;
    const int lrow = lane & 15, lcol = (lane >> 4) * 8;

    const uint32_t sqh = smem_to_u32(sm);
    const uint32_t skh = sqh + ATT_KH;
    const uint32_t svh = sqh + ATT_VH;

    auto issue_k = [&](int jt, int slot) {
        const int j0 = jt * 64;
        #pragma unroll
        for (int i = 0; i < 4; i++) {
            int id = i*128 + tid, row = id >> 3, col = (id & 7) * 8;
            size_t bkv = (size_t)(b*NSEQ + j0 + row)*EOUT + h*64 + col;
            cp16(skh + (row*ATPAD + col)*2, &g_uoh[bkv + 1536]);
        }
        if (tid < 64) pmj[slot*64 + tid] = pm[b*NSEQ + j0 + tid];
        CP_COMMIT();
    };
    auto issue_v = [&](int jt) {
        const int j0 = jt * 64;
        #pragma unroll
        for (int i = 0; i < 4; i++) {
            int id = i*128 + tid, row = id >> 3, col = (id & 7) * 8;
            size_t bkv = (size_t)(b*NSEQ + j0 + row)*EOUT + h*64 + col;
            cp16(svh + (row*ATPAD + col)*2, &g_uoh[bkv + 512]);
        }
        CP_COMMIT();
    };

    // Q tile (cols 1024 + h*64)
    #pragma unroll
    for (int i = 0; i < 4; i++) {
        int id = i*128 + tid, row = id >> 3, col = (id & 7) * 8;
        size_t src = (size_t)(b*NSEQ + i0 + row)*EOUT + 1024 + h*64 + col;
        cp16(sqh + (row*ATPAD + col)*2, &g_uoh[src]);
    }
    CP_COMMIT(); CP_WAIT(0);
    __syncthreads();

    issue_k(jlo, 0);
    issue_v(jlo);

    float of[8][4];
    #pragma unroll
    for (int f = 0; f < 8; f++)
        #pragma unroll
        for (int r = 0; r < 4; r++) of[f][r] = 0.0f;

    const int row_lo = wq*16 + (lane >> 2);
    const int col_in = (lane & 3) * 2;

    for (int jt = jlo; jt < jhi; jt++) {
        const int j0 = jt * 64;
        const int slot = (jt - jlo) & 1;
        CP_WAIT(1);          // K(jt) ready (V(jt) may be in flight)
        __syncthreads();

        // ---- Phase A: S = Q K^T (1 fp16 MMA per fragment) ----
        float sc[8][4];
        #pragma unroll
        for (int f = 0; f < 8; f++)
            #pragma unroll
            for (int r = 0; r < 4; r++) sc[f][r] = 0.0f;

        #pragma unroll
        for (int ks = 0; ks < 4; ks++) {
            uint32_t aq[4], kh[4][4];
            ldsm4(aq, sqh + ((wq*16 + lrow)*ATPAD + ks*16 + lcol)*2);
            #pragma unroll
            for (int g = 0; g < 4; g++)
                ldsm4(kh[g], skh + ((g*16 + lrow)*ATPAD + ks*16 + lcol)*2);
            #pragma unroll
            for (int fn = 0; fn < 8; fn++) {
                uint32_t bh_[2] = { kh[fn >> 1][(fn & 1) + 0], kh[fn >> 1][(fn & 1) + 2] };
                mma16816h(sc[fn], aq, bh_);
            }
        }
        __syncthreads();              // all warps done reading K(jt)
        if (jt + 1 < jhi) issue_k(jt + 1, slot ^ 1);

        // ---- Epilogue: +bias (precomputed), silu/N, mask ----
        const int* pms = pmj + slot*64;
        #pragma unroll
        for (int f = 0; f < 8; f++) {
            int jb = j0 + f*8 + col_in;
            float2 b0 = *(const float2*)&g_bias[((size_t)(b << 10) + i0 + row_lo)     * NSEQ + jb];
            float2 b1 = *(const float2*)&g_bias[((size_t)(b << 10) + i0 + row_lo + 8) * NSEQ + jb];
            #pragma unroll
            for (int r = 0; r < 4; r++) {
                int il = row_lo + ((r >> 1) ? 8 : 0);
                int jl = f*8 + col_in + (r & 1);
                int ig = i0 + il, jg = j0 + jl;
                float bb = (r < 2) ? ((r & 1) ? b0.y : b0.x) : ((r & 1) ? b1.y : b1.x);
                float s = sc[f][r] + bb;
                s = s / (1.0f + __expf(-s)) * (1.0f / NSEQ);
                if (jg > ig || pms[jl]) s = 0.0f;
                sc[f][r] = s;
            }
        }

        if (jt + 1 < jhi) { CP_WAIT(1); } else { CP_WAIT(0); }   // V(jt) ready
        __syncthreads();

        // ---- Phase B: O += S V (1 fp16 MMA per fragment) ----
        #pragma unroll
        for (int ks = 0; ks < 4; ks++) {
            uint32_t ah[4];
            ah[0] = packh_hi(sc[2*ks][0],   sc[2*ks][1]);
            ah[1] = packh_hi(sc[2*ks][2],   sc[2*ks][3]);
            ah[2] = packh_hi(sc[2*ks+1][0], sc[2*ks+1][1]);
            ah[3] = packh_hi(sc[2*ks+1][2], sc[2*ks+1][3]);
            uint32_t voff = ((ks*16 + ((lane >> 3) & 1)*8 + (lane & 7))*ATPAD
                            + (lane >> 4)*8) * 2;
            #pragma unroll
            for (int dg = 0; dg < 4; dg++) {
                uint32_t vh[4];
                ldsm4t(vh, svh + voff + dg*16*2);
                #pragma unroll
                for (int half = 0; half < 2; half++) {
                    int fd = dg*2 + half;
                    uint32_t bh_[2] = { vh[half*2], vh[half*2 + 1] };
                    mma16816h(of[fd], ah, bh_);
                }
            }
        }
        __syncthreads();              // all warps done reading V(jt)
        if (jt + 1 < jhi) issue_v(jt + 1);
    }

    // ---- write O partial ----
    float* aop = dst ? g_ao1 : g_ao0;
    #pragma unroll
    for (int fd = 0; fd < 8; fd++) {
        #pragma unroll
        for (int half = 0; half < 2; half++) {
            int row = i0 + row_lo + half*8;
            int col = h*64 + fd*8 + col_in;
            float2 v = { of[fd][half*2], of[fd][half*2 + 1] };
            *(float2*)&aop[(size_t)(b*NSEQ + row)*DMODEL + col] = v;
        }
    }
}

// ---------------------------------------------------------------------------
// Launch — two-stream schedule (R13-proven):
//   stream 0:  prep_core -> gemm_vqk -> [wait aux] attn -> [wait u] ln_a -> gemm1
//   stream B:  prep_aux -> [wait core] gemm_u
// ---------------------------------------------------------------------------
extern "C" void kernel_launch(void* const* d_in, const int* in_sizes, int n_in,
                              void* d_out, int out_size) {
    const float*          x      = (const float*)d_in[0];
    const int*            ts     = (const int*)d_in[1];     // int32 (JAX x64 off)
    /* d_in[2] = cm — analytic triu(k=1), unused */
    const unsigned char*  pm     = (const unsigned char*)d_in[3];
    const float*          uvqk   = (const float*)d_in[4];
    const float*          o_w    = (const float*)d_in[5];
    const float*          o_b    = (const float*)d_in[6];
    const float*          ln_x_w = (const float*)d_in[7];
    const float*          ln_x_b = (const float*)d_in[8];
    const float*          ln_a_w = (const float*)d_in[9];
    const float*          ln_a_b = (const float*)d_in[10];
    const float*          ts_w   = (const float*)d_in[11];
    const float*          pos_w  = (const float*)d_in[12];
    float*                out    = (float*)d_out;

    __half *p_uoh, *p_uol, *p_nxh, *p_nxl, *p_th, *p_tl, *p_B1, *p_B2;
    cudaGetSymbolAddress((void**)&p_uoh, g_uoh);
    cudaGetSymbolAddress((void**)&p_uol, g_uol);
    cudaGetSymbolAddress((void**)&p_nxh, g_nxh);
    cudaGetSymbolAddress((void**)&p_nxl, g_nxl);
    cudaGetSymbolAddress((void**)&p_th,  g_th);
    cudaGetSymbolAddress((void**)&p_tl,  g_tl);
    cudaGetSymbolAddress((void**)&p_B1,  g_B1);
    cudaGetSymbolAddress((void**)&p_B2,  g_B2);

    cudaFuncSetAttribute(mma_gemm<0>, cudaFuncAttributeMaxDynamicSharedMemorySize, SMEM_GEMM);
    cudaFuncSetAttribute(mma_gemm<1>, cudaFuncAttributeMaxDynamicSharedMemorySize, SMEM_GEMM);
    cudaFuncSetAttribute(mma_gemm<2>, cudaFuncAttributeMaxDynamicSharedMemorySize, SMEM_GEMM);
    cudaFuncSetAttribute(attn_kernel, cudaFuncAttributeMaxDynamicSharedMemorySize, SMEM_ATTN);

    static cudaStream_t sB = nullptr;
    static cudaEvent_t evStart, evAux, evCore, evU;
    if (sB == nullptr) {
        cudaStreamCreateWithFlags(&sB, cudaStreamNonBlocking);
        cudaEventCreateWithFlags(&evStart, cudaEventDisableTiming);
        cudaEventCreateWithFlags(&evAux,   cudaEventDisableTiming);
        cudaEventCreateWithFlags(&evCore,  cudaEventDisableTiming);
        cudaEventCreateWithFlags(&evU,     cudaEventDisableTiming);
    }

    cudaEventRecord(evStart, 0);
    cudaStreamWaitEvent(sB, evStart, 0);

    // stream B: bias + tsplit(o_w)
    prep_aux_kernel<<<4352, 256, 0, sB>>>(o_w, ts, ts_w, pos_w);
    cudaEventRecord(evAux, sB);

    // stream 0: ln_x + tsplit(uvqk)
    prep_core_kernel<<<5120, 256>>>(x, ln_x_w, ln_x_b, uvqk);
    cudaEventRecord(evCore, 0);

    // stream 0: vqk GEMM (cols 512..2048) + silu -> fp16 hi only
    mma_gemm<2><<<dim3(12, ROWS/128), 256, SMEM_GEMM>>>(
        p_nxh, p_nxl, p_B1 + (size_t)512*KSEG,
        nullptr, p_uoh + 512, nullptr, EOUT, nullptr, nullptr, nullptr);

    // stream B: u GEMM (cols 0..512) after prep_core -> fp16 hi/lo
    cudaStreamWaitEvent(sB, evCore, 0);
    mma_gemm<0><<<dim3(4, ROWS/128), 256, SMEM_GEMM, sB>>>(
        p_nxh, p_nxl, p_B1,
        nullptr, p_uoh, p_uol, EOUT, nullptr, nullptr, nullptr);
    cudaEventRecord(evU, sB);

    // stream 0: attention (needs vqk + bias)
    cudaStreamWaitEvent(0, evAux, 0);
    attn_kernel<<<dim3(NB*NH, 24), 128, SMEM_ATTN>>>(pm);

    // stream 0: ln_a (needs attention + u)
    cudaStreamWaitEvent(0, evU, 0);
    ln_a_kernel<<<ROWS, 256>>>(ln_a_w, ln_a_b);

    // stream 0: final GEMM (needs ln_a + tsplit o_w, joined via evAux above)
    mma_gemm<1><<<dim3(DMODEL/128, ROWS/128), 256, SMEM_GEMM>>>(
        p_th, p_tl, p_B2,
        out, nullptr, nullptr, DMODEL, o_b, x, pm);
}